// round 1
// baseline (speedup 1.0000x reference)
#include <cuda_runtime.h>
#include <math.h>

// Problem constants (fixed shapes per reference: (2,1,2048,2048) images, (3,16,128,128) psfs, overlap=64)
#define IMG     2048
#define HS_     512
#define OV2     32          // overlap // 2
#define PK      128         // psf kernel size
#define SEGMAX  576         // max tile segment extent
#define TILE_Y  64
#define TILE_X  32
#define SEG_ROWS (TILE_Y + PK - 1)   // 191
#define SEG_COLS (TILE_X + PK - 1)   // 159
#define SEG_PITCH 176                // 176 mod 32 = 16 -> the two warp row-halves hit disjoint bank sets
#define UCH     8                    // psf u-rows per smem chunk
#define SMEM_FLOATS (SEG_ROWS * SEG_PITCH + UCH * 128 * 3)
#define SMEM_BYTES  (SMEM_FLOATS * 4)

// Scratch: per-(b,l,tile) windowed conv result, row stride = actual tile width.
// 2*3*16*576*576 floats = 127.4 MB
__device__ float g_acc[(size_t)2 * 3 * 16 * SEGMAX * SEGMAX];
// Window tables: [tile_axis_idx 0..3][sigma_variant 0..1][pos 0..575]
__device__ float g_wtab[4 * 2 * SEGMAX];

__device__ __forceinline__ void tile_range(int i, int* a0, int* a1) {
  int lo = i * HS_ - OV2; if (lo < 0) lo = 0;
  int hi = (i + 1) * HS_ + OV2; if (hi > IMG) hi = IMG;
  *a0 = lo; *a1 = hi;
}

__global__ void init_wtab_kernel() {
  int idx = blockIdx.x * blockDim.x + threadIdx.x;
  if (idx >= 4 * 2 * SEGMAX) return;
  int p  = idx % SEGMAX;
  int sv = (idx / SEGMAX) & 1;
  int i  = idx / (2 * SEGMAX);
  int a0, a1; tile_range(i, &a0, &a1);
  int S = a1 - a0;
  float val = 0.0f;
  if (p < S) {
    // linspace(-S/2, S/2, S)[p] ; sigma = min(Hsz,Wsz)/4 in {136, 144}
    float sigma = sv ? 144.0f : 136.0f;
    float v = -0.5f * (float)S + (float)p * ((float)S / (float)(S - 1));
    val = expf(-0.5f * v * v / (sigma * sigma));
  }
  g_wtab[idx] = val;
}

// Direct same-size linear convolution per tile, all 3 PSF stacks per block.
// Rotated frame: im[y,x] = T[x, 2047-y]. seg[R,C] = im[h0+R, w0+C].
// cap[y,x] = sum_{p,q} psf_rot[p,q] * seg[y+64-p, x+64-q],  psf_rot[p,q] = psfs[l, hd, q, 127-p].
__global__ __launch_bounds__(256) void conv_kernel(
    const float* __restrict__ Timg, const float* __restrict__ psfs) {
  int zb = blockIdx.z;
  int b  = zb >> 4;
  int t  = zb & 15;
  int ti = t >> 2, tj = t & 3;
  int h0, h1, w0, w1;
  tile_range(ti, &h0, &h1);
  tile_range(tj, &w0, &w1);
  int Hsz = h1 - h0, Wsz = w1 - w0;
  int gy0 = blockIdx.y * TILE_Y;
  int gx0 = blockIdx.x * TILE_X;
  if (gy0 >= Hsz || gx0 >= Wsz) return;   // block-uniform early exit (before any barrier)

  extern __shared__ float smem[];
  float* seg_s = smem;                          // [SEG_ROWS][SEG_PITCH]
  float* psf_s = smem + SEG_ROWS * SEG_PITCH;   // [UCH][128][3]

  int tid = threadIdx.x;
  int tx = tid & 15, ty = tid >> 4;

  // Load segment tile (+halo), zero outside [0,Hsz)x[0,Wsz).
  // Consecutive tid -> consecutive r -> contiguous (descending) addresses in Timg (coalesced).
  const float* Tb = Timg + (size_t)b * IMG * IMG;
  for (int idx = tid; idx < SEG_ROWS * SEG_COLS; idx += 256) {
    int c = idx / SEG_ROWS;
    int r = idx - c * SEG_ROWS;
    int R = gy0 + r - (PK / 2 - 1);   // gy0 + r - 63
    int C = gx0 + c - (PK / 2 - 1);
    float v = 0.0f;
    if (R >= 0 && R < Hsz && C >= 0 && C < Wsz)
      v = Tb[(size_t)(w0 + C) * IMG + (IMG - 1 - (h0 + R))];
    seg_s[r * SEG_PITCH + c] = v;
  }

  float acc[4][2][3];
#pragma unroll
  for (int a = 0; a < 4; ++a)
#pragma unroll
    for (int d = 0; d < 2; ++d)
#pragma unroll
      for (int l = 0; l < 3; ++l) acc[a][d][l] = 0.0f;

  int hd = tj * 4 + ti;   // psf head index after reshape+transpose

  for (int u0 = 0; u0 < PK; u0 += UCH) {
    __syncthreads();
    // psf_s[u][v][l] = psfs[l, hd, v, 127-(u0+u)]
    for (int idx = tid; idx < UCH * 128 * 3; idx += 256) {
      int l = idx % 3;
      int rest = idx / 3;
      int v = rest & 127;
      int u = rest >> 7;
      int p = u0 + u;
      psf_s[idx] = psfs[(((size_t)l * 16 + hd) * 128 + v) * 128 + (127 - p)];
    }
    __syncthreads();
#pragma unroll
    for (int u = 0; u < UCH; ++u) {
      int p = u0 + u;
      int rb0 = (ty + (PK - 1) - p) * SEG_PITCH + tx + (PK - 1);
      int rb1 = rb0 + 16 * SEG_PITCH;
      int rb2 = rb1 + 16 * SEG_PITCH;
      int rb3 = rb2 + 16 * SEG_PITCH;
      int pb = u * 384;
#pragma unroll 8
      for (int v = 0; v < 128; ++v) {
        float pf0 = psf_s[pb + v * 3 + 0];
        float pf1 = psf_s[pb + v * 3 + 1];
        float pf2 = psf_s[pb + v * 3 + 2];
        float s[4][2];
        s[0][0] = seg_s[rb0 - v]; s[0][1] = seg_s[rb0 + 16 - v];
        s[1][0] = seg_s[rb1 - v]; s[1][1] = seg_s[rb1 + 16 - v];
        s[2][0] = seg_s[rb2 - v]; s[2][1] = seg_s[rb2 + 16 - v];
        s[3][0] = seg_s[rb3 - v]; s[3][1] = seg_s[rb3 + 16 - v];
#pragma unroll
        for (int dy = 0; dy < 4; ++dy)
#pragma unroll
          for (int dx = 0; dx < 2; ++dx) {
            acc[dy][dx][0] += pf0 * s[dy][dx];
            acc[dy][dx][1] += pf1 * s[dy][dx];
            acc[dy][dx][2] += pf2 * s[dy][dx];
          }
      }
    }
  }

  // Multiply by window and store per-tile result (each cell written by exactly one thread: deterministic).
  int sv = (Hsz == 576 && Wsz == 576) ? 1 : 0;
#pragma unroll
  for (int dy = 0; dy < 4; ++dy) {
    int Rr = gy0 + ty + 16 * dy;
    if (Rr >= Hsz) continue;
    float wy = g_wtab[(ti * 2 + sv) * SEGMAX + Rr];
#pragma unroll
    for (int dx = 0; dx < 2; ++dx) {
      int Cc = gx0 + tx + 16 * dx;   // always < Wsz (Wsz is a multiple of 32)
      float wx = g_wtab[(tj * 2 + sv) * SEGMAX + Cc];
      float w = wy * wx;
#pragma unroll
      for (int l = 0; l < 3; ++l) {
        size_t off = (size_t)((b * 3 + l) * 16 + t) * (SEGMAX * SEGMAX)
                   + (size_t)Rr * Wsz + Cc;
        g_acc[off] = acc[dy][dx][l] * w;
      }
    }
  }
}

// Overlap-add gather + normalization + inverse rotation: O[b,l,I,J] = out[b,l, 2047-J, I]
__global__ __launch_bounds__(256) void finalize_kernel(float* __restrict__ outp) {
  size_t idx = (size_t)blockIdx.x * 256 + threadIdx.x;
  if (idx >= (size_t)2 * 3 * IMG * IMG) return;
  int J = (int)(idx & (IMG - 1));
  size_t r2 = idx >> 11;
  int I = (int)(r2 & (IMG - 1));
  size_t r3 = r2 >> 11;
  int l = (int)(r3 % 3);
  int b = (int)(r3 / 3);
  int y = IMG - 1 - J;
  int x = I;
  float s = 0.0f, wsum = 0.0f;
#pragma unroll
  for (int i = 0; i < 4; ++i) {
    int h0, h1; tile_range(i, &h0, &h1);
    if (y < h0 || y >= h1) continue;
#pragma unroll
    for (int j = 0; j < 4; ++j) {
      int w0, w1; tile_range(j, &w0, &w1);
      if (x < w0 || x >= w1) continue;
      int Hsz = h1 - h0, Wsz = w1 - w0;
      int sv = (Hsz == 576 && Wsz == 576) ? 1 : 0;
      int r = y - h0, c = x - w0;
      float wy = g_wtab[(i * 2 + sv) * SEGMAX + r];
      float wx = g_wtab[(j * 2 + sv) * SEGMAX + c];
      int t = i * 4 + j;
      s += g_acc[(size_t)((b * 3 + l) * 16 + t) * (SEGMAX * SEGMAX) + (size_t)r * Wsz + c];
      wsum += wy * wx;
    }
  }
  float res = s / fmaxf(wsum, 1e-12f);
  if (!(res == res)) res = 0.0f;   // nan_to_num(nan=0)
  outp[idx] = res;
}

extern "C" void kernel_launch(void* const* d_in, const int* in_sizes, int n_in,
                              void* d_out, int out_size) {
  const float* Timg = (const float*)d_in[0];   // (2,1,2048,2048) float32
  const float* psfs = (const float*)d_in[1];   // (3,16,128,128) float32
  (void)in_sizes; (void)n_in;                  // overlap fixed at 64 per problem setup
  float* outp = (float*)d_out;                 // (2,3,2048,2048) float32

  cudaFuncSetAttribute(conv_kernel, cudaFuncAttributeMaxDynamicSharedMemorySize, SMEM_BYTES);

  init_wtab_kernel<<<18, 256>>>();
  // grid.x: 18*32 = 576 cols, grid.y: 9*64 = 576 rows, grid.z: 2 batches * 16 tiles
  conv_kernel<<<dim3(18, 9, 32), 256, SMEM_BYTES>>>(Timg, psfs);

  size_t total = (size_t)2 * 3 * IMG * IMG;
  finalize_kernel<<<(unsigned)((total + 255) / 256), 256>>>(outp);
}

// round 2
// speedup vs baseline: 1.6385x; 1.6385x over previous
#include <cuda_runtime.h>
#include <math.h>

// Problem constants (fixed shapes per reference: (2,1,2048,2048) images, (3,16,128,128) psfs, overlap=64)
#define IMG     2048
#define HS_     512
#define OV2     32          // overlap // 2
#define PK      128         // psf kernel size
#define SEGMAX  576         // max tile segment extent
#define TILE_Y  64
#define TILE_X  32
#define SEG_ROWS (TILE_Y + PK - 1)   // 191
#define SEG_COLS (TILE_X + PK - 1)   // 159
#define SEG_PITCH 176                // 176 mod 32 = 16 -> the two warp row-halves hit disjoint bank sets
#define UCH     8                    // psf u-rows per smem chunk
#define SMEM_FLOATS (SEG_ROWS * SEG_PITCH + UCH * 128 * 3)
#define SMEM_BYTES  (SMEM_FLOATS * 4)

// Scratch: per-(b,l,tile) windowed conv result, row stride = actual tile width.
// 2*3*16*576*576 floats = 127.4 MB
__device__ float g_acc[(size_t)2 * 3 * 16 * SEGMAX * SEGMAX];
// Window tables: [tile_axis_idx 0..3][sigma_variant 0..1][pos 0..575]
__device__ float g_wtab[4 * 2 * SEGMAX];

__device__ __forceinline__ void tile_range(int i, int* a0, int* a1) {
  int lo = i * HS_ - OV2; if (lo < 0) lo = 0;
  int hi = (i + 1) * HS_ + OV2; if (hi > IMG) hi = IMG;
  *a0 = lo; *a1 = hi;
}

__global__ void init_wtab_kernel() {
  int idx = blockIdx.x * blockDim.x + threadIdx.x;
  if (idx >= 4 * 2 * SEGMAX) return;
  int p  = idx % SEGMAX;
  int sv = (idx / SEGMAX) & 1;
  int i  = idx / (2 * SEGMAX);
  int a0, a1; tile_range(i, &a0, &a1);
  int S = a1 - a0;
  float val = 0.0f;
  if (p < S) {
    // linspace(-S/2, S/2, S)[p] ; sigma = min(Hsz,Wsz)/4 in {136, 144}
    float sigma = sv ? 144.0f : 136.0f;
    float v = -0.5f * (float)S + (float)p * ((float)S / (float)(S - 1));
    val = expf(-0.5f * v * v / (sigma * sigma));
  }
  g_wtab[idx] = val;
}

// Direct same-size linear convolution per tile, all 3 PSF stacks per block.
// Rotated frame: im[y,x] = T[x, 2047-y]. seg[R,C] = im[h0+R, w0+C].
// cap[y,x] = sum_{p,q} psf_rot[p,q] * seg[y+64-p, x+64-q],  psf_rot[p,q] = psfs[l, hd, q, 127-p].
__global__ __launch_bounds__(256) void conv_kernel(
    const float* __restrict__ Timg, const float* __restrict__ psfs) {
  int zb = blockIdx.z;
  int b  = zb >> 4;
  int t  = zb & 15;
  int ti = t >> 2, tj = t & 3;
  int h0, h1, w0, w1;
  tile_range(ti, &h0, &h1);
  tile_range(tj, &w0, &w1);
  int Hsz = h1 - h0, Wsz = w1 - w0;
  int gy0 = blockIdx.y * TILE_Y;
  int gx0 = blockIdx.x * TILE_X;
  if (gy0 >= Hsz || gx0 >= Wsz) return;   // block-uniform early exit (before any barrier)

  extern __shared__ float smem[];
  float* seg_s = smem;                          // [SEG_ROWS][SEG_PITCH]
  float* psf_s = smem + SEG_ROWS * SEG_PITCH;   // [UCH][128][3]

  int tid = threadIdx.x;
  int tx = tid & 15, ty = tid >> 4;

  // Load segment tile (+halo), zero outside [0,Hsz)x[0,Wsz).
  // Consecutive tid -> consecutive r -> contiguous (descending) addresses in Timg (coalesced).
  const float* Tb = Timg + (size_t)b * IMG * IMG;
  for (int idx = tid; idx < SEG_ROWS * SEG_COLS; idx += 256) {
    int c = idx / SEG_ROWS;
    int r = idx - c * SEG_ROWS;
    int R = gy0 + r - (PK / 2 - 1);   // gy0 + r - 63
    int C = gx0 + c - (PK / 2 - 1);
    float v = 0.0f;
    if (R >= 0 && R < Hsz && C >= 0 && C < Wsz)
      v = Tb[(size_t)(w0 + C) * IMG + (IMG - 1 - (h0 + R))];
    seg_s[r * SEG_PITCH + c] = v;
  }

  float acc[4][2][3];
#pragma unroll
  for (int a = 0; a < 4; ++a)
#pragma unroll
    for (int d = 0; d < 2; ++d)
#pragma unroll
      for (int l = 0; l < 3; ++l) acc[a][d][l] = 0.0f;

  int hd = tj * 4 + ti;   // psf head index after reshape+transpose

  for (int u0 = 0; u0 < PK; u0 += UCH) {
    __syncthreads();
    // psf_s[u][v][l] = psfs[l, hd, v, 127-(u0+u)]
    for (int idx = tid; idx < UCH * 128 * 3; idx += 256) {
      int l = idx % 3;
      int rest = idx / 3;
      int v = rest & 127;
      int u = rest >> 7;
      int p = u0 + u;
      psf_s[idx] = psfs[(((size_t)l * 16 + hd) * 128 + v) * 128 + (127 - p)];
    }
    __syncthreads();
#pragma unroll
    for (int u = 0; u < UCH; ++u) {
      int p = u0 + u;
      int rb0 = (ty + (PK - 1) - p) * SEG_PITCH + tx + (PK - 1);
      int rb1 = rb0 + 16 * SEG_PITCH;
      int rb2 = rb1 + 16 * SEG_PITCH;
      int rb3 = rb2 + 16 * SEG_PITCH;
      int pb = u * 384;
#pragma unroll 8
      for (int v = 0; v < 128; ++v) {
        float pf0 = psf_s[pb + v * 3 + 0];
        float pf1 = psf_s[pb + v * 3 + 1];
        float pf2 = psf_s[pb + v * 3 + 2];
        float s[4][2];
        s[0][0] = seg_s[rb0 - v]; s[0][1] = seg_s[rb0 + 16 - v];
        s[1][0] = seg_s[rb1 - v]; s[1][1] = seg_s[rb1 + 16 - v];
        s[2][0] = seg_s[rb2 - v]; s[2][1] = seg_s[rb2 + 16 - v];
        s[3][0] = seg_s[rb3 - v]; s[3][1] = seg_s[rb3 + 16 - v];
#pragma unroll
        for (int dy = 0; dy < 4; ++dy)
#pragma unroll
          for (int dx = 0; dx < 2; ++dx) {
            acc[dy][dx][0] += pf0 * s[dy][dx];
            acc[dy][dx][1] += pf1 * s[dy][dx];
            acc[dy][dx][2] += pf2 * s[dy][dx];
          }
      }
    }
  }

  // Multiply by window and store per-tile result (each cell written by exactly one thread: deterministic).
  int sv = (Hsz == 576 && Wsz == 576) ? 1 : 0;
#pragma unroll
  for (int dy = 0; dy < 4; ++dy) {
    int Rr = gy0 + ty + 16 * dy;
    if (Rr >= Hsz) continue;
    float wy = g_wtab[(ti * 2 + sv) * SEGMAX + Rr];
#pragma unroll
    for (int dx = 0; dx < 2; ++dx) {
      int Cc = gx0 + tx + 16 * dx;   // always < Wsz (Wsz is a multiple of 32)
      float wx = g_wtab[(tj * 2 + sv) * SEGMAX + Cc];
      float w = wy * wx;
#pragma unroll
      for (int l = 0; l < 3; ++l) {
        size_t off = (size_t)((b * 3 + l) * 16 + t) * (SEGMAX * SEGMAX)
                   + (size_t)Rr * Wsz + Cc;
        g_acc[off] = acc[dy][dx][l] * w;
      }
    }
  }
}

// Overlap-add gather + normalization + inverse rotation: O[b,l,I,J] = out[b,l, 2047-J, I]
__global__ __launch_bounds__(256) void finalize_kernel(float* __restrict__ outp) {
  size_t idx = (size_t)blockIdx.x * 256 + threadIdx.x;
  if (idx >= (size_t)2 * 3 * IMG * IMG) return;
  int J = (int)(idx & (IMG - 1));
  size_t r2 = idx >> 11;
  int I = (int)(r2 & (IMG - 1));
  size_t r3 = r2 >> 11;
  int l = (int)(r3 % 3);
  int b = (int)(r3 / 3);
  int y = IMG - 1 - J;
  int x = I;
  float s = 0.0f, wsum = 0.0f;
#pragma unroll
  for (int i = 0; i < 4; ++i) {
    int h0, h1; tile_range(i, &h0, &h1);
    if (y < h0 || y >= h1) continue;
#pragma unroll
    for (int j = 0; j < 4; ++j) {
      int w0, w1; tile_range(j, &w0, &w1);
      if (x < w0 || x >= w1) continue;
      int Hsz = h1 - h0, Wsz = w1 - w0;
      int sv = (Hsz == 576 && Wsz == 576) ? 1 : 0;
      int r = y - h0, c = x - w0;
      float wy = g_wtab[(i * 2 + sv) * SEGMAX + r];
      float wx = g_wtab[(j * 2 + sv) * SEGMAX + c];
      int t = i * 4 + j;
      s += g_acc[(size_t)((b * 3 + l) * 16 + t) * (SEGMAX * SEGMAX) + (size_t)r * Wsz + c];
      wsum += wy * wx;
    }
  }
  float res = s / fmaxf(wsum, 1e-12f);
  if (!(res == res)) res = 0.0f;   // nan_to_num(nan=0)
  outp[idx] = res;
}

extern "C" void kernel_launch(void* const* d_in, const int* in_sizes, int n_in,
                              void* d_out, int out_size) {
  const float* Timg = (const float*)d_in[0];   // (2,1,2048,2048) float32
  const float* psfs = (const float*)d_in[1];   // (3,16,128,128) float32
  (void)in_sizes; (void)n_in;                  // overlap fixed at 64 per problem setup
  float* outp = (float*)d_out;                 // (2,3,2048,2048) float32

  cudaFuncSetAttribute(conv_kernel, cudaFuncAttributeMaxDynamicSharedMemorySize, SMEM_BYTES);

  init_wtab_kernel<<<18, 256>>>();
  // grid.x: 18*32 = 576 cols, grid.y: 9*64 = 576 rows, grid.z: 2 batches * 16 tiles
  conv_kernel<<<dim3(18, 9, 32), 256, SMEM_BYTES>>>(Timg, psfs);

  size_t total = (size_t)2 * 3 * IMG * IMG;
  finalize_kernel<<<(unsigned)((total + 255) / 256), 256>>>(outp);
}

// round 3
// speedup vs baseline: 9.5743x; 5.8433x over previous
#include <cuda_runtime.h>
#include <math.h>

#ifndef M_PI
#define M_PI 3.14159265358979323846
#endif

// Problem constants (fixed shapes: (2,1,2048,2048) images, (3,16,128,128) psfs, overlap=64)
#define IMG     2048
#define HS_     512
#define OV2     32
#define PK      128
#define SEGMAX  576
#define NF      1024          // FFT length (>= 576+128-1=703, power of two)

// ---------------- static scratch ----------------
__device__ float  g_acc[(size_t)2 * 3 * 16 * SEGMAX * SEGMAX];   // 127 MB
__device__ float  g_wtab[4 * 2 * SEGMAX];
__device__ float2 g_tw[NF / 2];                                   // exp(-2*pi*i*j/1024)
__device__ float2 g_segF[(size_t)32 * NF * NF];                   // 256 MB  [b*16+t][fy][fx]
__device__ float2 g_psfF[(size_t)48 * NF * NF];                   // 384 MB  [l*16+t][fy][fx]
// reused: seg pass1 out [32][1024][576]; psf pass1 out [48][1024][128]; Q [32][576][1024]
__device__ float2 g_mid[(size_t)32 * NF * SEGMAX];                // 151 MB

__device__ __forceinline__ void tile_range(int i, int* a0, int* a1) {
  int lo = i * HS_ - OV2; if (lo < 0) lo = 0;
  int hi = (i + 1) * HS_ + OV2; if (hi > IMG) hi = IMG;
  *a0 = lo; *a1 = hi;
}
__device__ __forceinline__ int brev10(int i) { return (int)(__brev((unsigned)i) >> 22); }

// ---------------- init kernels ----------------
__global__ void init_wtab_kernel() {
  int idx = blockIdx.x * blockDim.x + threadIdx.x;
  if (idx >= 4 * 2 * SEGMAX) return;
  int p  = idx % SEGMAX;
  int sv = (idx / SEGMAX) & 1;
  int i  = idx / (2 * SEGMAX);
  int a0, a1; tile_range(i, &a0, &a1);
  int S = a1 - a0;
  float val = 0.0f;
  if (p < S) {
    float sigma = sv ? 144.0f : 136.0f;
    float v = -0.5f * (float)S + (float)p * ((float)S / (float)(S - 1));
    val = expf(-0.5f * v * v / (sigma * sigma));
  }
  g_wtab[idx] = val;
}

__global__ void init_tw_kernel() {
  int j = blockIdx.x * blockDim.x + threadIdx.x;
  if (j >= NF / 2) return;
  double ang = -2.0 * M_PI * (double)j / (double)NF;
  double s, c;
  sincos(ang, &s, &c);
  g_tw[j] = make_float2((float)c, (float)s);
}

// ---------------- in-SMEM radix-2 FFT (1024 pt), input pre-bit-reversed ----------------
// arr: ncols columns, column c at arr[c*colstride ... +1023]. dir=-1 fwd, +1 inv (unscaled).
__device__ __forceinline__ void fft_stages(float2* arr, int colstride, int ncols,
                                           const float2* tw, int dir, int tid, int nth) {
  int nbf = ncols * 512;
#pragma unroll 1
  for (int s = 1; s <= 10; ++s) {
    int m = 1 << s, half = m >> 1;
    int tstep = NF >> s;
    __syncthreads();
    for (int t = tid; t < nbf; t += nth) {
      int col = t >> 9, j = t & 511;
      int k = j & (half - 1);
      int grp = j >> (s - 1);
      int i0 = grp * m + k, i1 = i0 + half;
      float2 w = tw[k * tstep];
      float wi = (dir > 0) ? -w.y : w.y;
      float2* A = arr + col * colstride;
      float2 x0 = A[i0], x1 = A[i1];
      float tr = x1.x * w.x - x1.y * wi;
      float ti = x1.x * wi + x1.y * w.x;
      A[i0] = make_float2(x0.x + tr, x0.y + ti);
      A[i1] = make_float2(x0.x - tr, x0.y - ti);
    }
  }
  __syncthreads();
}

#define CSTR 1025   // padded column stride (float2) for 16-col kernels
#define S16_SMEM ((16 * CSTR + 512) * sizeof(float2))
#define S1_SMEM  ((NF + 512) * sizeof(float2))

// ---------------- seg forward pass 1: FFT along y (contiguous in Timg) ----------------
// grid (36, 32) block 512.  writes g_mid[a][fy][C] (C-contiguous, stride 576)
__global__ __launch_bounds__(512) void seg_p1(const float* __restrict__ Timg) {
  int g = blockIdx.x, a = blockIdx.y;
  int b = a >> 4, t = a & 15, ti = t >> 2, tj = t & 3;
  int h0, h1, w0, w1; tile_range(ti, &h0, &h1); tile_range(tj, &w0, &w1);
  int Hsz = h1 - h0, Wsz = w1 - w0;
  extern __shared__ float2 sm[];
  float2* arr = sm;
  float2* tws = sm + 16 * CSTR;
  int tid = threadIdx.x;
  for (int i = tid; i < 512; i += 512) tws[i] = g_tw[i];
  const float* Tb = Timg + (size_t)b * IMG * IMG;
  for (int idx = tid; idx < 16 * NF; idx += 512) {
    int c = idx >> 10, R = idx & 1023;
    int C = g * 16 + c;
    float v = 0.0f;
    if (R < Hsz && C < Wsz)
      v = Tb[(size_t)(w0 + C) * IMG + (IMG - 1 - (h0 + R))];
    arr[c * CSTR + brev10(R)] = make_float2(v, 0.0f);
  }
  fft_stages(arr, CSTR, 16, tws, -1, tid, 512);
  float2* outp = g_mid + (size_t)a * NF * SEGMAX;
  for (int idx = tid; idx < NF * 16; idx += 512) {
    int fy = idx >> 4, c = idx & 15;
    outp[(size_t)fy * SEGMAX + g * 16 + c] = arr[c * CSTR + fy];
  }
}

// ---------------- seg forward pass 2: FFT along x ----------------
// grid (1024, 32) block 512
__global__ __launch_bounds__(512) void seg_p2() {
  int fy = blockIdx.x, a = blockIdx.y;
  extern __shared__ float2 sm[];
  float2* arr = sm;
  float2* tws = sm + NF;
  int tid = threadIdx.x;
  for (int i = tid; i < 512; i += 512) tws[i] = g_tw[i];
  const float2* inp = g_mid + ((size_t)a * NF + fy) * SEGMAX;
  for (int C = tid; C < NF; C += 512) {
    float2 v = (C < SEGMAX) ? inp[C] : make_float2(0.0f, 0.0f);
    arr[brev10(C)] = v;
  }
  fft_stages(arr, NF, 1, tws, -1, tid, 512);
  float2* outp = g_segF + ((size_t)a * NF + fy) * NF;
  for (int fx = tid; fx < NF; fx += 512) outp[fx] = arr[fx];
}

// ---------------- psf forward pass 1: FFT along p ----------------
// grid (8, 48) block 512.  k[p][q] = psfs[l,hd,q,127-p].  writes g_mid[ap][fy][C] stride 128
__global__ __launch_bounds__(512) void psf_p1(const float* __restrict__ psfs) {
  int g = blockIdx.x, ap = blockIdx.y;
  int l = ap / 16, t = ap % 16, ti = t >> 2, tj = t & 3;
  int hd = tj * 4 + ti;
  extern __shared__ float2 sm[];
  float2* arr = sm;
  float2* tws = sm + 16 * CSTR;
  int tid = threadIdx.x;
  for (int i = tid; i < 512; i += 512) tws[i] = g_tw[i];
  for (int idx = tid; idx < 16 * NF; idx += 512) {
    int c = idx >> 10, p = idx & 1023;
    int C = g * 16 + c;   // q
    float v = 0.0f;
    if (p < PK)
      v = psfs[(((size_t)l * 16 + hd) * PK + C) * PK + (PK - 1 - p)];
    arr[c * CSTR + brev10(p)] = make_float2(v, 0.0f);
  }
  fft_stages(arr, CSTR, 16, tws, -1, tid, 512);
  float2* outp = g_mid + (size_t)ap * NF * PK;
  for (int idx = tid; idx < NF * 16; idx += 512) {
    int fy = idx >> 4, c = idx & 15;
    outp[(size_t)fy * PK + g * 16 + c] = arr[c * CSTR + fy];
  }
}

// ---------------- psf forward pass 2: FFT along q ----------------
// grid (1024, 48) block 512
__global__ __launch_bounds__(512) void psf_p2() {
  int fy = blockIdx.x, ap = blockIdx.y;
  extern __shared__ float2 sm[];
  float2* arr = sm;
  float2* tws = sm + NF;
  int tid = threadIdx.x;
  for (int i = tid; i < 512; i += 512) tws[i] = g_tw[i];
  const float2* inp = g_mid + ((size_t)ap * NF + fy) * PK;
  for (int C = tid; C < NF; C += 512) {
    float2 v = (C < PK) ? inp[C] : make_float2(0.0f, 0.0f);
    arr[brev10(C)] = v;
  }
  fft_stages(arr, NF, 1, tws, -1, tid, 512);
  float2* outp = g_psfF + ((size_t)ap * NF + fy) * NF;
  for (int fx = tid; fx < NF; fx += 512) outp[fx] = arr[fx];
}

// ---------------- inverse pass 1: pointwise product + IFFT along fy ----------------
// grid (64, 32) block 512, per-l launch.  writes Q = g_mid[a][y-64][fx] (y in [64,640))
__global__ __launch_bounds__(512) void conv_ifft_y(int l) {
  int g = blockIdx.x, a = blockIdx.y;
  int t = a & 15;
  int al = l * 16 + t;
  extern __shared__ float2 sm[];
  float2* arr = sm;
  float2* tws = sm + 16 * CSTR;
  int tid = threadIdx.x;
  for (int i = tid; i < 512; i += 512) tws[i] = g_tw[i];
  const float2* Sb = g_segF + (size_t)a * NF * NF;
  const float2* Fb = g_psfF + (size_t)al * NF * NF;
  for (int idx = tid; idx < NF * 16; idx += 512) {
    int fy = idx >> 4, c = idx & 15;
    int fx = g * 16 + c;
    float2 S = Sb[(size_t)fy * NF + fx];
    float2 F = Fb[(size_t)fy * NF + fx];
    float2 P = make_float2(S.x * F.x - S.y * F.y, S.x * F.y + S.y * F.x);
    arr[c * CSTR + brev10(fy)] = P;
  }
  fft_stages(arr, CSTR, 16, tws, +1, tid, 512);
  const float sc = 1.0f / (float)NF;
  float2* Q = g_mid + (size_t)a * SEGMAX * NF;
  for (int idx = tid; idx < SEGMAX * 16; idx += 512) {
    int r = idx >> 4, c = idx & 15;       // r = y - 64
    float2 v = arr[c * CSTR + (r + 64)];
    Q[(size_t)r * NF + g * 16 + c] = make_float2(v.x * sc, v.y * sc);
  }
}

// ---------------- inverse pass 2: IFFT along fx + window + store to g_acc ----------------
// grid (576, 32) block 512, per-l launch
__global__ __launch_bounds__(512) void conv_ifft_x(int l) {
  int r = blockIdx.x, a = blockIdx.y;
  int b = a >> 4, t = a & 15, ti = t >> 2, tj = t & 3;
  int h0, h1, w0, w1; tile_range(ti, &h0, &h1); tile_range(tj, &w0, &w1);
  int Hsz = h1 - h0, Wsz = w1 - w0;
  if (r >= Hsz) return;                       // block-uniform
  extern __shared__ float2 sm[];
  float2* arr = sm;
  float2* tws = sm + NF;
  int tid = threadIdx.x;
  for (int i = tid; i < 512; i += 512) tws[i] = g_tw[i];
  const float2* Q = g_mid + ((size_t)a * SEGMAX + r) * NF;
  for (int fx = tid; fx < NF; fx += 512) arr[brev10(fx)] = Q[fx];
  fft_stages(arr, NF, 1, tws, +1, tid, 512);
  int sv = (Hsz == 576 && Wsz == 576) ? 1 : 0;
  float wy = g_wtab[(ti * 2 + sv) * SEGMAX + r];
  const float sc = 1.0f / (float)NF;
  float* outp = g_acc + (size_t)((b * 3 + l) * 16 + t) * (SEGMAX * SEGMAX) + (size_t)r * Wsz;
  for (int x = tid; x < Wsz; x += 512) {
    float wx = g_wtab[(tj * 2 + sv) * SEGMAX + x];
    outp[x] = arr[64 + x].x * sc * wy * wx;
  }
}

// ---------------- overlap-add gather + normalize + inverse rotation (unchanged) --------
__global__ __launch_bounds__(256) void finalize_kernel(float* __restrict__ outp) {
  size_t idx = (size_t)blockIdx.x * 256 + threadIdx.x;
  if (idx >= (size_t)2 * 3 * IMG * IMG) return;
  int J = (int)(idx & (IMG - 1));
  size_t r2 = idx >> 11;
  int I = (int)(r2 & (IMG - 1));
  size_t r3 = r2 >> 11;
  int l = (int)(r3 % 3);
  int b = (int)(r3 / 3);
  int y = IMG - 1 - J;
  int x = I;
  float s = 0.0f, wsum = 0.0f;
#pragma unroll
  for (int i = 0; i < 4; ++i) {
    int h0, h1; tile_range(i, &h0, &h1);
    if (y < h0 || y >= h1) continue;
#pragma unroll
    for (int j = 0; j < 4; ++j) {
      int w0, w1; tile_range(j, &w0, &w1);
      if (x < w0 || x >= w1) continue;
      int Hsz = h1 - h0, Wsz = w1 - w0;
      int sv = (Hsz == 576 && Wsz == 576) ? 1 : 0;
      int r = y - h0, c = x - w0;
      float wy = g_wtab[(i * 2 + sv) * SEGMAX + r];
      float wx = g_wtab[(j * 2 + sv) * SEGMAX + c];
      int t = i * 4 + j;
      s += g_acc[(size_t)((b * 3 + l) * 16 + t) * (SEGMAX * SEGMAX) + (size_t)r * Wsz + c];
      wsum += wy * wx;
    }
  }
  float res = s / fmaxf(wsum, 1e-12f);
  if (!(res == res)) res = 0.0f;
  outp[idx] = res;
}

extern "C" void kernel_launch(void* const* d_in, const int* in_sizes, int n_in,
                              void* d_out, int out_size) {
  const float* Timg = (const float*)d_in[0];
  const float* psfs = (const float*)d_in[1];
  (void)in_sizes; (void)n_in;
  float* outp = (float*)d_out;

  cudaFuncSetAttribute(seg_p1,      cudaFuncAttributeMaxDynamicSharedMemorySize, (int)S16_SMEM);
  cudaFuncSetAttribute(psf_p1,      cudaFuncAttributeMaxDynamicSharedMemorySize, (int)S16_SMEM);
  cudaFuncSetAttribute(conv_ifft_y, cudaFuncAttributeMaxDynamicSharedMemorySize, (int)S16_SMEM);
  cudaFuncSetAttribute(seg_p2,      cudaFuncAttributeMaxDynamicSharedMemorySize, (int)S1_SMEM);
  cudaFuncSetAttribute(psf_p2,      cudaFuncAttributeMaxDynamicSharedMemorySize, (int)S1_SMEM);
  cudaFuncSetAttribute(conv_ifft_x, cudaFuncAttributeMaxDynamicSharedMemorySize, (int)S1_SMEM);

  init_wtab_kernel<<<18, 256>>>();
  init_tw_kernel<<<2, 256>>>();

  seg_p1<<<dim3(36, 32), 512, S16_SMEM>>>(Timg);
  seg_p2<<<dim3(NF, 32), 512, S1_SMEM>>>();
  psf_p1<<<dim3(8, 48), 512, S16_SMEM>>>(psfs);
  psf_p2<<<dim3(NF, 48), 512, S1_SMEM>>>();

  for (int l = 0; l < 3; ++l) {
    conv_ifft_y<<<dim3(64, 32), 512, S16_SMEM>>>(l);
    conv_ifft_x<<<dim3(SEGMAX, 32), 512, S1_SMEM>>>(l);
  }

  size_t total = (size_t)2 * 3 * IMG * IMG;
  finalize_kernel<<<(unsigned)((total + 255) / 256), 256>>>(outp);
}

// round 4
// speedup vs baseline: 24.6363x; 2.5732x over previous
#include <cuda_runtime.h>
#include <math.h>

#ifndef M_PI
#define M_PI 3.14159265358979323846
#endif

// Problem constants (fixed shapes: (2,1,2048,2048) images, (3,16,128,128) psfs, overlap=64)
#define IMG     2048
#define HS_     512
#define OV2     32
#define PK      128
#define SEGMAX  576
#define NF      1024

#define CSTRP   1057                    // padded per-column float2 stride (>= 1023+31+1)
#define PD(i)   ((i) + ((i) >> 5))      // smem pad: +1 float2 per 32
#define TWN     341                     // per-stage compacted twiddles: 256+64+16+4+1

// ---------------- static scratch ----------------
__device__ float  g_acc[(size_t)2 * 3 * 16 * SEGMAX * SEGMAX];       // 127 MB
__device__ float  g_wtab[4 * 2 * SEGMAX];
__device__ float2 g_tw4[TWN];
__device__ float2 g_segF[(size_t)32 * NF * NF];                      // 268 MB  [a][fy'][fx'] (scrambled)
__device__ float2 g_psfF[(size_t)48 * NF * NF];                      // 402 MB  [al][fy'][fx']
// multi-use: seg mid [32][1024][576]; psf mid [48][1024][128]; Q [96][576][1024]
__device__ float2 g_mid[(size_t)96 * SEGMAX * NF];                   // 453 MB

__device__ __forceinline__ void tile_range(int i, int* a0, int* a1) {
  int lo = i * HS_ - OV2; if (lo < 0) lo = 0;
  int hi = (i + 1) * HS_ + OV2; if (hi > IMG) hi = IMG;
  *a0 = lo; *a1 = hi;
}
__device__ __forceinline__ float2 cmul(float2 a, float2 b) {
  return make_float2(a.x * b.x - a.y * b.y, a.x * b.y + a.y * b.x);
}

// ---------------- init ----------------
__global__ void init_wtab_kernel() {
  int idx = blockIdx.x * blockDim.x + threadIdx.x;
  if (idx >= 4 * 2 * SEGMAX) return;
  int p  = idx % SEGMAX;
  int sv = (idx / SEGMAX) & 1;
  int i  = idx / (2 * SEGMAX);
  int a0, a1; tile_range(i, &a0, &a1);
  int S = a1 - a0;
  float val = 0.0f;
  if (p < S) {
    float sigma = sv ? 144.0f : 136.0f;
    float v = -0.5f * (float)S + (float)p * ((float)S / (float)(S - 1));
    val = expf(-0.5f * v * v / (sigma * sigma));
  }
  g_wtab[idx] = val;
}

__global__ void init_tw4_kernel() {
  int idx = blockIdx.x * blockDim.x + threadIdx.x;
  if (idx >= TWN) return;
  int s, m;
  if      (idx < 256) { s = 0; m = idx; }
  else if (idx < 320) { s = 1; m = idx - 256; }
  else if (idx < 336) { s = 2; m = idx - 320; }
  else if (idx < 340) { s = 3; m = idx - 336; }
  else                { s = 4; m = 0; }
  double ang = -2.0 * M_PI * (double)(m << (2 * s)) / (double)NF;
  double sn, cs; sincos(ang, &sn, &cs);
  g_tw4[idx] = make_float2((float)cs, (float)sn);
}

// ---------------- radix-4 FFT, 1024 pt, in padded smem columns ----------------
// Forward: DIF, natural input -> base-4 digit-scrambled output.
// Inverse: DIT, scrambled input -> natural output (unscaled).
// Block = 512 threads. Each column is owned by 512/NCOLS consecutive threads
// (warps never straddle columns -> lane-consecutive smem addresses).
template<int NCOLS, bool INV>
__device__ __forceinline__ void fft4_run(float2* cols, const float2* tws, int tid) {
  const int TPC = 512 / NCOLS;
  float2* col = cols + (tid / TPC) * CSTRP;
  int tc = tid % TPC;
#pragma unroll
  for (int ss = 0; ss < 5; ++ss) {
    const int s   = INV ? (4 - ss) : ss;
    const int qsh = 8 - 2 * s;
    const int q   = 1 << qsh;
    const int off = (s == 0) ? 0 : (s == 1) ? 256 : (s == 2) ? 320 : (s == 3) ? 336 : 340;
    __syncthreads();
#pragma unroll 1
    for (int bf = tc; bf < 256; bf += TPC) {
      int m  = bf & (q - 1);
      int i0 = ((bf >> qsh) << (qsh + 2)) + m;
      float2 w1 = tws[off + m];
      if (INV) w1.y = -w1.y;
      float2 w2 = cmul(w1, w1);
      float2 w3 = cmul(w2, w1);
      int p0 = PD(i0), p1 = PD(i0 + q), p2 = PD(i0 + 2 * q), p3 = PD(i0 + 3 * q);
      float2 a = col[p0], b = col[p1], c = col[p2], d = col[p3];
      if (!INV) {
        float2 t0 = make_float2(a.x + c.x, a.y + c.y);
        float2 t1 = make_float2(a.x - c.x, a.y - c.y);
        float2 t2 = make_float2(b.x + d.x, b.y + d.y);
        float2 t3 = make_float2(b.x - d.x, b.y - d.y);
        float2 u1 = make_float2(t1.x + t3.y, t1.y - t3.x);   // t1 - i*t3
        float2 u3 = make_float2(t1.x - t3.y, t1.y + t3.x);   // t1 + i*t3
        col[p0] = make_float2(t0.x + t2.x, t0.y + t2.y);
        col[p1] = cmul(u1, w1);
        col[p2] = cmul(make_float2(t0.x - t2.x, t0.y - t2.y), w2);
        col[p3] = cmul(u3, w3);
      } else {
        float2 bb = cmul(b, w1), cc = cmul(c, w2), dd = cmul(d, w3);
        float2 t0 = make_float2(a.x + cc.x, a.y + cc.y);
        float2 t1 = make_float2(a.x - cc.x, a.y - cc.y);
        float2 t2 = make_float2(bb.x + dd.x, bb.y + dd.y);
        float2 t3 = make_float2(bb.x - dd.x, bb.y - dd.y);
        col[p0] = make_float2(t0.x + t2.x, t0.y + t2.y);
        col[p1] = make_float2(t1.x - t3.y, t1.y + t3.x);     // t1 + i*t3
        col[p2] = make_float2(t0.x - t2.x, t0.y - t2.y);
        col[p3] = make_float2(t1.x + t3.y, t1.y - t3.x);     // t1 - i*t3
      }
    }
  }
  __syncthreads();
}

#define SM8_BYTES ((344 + 8 * CSTRP) * sizeof(float2))   // 70.4 KB
#define SM2_BYTES ((344 + 2 * CSTRP) * sizeof(float2))   // 19.7 KB

__device__ __forceinline__ void load_tws(float2* tws, int tid) {
  for (int i = tid; i < TWN; i += 512) tws[i] = g_tw4[i];
}

// ---------------- seg pass 1: forward FFT along y ----------------
// grid (72, 32) block 512; 8 columns/block. writes g_mid[a][fy'][C] (stride 576)
__global__ __launch_bounds__(512) void seg_fy(const float* __restrict__ Timg) {
  int g = blockIdx.x, a = blockIdx.y;
  int b = a >> 4, t = a & 15, ti = t >> 2, tj = t & 3;
  int h0, h1, w0, w1; tile_range(ti, &h0, &h1); tile_range(tj, &w0, &w1);
  int Hsz = h1 - h0, Wsz = w1 - w0;
  extern __shared__ float2 sm[];
  float2* tws = sm; float2* cols = sm + 344;
  int tid = threadIdx.x;
  load_tws(tws, tid);
  const float* Tb = Timg + (size_t)b * IMG * IMG;
  for (int idx = tid; idx < 8 * NF; idx += 512) {
    int c = idx >> 10, R = idx & 1023;
    int C = g * 8 + c;
    float v = 0.0f;
    if (R < Hsz && C < Wsz)
      v = Tb[(size_t)(w0 + C) * IMG + (IMG - 1 - (h0 + R))];
    cols[c * CSTRP + PD(R)] = make_float2(v, 0.0f);
  }
  fft4_run<8, false>(cols, tws, tid);
  float2* outp = g_mid + (size_t)a * NF * SEGMAX;
  for (int idx = tid; idx < NF * 8; idx += 512) {
    int fy = idx >> 3, c = idx & 7;
    outp[(size_t)fy * SEGMAX + g * 8 + c] = cols[c * CSTRP + PD(fy)];
  }
}

// ---------------- seg pass 2: forward FFT along x ----------------
// grid (512, 32) block 512; 2 rows/block
__global__ __launch_bounds__(512) void seg_fx() {
  int fy0 = blockIdx.x * 2, a = blockIdx.y;
  extern __shared__ float2 sm[];
  float2* tws = sm; float2* cols = sm + 344;
  int tid = threadIdx.x;
  load_tws(tws, tid);
  for (int idx = tid; idx < 2 * NF; idx += 512) {
    int row = idx >> 10, C = idx & 1023;
    float2 v = make_float2(0.0f, 0.0f);
    if (C < SEGMAX) v = g_mid[((size_t)a * NF + fy0 + row) * SEGMAX + C];
    cols[row * CSTRP + PD(C)] = v;
  }
  fft4_run<2, false>(cols, tws, tid);
  for (int idx = tid; idx < 2 * NF; idx += 512) {
    int row = idx >> 10, fx = idx & 1023;
    g_segF[((size_t)a * NF + fy0 + row) * NF + fx] = cols[row * CSTRP + PD(fx)];
  }
}

// ---------------- psf pass 1: forward FFT along p ----------------
// grid (16, 48) block 512. k[p][q] = psfs[l,hd,q,127-p]. writes g_mid[ap][fy'][q] (stride 128)
__global__ __launch_bounds__(512) void psf_fy(const float* __restrict__ psfs) {
  int g = blockIdx.x, ap = blockIdx.y;
  int l = ap / 16, t = ap % 16, ti = t >> 2, tj = t & 3;
  int hd = tj * 4 + ti;
  extern __shared__ float2 sm[];
  float2* tws = sm; float2* cols = sm + 344;
  int tid = threadIdx.x;
  load_tws(tws, tid);
  for (int idx = tid; idx < 8 * NF; idx += 512) {
    int c = idx >> 10, p = idx & 1023;
    int C = g * 8 + c;   // q index, < 128
    float v = 0.0f;
    if (p < PK)
      v = psfs[(((size_t)l * 16 + hd) * PK + C) * PK + (PK - 1 - p)];
    cols[c * CSTRP + PD(p)] = make_float2(v, 0.0f);
  }
  fft4_run<8, false>(cols, tws, tid);
  float2* outp = g_mid + (size_t)ap * NF * PK;
  for (int idx = tid; idx < NF * 8; idx += 512) {
    int fy = idx >> 3, c = idx & 7;
    outp[(size_t)fy * PK + g * 8 + c] = cols[c * CSTRP + PD(fy)];
  }
}

// ---------------- psf pass 2: forward FFT along q ----------------
// grid (512, 48) block 512; 2 rows/block
__global__ __launch_bounds__(512) void psf_fx() {
  int fy0 = blockIdx.x * 2, ap = blockIdx.y;
  extern __shared__ float2 sm[];
  float2* tws = sm; float2* cols = sm + 344;
  int tid = threadIdx.x;
  load_tws(tws, tid);
  for (int idx = tid; idx < 2 * NF; idx += 512) {
    int row = idx >> 10, C = idx & 1023;
    float2 v = make_float2(0.0f, 0.0f);
    if (C < PK) v = g_mid[((size_t)ap * NF + fy0 + row) * PK + C];
    cols[row * CSTRP + PD(C)] = v;
  }
  fft4_run<2, false>(cols, tws, tid);
  for (int idx = tid; idx < 2 * NF; idx += 512) {
    int row = idx >> 10, fx = idx & 1023;
    g_psfF[((size_t)ap * NF + fy0 + row) * NF + fx] = cols[row * CSTRP + PD(fx)];
  }
}

// ---------------- inverse pass 1: pointwise product (scrambled domain) + IFFT along fy ----
// grid (128, 32, 3) block 512; 8 fx-columns/block. Q = g_mid[(l*32+a)][r][fx'] (r = y-64)
__global__ __launch_bounds__(512) void conv_ifft_y() {
  int g = blockIdx.x, a = blockIdx.y, l = blockIdx.z;
  int t = a & 15;
  int al = l * 16 + t;
  extern __shared__ float2 sm[];
  float2* tws = sm; float2* cols = sm + 344;
  int tid = threadIdx.x;
  load_tws(tws, tid);
  const float2* Sb = g_segF + (size_t)a * NF * NF;
  const float2* Fb = g_psfF + (size_t)al * NF * NF;
  for (int idx = tid; idx < NF * 8; idx += 512) {
    int fy = idx >> 3, c = idx & 7;
    int fx = g * 8 + c;
    float2 S = Sb[(size_t)fy * NF + fx];
    float2 F = Fb[(size_t)fy * NF + fx];
    cols[c * CSTRP + PD(fy)] = cmul(S, F);
  }
  fft4_run<8, true>(cols, tws, tid);
  const float sc = 1.0f / (float)NF;
  float2* Q = g_mid + (size_t)(l * 32 + a) * SEGMAX * NF;
  for (int idx = tid; idx < SEGMAX * 8; idx += 512) {
    int r = idx >> 3, c = idx & 7;
    float2 v = cols[c * CSTRP + PD(r + 64)];
    Q[(size_t)r * NF + g * 8 + c] = make_float2(v.x * sc, v.y * sc);
  }
}

// ---------------- inverse pass 2: IFFT along fx + window + store to g_acc ----------------
// grid (288, 32, 3) block 512; 2 rows/block
__global__ __launch_bounds__(512) void conv_ifft_x() {
  int r0 = blockIdx.x * 2, a = blockIdx.y, l = blockIdx.z;
  int b = a >> 4, t = a & 15, ti = t >> 2, tj = t & 3;
  int h0, h1, w0, w1; tile_range(ti, &h0, &h1); tile_range(tj, &w0, &w1);
  int Hsz = h1 - h0, Wsz = w1 - w0;
  extern __shared__ float2 sm[];
  float2* tws = sm; float2* cols = sm + 344;
  int tid = threadIdx.x;
  load_tws(tws, tid);
  const float2* Q = g_mid + (size_t)(l * 32 + a) * SEGMAX * NF;
  for (int idx = tid; idx < 2 * NF; idx += 512) {
    int row = idx >> 10, fx = idx & 1023;
    cols[row * CSTRP + PD(fx)] = Q[(size_t)(r0 + row) * NF + fx];
  }
  fft4_run<2, true>(cols, tws, tid);
  int sv = (Hsz == 576 && Wsz == 576) ? 1 : 0;
  const float sc = 1.0f / (float)NF;
  float* outbase = g_acc + (size_t)((b * 3 + l) * 16 + t) * (SEGMAX * SEGMAX);
  for (int e = tid; e < 2 * SEGMAX; e += 512) {
    int row = (e >= SEGMAX) ? 1 : 0;
    int x = e - row * SEGMAX;
    int r = r0 + row;
    if (r < Hsz && x < Wsz) {
      float wy = g_wtab[(ti * 2 + sv) * SEGMAX + r];
      float wx = g_wtab[(tj * 2 + sv) * SEGMAX + x];
      outbase[(size_t)r * Wsz + x] = cols[row * CSTRP + PD(64 + x)].x * sc * wy * wx;
    }
  }
}

// ---------------- overlap-add gather + normalize + inverse rotation ----------------
__global__ __launch_bounds__(256) void finalize_kernel(float* __restrict__ outp) {
  size_t idx = (size_t)blockIdx.x * 256 + threadIdx.x;
  if (idx >= (size_t)2 * 3 * IMG * IMG) return;
  int J = (int)(idx & (IMG - 1));
  size_t r2 = idx >> 11;
  int I = (int)(r2 & (IMG - 1));
  size_t r3 = r2 >> 11;
  int l = (int)(r3 % 3);
  int b = (int)(r3 / 3);
  int y = IMG - 1 - J;
  int x = I;
  float s = 0.0f, wsum = 0.0f;
#pragma unroll
  for (int i = 0; i < 4; ++i) {
    int h0, h1; tile_range(i, &h0, &h1);
    if (y < h0 || y >= h1) continue;
#pragma unroll
    for (int j = 0; j < 4; ++j) {
      int w0, w1; tile_range(j, &w0, &w1);
      if (x < w0 || x >= w1) continue;
      int Hsz = h1 - h0, Wsz = w1 - w0;
      int sv = (Hsz == 576 && Wsz == 576) ? 1 : 0;
      int r = y - h0, c = x - w0;
      float wy = g_wtab[(i * 2 + sv) * SEGMAX + r];
      float wx = g_wtab[(j * 2 + sv) * SEGMAX + c];
      int t = i * 4 + j;
      s += g_acc[(size_t)((b * 3 + l) * 16 + t) * (SEGMAX * SEGMAX) + (size_t)r * Wsz + c];
      wsum += wy * wx;
    }
  }
  float res = s / fmaxf(wsum, 1e-12f);
  if (!(res == res)) res = 0.0f;
  outp[idx] = res;
}

extern "C" void kernel_launch(void* const* d_in, const int* in_sizes, int n_in,
                              void* d_out, int out_size) {
  const float* Timg = (const float*)d_in[0];
  const float* psfs = (const float*)d_in[1];
  (void)in_sizes; (void)n_in;
  float* outp = (float*)d_out;

  cudaFuncSetAttribute(seg_fy,      cudaFuncAttributeMaxDynamicSharedMemorySize, (int)SM8_BYTES);
  cudaFuncSetAttribute(psf_fy,      cudaFuncAttributeMaxDynamicSharedMemorySize, (int)SM8_BYTES);
  cudaFuncSetAttribute(conv_ifft_y, cudaFuncAttributeMaxDynamicSharedMemorySize, (int)SM8_BYTES);

  init_wtab_kernel<<<18, 256>>>();
  init_tw4_kernel<<<2, 256>>>();

  seg_fy<<<dim3(72, 32), 512, SM8_BYTES>>>(Timg);
  seg_fx<<<dim3(512, 32), 512, SM2_BYTES>>>();
  psf_fy<<<dim3(16, 48), 512, SM8_BYTES>>>(psfs);
  psf_fx<<<dim3(512, 48), 512, SM2_BYTES>>>();

  conv_ifft_y<<<dim3(128, 32, 3), 512, SM8_BYTES>>>();
  conv_ifft_x<<<dim3(288, 32, 3), 512, SM2_BYTES>>>();

  size_t total = (size_t)2 * 3 * IMG * IMG;
  finalize_kernel<<<(unsigned)((total + 255) / 256), 256>>>(outp);
}

// round 5
// speedup vs baseline: 29.3244x; 1.1903x over previous
#include <cuda_runtime.h>
#include <math.h>

#ifndef M_PI
#define M_PI 3.14159265358979323846
#endif

// Problem constants (fixed shapes: (2,1,2048,2048) images, (3,16,128,128) psfs, overlap=64)
#define IMG     2048
#define HS_     512
#define OV2     32
#define PK      128
#define SEGMAX  576
#define NF      1024
#define NH      513                    // Hermitian rows: fy in [0,512]

#define CSTRP   1057                    // padded per-column float2 stride
#define PD(i)   ((i) + ((i) >> 5))      // smem pad: +1 float2 per 32
#define TWN     341                     // per-stage compacted twiddles: 256+64+16+4+1

// ---------------- static scratch ----------------
__device__ __align__(16) float  g_acc[(size_t)2 * 3 * 16 * SEGMAX * SEGMAX];   // 127 MB
__device__ float  g_wtab[4 * 2 * SEGMAX];
__device__ float2 g_tw4[TWN];
__device__ __align__(16) float2 g_segF[(size_t)32 * NH * NF];                  // 134 MB [a][fy][fx']
__device__ __align__(16) float2 g_psfF[(size_t)48 * NH * NF];                  // 202 MB [al][fy][fx']
// multi-use: seg mid [32][513][576]; psf mid [48][513][128]; Q [96][513][576]
__device__ __align__(16) float2 g_mid[(size_t)96 * NH * SEGMAX];               // 227 MB

__device__ __forceinline__ void tile_range(int i, int* a0, int* a1) {
  int lo = i * HS_ - OV2; if (lo < 0) lo = 0;
  int hi = (i + 1) * HS_ + OV2; if (hi > IMG) hi = IMG;
  *a0 = lo; *a1 = hi;
}
__device__ __forceinline__ float2 cmul(float2 a, float2 b) {
  return make_float2(a.x * b.x - a.y * b.y, a.x * b.y + a.y * b.x);
}
// base-4 digit reversal of 5 digits (engine scramble; involution): pos p holds X[drev4(p)]
__device__ __forceinline__ int drev4(int i) {
  return ((i & 3) << 8) | (((i >> 2) & 3) << 6) | (((i >> 4) & 3) << 4)
       | (((i >> 6) & 3) << 2) | ((i >> 8) & 3);
}

// ---------------- init ----------------
__global__ void init_wtab_kernel() {
  int idx = blockIdx.x * blockDim.x + threadIdx.x;
  if (idx >= 4 * 2 * SEGMAX) return;
  int p  = idx % SEGMAX;
  int sv = (idx / SEGMAX) & 1;
  int i  = idx / (2 * SEGMAX);
  int a0, a1; tile_range(i, &a0, &a1);
  int S = a1 - a0;
  float val = 0.0f;
  if (p < S) {
    float sigma = sv ? 144.0f : 136.0f;
    float v = -0.5f * (float)S + (float)p * ((float)S / (float)(S - 1));
    val = expf(-0.5f * v * v / (sigma * sigma));
  }
  g_wtab[idx] = val;
}

__global__ void init_tw4_kernel() {
  int idx = blockIdx.x * blockDim.x + threadIdx.x;
  if (idx >= TWN) return;
  int s, m;
  if      (idx < 256) { s = 0; m = idx; }
  else if (idx < 320) { s = 1; m = idx - 256; }
  else if (idx < 336) { s = 2; m = idx - 320; }
  else if (idx < 340) { s = 3; m = idx - 336; }
  else                { s = 4; m = 0; }
  double ang = -2.0 * M_PI * (double)(m << (2 * s)) / (double)NF;
  double sn, cs; sincos(ang, &sn, &cs);
  g_tw4[idx] = make_float2((float)cs, (float)sn);
}

// ---------------- radix-4 FFT, 1024 pt, in padded smem columns ----------------
// Forward: DIF, natural input -> base-4 digit-scrambled output (pos p holds X[drev4(p)]).
// Inverse: DIT, scrambled input (pos p holds Y[drev4(p)]) -> natural output (unscaled).
template<int NCOLS, bool INV>
__device__ __forceinline__ void fft4_run(float2* cols, const float2* tws, int tid) {
  const int TPC = 512 / NCOLS;
  float2* col = cols + (tid / TPC) * CSTRP;
  int tc = tid % TPC;
#pragma unroll
  for (int ss = 0; ss < 5; ++ss) {
    const int s   = INV ? (4 - ss) : ss;
    const int qsh = 8 - 2 * s;
    const int q   = 1 << qsh;
    const int off = (s == 0) ? 0 : (s == 1) ? 256 : (s == 2) ? 320 : (s == 3) ? 336 : 340;
    __syncthreads();
#pragma unroll 1
    for (int bf = tc; bf < 256; bf += TPC) {
      int m  = bf & (q - 1);
      int i0 = ((bf >> qsh) << (qsh + 2)) + m;
      float2 w1 = tws[off + m];
      if (INV) w1.y = -w1.y;
      float2 w2 = cmul(w1, w1);
      float2 w3 = cmul(w2, w1);
      int p0 = PD(i0), p1 = PD(i0 + q), p2 = PD(i0 + 2 * q), p3 = PD(i0 + 3 * q);
      float2 a = col[p0], b = col[p1], c = col[p2], d = col[p3];
      if (!INV) {
        float2 t0 = make_float2(a.x + c.x, a.y + c.y);
        float2 t1 = make_float2(a.x - c.x, a.y - c.y);
        float2 t2 = make_float2(b.x + d.x, b.y + d.y);
        float2 t3 = make_float2(b.x - d.x, b.y - d.y);
        float2 u1 = make_float2(t1.x + t3.y, t1.y - t3.x);
        float2 u3 = make_float2(t1.x - t3.y, t1.y + t3.x);
        col[p0] = make_float2(t0.x + t2.x, t0.y + t2.y);
        col[p1] = cmul(u1, w1);
        col[p2] = cmul(make_float2(t0.x - t2.x, t0.y - t2.y), w2);
        col[p3] = cmul(u3, w3);
      } else {
        float2 bb = cmul(b, w1), cc = cmul(c, w2), dd = cmul(d, w3);
        float2 t0 = make_float2(a.x + cc.x, a.y + cc.y);
        float2 t1 = make_float2(a.x - cc.x, a.y - cc.y);
        float2 t2 = make_float2(bb.x + dd.x, bb.y + dd.y);
        float2 t3 = make_float2(bb.x - dd.x, bb.y - dd.y);
        col[p0] = make_float2(t0.x + t2.x, t0.y + t2.y);
        col[p1] = make_float2(t1.x - t3.y, t1.y + t3.x);
        col[p2] = make_float2(t0.x - t2.x, t0.y - t2.y);
        col[p3] = make_float2(t1.x + t3.y, t1.y - t3.x);
      }
    }
  }
  __syncthreads();
}

#define SM8_BYTES ((344 + 8 * CSTRP) * sizeof(float2))   // 70.4 KB
#define SM2_BYTES ((344 + 2 * CSTRP) * sizeof(float2))   // 19.7 KB

__device__ __forceinline__ void load_tws(float2* tws, int tid) {
  for (int i = tid; i < TWN; i += 512) tws[i] = g_tw4[i];
}

// ---------------- seg pass 1: two-for-one forward FFT along y ----------------
// 8 packed FFTs/block = 16 real columns. grid (36, 32).
// Output: g_mid[a][fy 0..512][C] natural fy, C contiguous (stride 576).
__global__ __launch_bounds__(512) void seg_fy(const float* __restrict__ Timg) {
  int g = blockIdx.x, a = blockIdx.y;
  int b = a >> 4, t = a & 15, ti = t >> 2, tj = t & 3;
  int h0, h1, w0, w1; tile_range(ti, &h0, &h1); tile_range(tj, &w0, &w1);
  int Hsz = h1 - h0, Wsz = w1 - w0;
  extern __shared__ float2 sm[];
  float2* tws = sm; float2* cols = sm + 344;
  int tid = threadIdx.x;
  load_tws(tws, tid);
  const float* Tb = Timg + (size_t)b * IMG * IMG;
  for (int idx = tid; idx < 8 * NF; idx += 512) {
    int c = idx >> 10, R = idx & 1023;
    int C0 = g * 16 + 2 * c;
    float vr = 0.0f, vi = 0.0f;
    if (R < Hsz) {
      int base = IMG - 1 - (h0 + R);
      if (C0 < Wsz)     vr = Tb[(size_t)(w0 + C0) * IMG + base];
      if (C0 + 1 < Wsz) vi = Tb[(size_t)(w0 + C0 + 1) * IMG + base];
    }
    cols[c * CSTRP + PD(R)] = make_float2(vr, vi);
  }
  fft4_run<8, false>(cols, tws, tid);
  float2* outp = g_mid + (size_t)a * NH * SEGMAX;
  for (int idx = tid; idx < NH * 8; idx += 512) {
    int c = idx & 7, fy = idx >> 3;
    float2 z1 = cols[c * CSTRP + PD(drev4(fy))];
    float2 z2 = cols[c * CSTRP + PD(drev4((NF - fy) & (NF - 1)))];
    z2.y = -z2.y;   // conj
    float2 c0 = make_float2(0.5f * (z1.x + z2.x), 0.5f * (z1.y + z2.y));
    float2 c1 = make_float2(0.5f * (z1.y - z2.y), -0.5f * (z1.x - z2.x));
    float4* o4 = (float4*)(outp + (size_t)fy * SEGMAX + g * 16 + 2 * c);
    *o4 = make_float4(c0.x, c0.y, c1.x, c1.y);
  }
}

// ---------------- seg pass 2: forward FFT along x, rows fy=0..512 ----------------
// grid (257, 32); 2 rows/block, tail-guarded
__global__ __launch_bounds__(512) void seg_fx() {
  int fy0 = blockIdx.x * 2, a = blockIdx.y;
  extern __shared__ float2 sm[];
  float2* tws = sm; float2* cols = sm + 344;
  int tid = threadIdx.x;
  load_tws(tws, tid);
  const float2* mid = g_mid + (size_t)a * NH * SEGMAX;
  for (int idx = tid; idx < 2 * NF; idx += 512) {
    int row = idx >> 10, C = idx & 1023;
    int fy = fy0 + row; if (fy > 512) fy = 512;
    float2 v = make_float2(0.0f, 0.0f);
    if (C < SEGMAX) v = mid[(size_t)fy * SEGMAX + C];
    cols[row * CSTRP + PD(C)] = v;
  }
  fft4_run<2, false>(cols, tws, tid);
  for (int idx = tid; idx < 2 * NF; idx += 512) {
    int row = idx >> 10, fx = idx & 1023;
    if (fy0 + row <= 512)
      g_segF[((size_t)a * NH + fy0 + row) * NF + fx] = cols[row * CSTRP + PD(fx)];
  }
}

// ---------------- psf pass 1: two-for-one forward FFT along p ----------------
// grid (8, 48). k[p][q] = psfs[l,hd,q,127-p]. Output g_mid[ap][fy][q] (stride 128).
__global__ __launch_bounds__(512) void psf_fy(const float* __restrict__ psfs) {
  int g = blockIdx.x, ap = blockIdx.y;
  int l = ap / 16, t = ap % 16, ti = t >> 2, tj = t & 3;
  int hd = tj * 4 + ti;
  extern __shared__ float2 sm[];
  float2* tws = sm; float2* cols = sm + 344;
  int tid = threadIdx.x;
  load_tws(tws, tid);
  const float* Pb = psfs + ((size_t)l * 16 + hd) * PK * PK;
  for (int idx = tid; idx < 8 * NF; idx += 512) {
    int c = idx >> 10, p = idx & 1023;
    int q0 = g * 16 + 2 * c;
    float vr = 0.0f, vi = 0.0f;
    if (p < PK) {
      vr = Pb[(size_t)q0 * PK + (PK - 1 - p)];
      vi = Pb[(size_t)(q0 + 1) * PK + (PK - 1 - p)];
    }
    cols[c * CSTRP + PD(p)] = make_float2(vr, vi);
  }
  fft4_run<8, false>(cols, tws, tid);
  float2* outp = g_mid + (size_t)ap * NH * PK;
  for (int idx = tid; idx < NH * 8; idx += 512) {
    int c = idx & 7, fy = idx >> 3;
    float2 z1 = cols[c * CSTRP + PD(drev4(fy))];
    float2 z2 = cols[c * CSTRP + PD(drev4((NF - fy) & (NF - 1)))];
    z2.y = -z2.y;
    float2 c0 = make_float2(0.5f * (z1.x + z2.x), 0.5f * (z1.y + z2.y));
    float2 c1 = make_float2(0.5f * (z1.y - z2.y), -0.5f * (z1.x - z2.x));
    float4* o4 = (float4*)(outp + (size_t)fy * PK + g * 16 + 2 * c);
    *o4 = make_float4(c0.x, c0.y, c1.x, c1.y);
  }
}

// ---------------- psf pass 2: forward FFT along q, rows fy=0..512 ----------------
// grid (257, 48)
__global__ __launch_bounds__(512) void psf_fx() {
  int fy0 = blockIdx.x * 2, ap = blockIdx.y;
  extern __shared__ float2 sm[];
  float2* tws = sm; float2* cols = sm + 344;
  int tid = threadIdx.x;
  load_tws(tws, tid);
  const float2* mid = g_mid + (size_t)ap * NH * PK;
  for (int idx = tid; idx < 2 * NF; idx += 512) {
    int row = idx >> 10, C = idx & 1023;
    int fy = fy0 + row; if (fy > 512) fy = 512;
    float2 v = make_float2(0.0f, 0.0f);
    if (C < PK) v = mid[(size_t)fy * PK + C];
    cols[row * CSTRP + PD(C)] = v;
  }
  fft4_run<2, false>(cols, tws, tid);
  for (int idx = tid; idx < 2 * NF; idx += 512) {
    int row = idx >> 10, fx = idx & 1023;
    if (fy0 + row <= 512)
      g_psfF[((size_t)ap * NH + fy0 + row) * NF + fx] = cols[row * CSTRP + PD(fx)];
  }
}

// ---------------- inverse pass A: pointwise product + IFFT along x (513 rows) --------
// grid (257, 32, 3); 2 rows/block. Stores Q[(l*32+a)][fy][x-64] for x in [64,640).
__global__ __launch_bounds__(512) void conv_x() {
  int fy0 = blockIdx.x * 2, a = blockIdx.y, l = blockIdx.z;
  int al = l * 16 + (a & 15);
  extern __shared__ float2 sm[];
  float2* tws = sm; float2* cols = sm + 344;
  int tid = threadIdx.x;
  load_tws(tws, tid);
  const float2* Sb = g_segF + (size_t)a * NH * NF;
  const float2* Fb = g_psfF + (size_t)al * NH * NF;
  for (int idx = tid; idx < 2 * NF; idx += 512) {
    int row = idx >> 10, fx = idx & 1023;
    int fy = fy0 + row; if (fy > 512) fy = 512;
    float2 S = Sb[(size_t)fy * NF + fx];
    float2 F = Fb[(size_t)fy * NF + fx];
    cols[row * CSTRP + PD(fx)] = cmul(S, F);
  }
  fft4_run<2, true>(cols, tws, tid);
  const float sc = 1.0f / (float)NF;
  float2* Q = g_mid + (size_t)(l * 32 + a) * NH * SEGMAX;
  for (int idx = tid; idx < 2 * SEGMAX; idx += 512) {
    int row = (idx >= SEGMAX) ? 1 : 0;
    int x = idx - row * SEGMAX;
    if (fy0 + row <= 512) {
      float2 v = cols[row * CSTRP + PD(64 + x)];
      Q[(size_t)(fy0 + row) * SEGMAX + x] = make_float2(v.x * sc, v.y * sc);
    }
  }
}

// ---------------- inverse pass B: C2R IFFT along y (two columns per FFT) -------------
// grid (36, 32, 3); 8 packed FFTs/block = 16 x-columns. Window + store to g_acc.
__global__ __launch_bounds__(512) void conv_y() {
  int g = blockIdx.x, a = blockIdx.y, l = blockIdx.z;
  int b = a >> 4, t = a & 15, ti = t >> 2, tj = t & 3;
  int h0, h1, w0, w1; tile_range(ti, &h0, &h1); tile_range(tj, &w0, &w1);
  int Hsz = h1 - h0, Wsz = w1 - w0;
  extern __shared__ float2 sm[];
  float2* tws = sm; float2* cols = sm + 344;
  int tid = threadIdx.x;
  load_tws(tws, tid);
  const float2* Q = g_mid + (size_t)(l * 32 + a) * NH * SEGMAX;
  // Build full H spectrum (scrambled positions): H[fy] = Q0[fy] + i*Q1[fy],
  // H[1024-fy] = conj(Q0[fy]) + i*conj(Q1[fy]).
  for (int idx = tid; idx < NH * 8; idx += 512) {
    int c = idx & 7, fy = idx >> 3;
    const float4 q4 = *(const float4*)(Q + (size_t)fy * SEGMAX + g * 16 + 2 * c);
    // q0 = (q4.x, q4.y), q1 = (q4.z, q4.w)
    cols[c * CSTRP + PD(drev4(fy))] = make_float2(q4.x - q4.w, q4.y + q4.z);
    if (fy >= 1 && fy <= 511)
      cols[c * CSTRP + PD(drev4(NF - fy))] = make_float2(q4.x + q4.w, q4.z - q4.y);
  }
  fft4_run<8, true>(cols, tws, tid);
  int sv = (Hsz == 576 && Wsz == 576) ? 1 : 0;
  const float sc = 1.0f / (float)NF;
  float* outbase = g_acc + (size_t)((b * 3 + l) * 16 + t) * (SEGMAX * SEGMAX);
  for (int idx = tid; idx < 8 * SEGMAX; idx += 512) {
    int c = idx & 7, r = idx >> 3;
    int x0 = g * 16 + 2 * c;
    if (r < Hsz && x0 < Wsz) {
      float2 v = cols[c * CSTRP + PD(r + 64)];
      float wy  = g_wtab[(ti * 2 + sv) * SEGMAX + r];
      float wx0 = g_wtab[(tj * 2 + sv) * SEGMAX + x0];
      float wx1 = g_wtab[(tj * 2 + sv) * SEGMAX + x0 + 1];
      float2 o = make_float2(v.x * sc * wy * wx0, v.y * sc * wy * wx1);
      *(float2*)(outbase + (size_t)r * Wsz + x0) = o;
    }
  }
}

// ---------------- overlap-add gather + normalize + inverse rotation ----------------
__global__ __launch_bounds__(256) void finalize_kernel(float* __restrict__ outp) {
  size_t idx = (size_t)blockIdx.x * 256 + threadIdx.x;
  if (idx >= (size_t)2 * 3 * IMG * IMG) return;
  int J = (int)(idx & (IMG - 1));
  size_t r2 = idx >> 11;
  int I = (int)(r2 & (IMG - 1));
  size_t r3 = r2 >> 11;
  int l = (int)(r3 % 3);
  int b = (int)(r3 / 3);
  int y = IMG - 1 - J;
  int x = I;
  float s = 0.0f, wsum = 0.0f;
#pragma unroll
  for (int i = 0; i < 4; ++i) {
    int h0, h1; tile_range(i, &h0, &h1);
    if (y < h0 || y >= h1) continue;
#pragma unroll
    for (int j = 0; j < 4; ++j) {
      int w0, w1; tile_range(j, &w0, &w1);
      if (x < w0 || x >= w1) continue;
      int Hsz = h1 - h0, Wsz = w1 - w0;
      int sv = (Hsz == 576 && Wsz == 576) ? 1 : 0;
      int r = y - h0, c = x - w0;
      float wy = g_wtab[(i * 2 + sv) * SEGMAX + r];
      float wx = g_wtab[(j * 2 + sv) * SEGMAX + c];
      int t = i * 4 + j;
      s += g_acc[(size_t)((b * 3 + l) * 16 + t) * (SEGMAX * SEGMAX) + (size_t)r * Wsz + c];
      wsum += wy * wx;
    }
  }
  float res = s / fmaxf(wsum, 1e-12f);
  if (!(res == res)) res = 0.0f;
  outp[idx] = res;
}

extern "C" void kernel_launch(void* const* d_in, const int* in_sizes, int n_in,
                              void* d_out, int out_size) {
  const float* Timg = (const float*)d_in[0];
  const float* psfs = (const float*)d_in[1];
  (void)in_sizes; (void)n_in;
  float* outp = (float*)d_out;

  cudaFuncSetAttribute(seg_fy, cudaFuncAttributeMaxDynamicSharedMemorySize, (int)SM8_BYTES);
  cudaFuncSetAttribute(psf_fy, cudaFuncAttributeMaxDynamicSharedMemorySize, (int)SM8_BYTES);
  cudaFuncSetAttribute(conv_y, cudaFuncAttributeMaxDynamicSharedMemorySize, (int)SM8_BYTES);

  init_wtab_kernel<<<18, 256>>>();
  init_tw4_kernel<<<2, 256>>>();

  seg_fy<<<dim3(36, 32), 512, SM8_BYTES>>>(Timg);
  seg_fx<<<dim3(257, 32), 512, SM2_BYTES>>>();
  psf_fy<<<dim3(8, 48), 512, SM8_BYTES>>>(psfs);
  psf_fx<<<dim3(257, 48), 512, SM2_BYTES>>>();

  conv_x<<<dim3(257, 32, 3), 512, SM2_BYTES>>>();
  conv_y<<<dim3(36, 32, 3), 512, SM8_BYTES>>>();

  size_t total = (size_t)2 * 3 * IMG * IMG;
  finalize_kernel<<<(unsigned)((total + 255) / 256), 256>>>(outp);
}

// round 6
// speedup vs baseline: 60.5799x; 2.0659x over previous
#include <cuda_runtime.h>
#include <math.h>

#ifndef M_PI
#define M_PI 3.14159265358979323846
#endif

// Problem constants (fixed shapes: (2,1,2048,2048) images, (3,16,128,128) psfs, overlap=64)
#define IMG     2048
#define HS_     512
#define OV2     32
#define PK      128
#define SEGMAX  576
#define NF      768                     // FFT length = 3 * 4^4  (>= 703 support)
#define NH      385                     // Hermitian rows: fy in [0,384]

#define CSTRP   791                     // padded per-column float2 stride (>= PD(767)+1)
#define PD(i)   ((i) + ((i) >> 5))      // smem pad: +1 float2 per 32
#define TWN     341                     // 256 (radix-3 stage W^n) + 85 (radix-4 tables 64+16+4+1)
#define S3F     0.86602540378443864676f // sqrt(3)/2

// ---------------- static scratch ----------------
__device__ __align__(16) float  g_acc[(size_t)2 * 3 * 16 * SEGMAX * SEGMAX];   // 127 MB
__device__ float  g_wtab[4 * 2 * SEGMAX];
__device__ float2 g_twm[TWN];
__device__ __align__(16) float2 g_segF[(size_t)32 * NH * NF];                  // 76 MB  [a][fy][fx']
__device__ __align__(16) float2 g_psfF[(size_t)48 * NH * NF];                  // 113 MB [al][fy][fx']
// multi-use: seg mid [32][385][576]; psf mid [48][385][128]; Q [96][385][576]
__device__ __align__(16) float2 g_mid[(size_t)96 * NH * SEGMAX];               // 170 MB

__device__ __forceinline__ void tile_range(int i, int* a0, int* a1) {
  int lo = i * HS_ - OV2; if (lo < 0) lo = 0;
  int hi = (i + 1) * HS_ + OV2; if (hi > IMG) hi = IMG;
  *a0 = lo; *a1 = hi;
}
__device__ __forceinline__ float2 cmul(float2 a, float2 b) {
  return make_float2(a.x * b.x - a.y * b.y, a.x * b.y + a.y * b.x);
}
// 4-digit base-4 reversal (involution)
__device__ __forceinline__ int drev4_4(int k) {
  return ((k & 3) << 6) | (((k >> 2) & 3) << 4) | (((k >> 4) & 3) << 2) | ((k >> 6) & 3);
}
// smem position holding natural frequency f (engine scramble): chunk = f%3, within-chunk drev
__device__ __forceinline__ int posf(int f) {
  return (f % 3) * 256 + drev4_4(f / 3);
}

// ---------------- init ----------------
__global__ void init_wtab_kernel() {
  int idx = blockIdx.x * blockDim.x + threadIdx.x;
  if (idx >= 4 * 2 * SEGMAX) return;
  int p  = idx % SEGMAX;
  int sv = (idx / SEGMAX) & 1;
  int i  = idx / (2 * SEGMAX);
  int a0, a1; tile_range(i, &a0, &a1);
  int S = a1 - a0;
  float val = 0.0f;
  if (p < S) {
    float sigma = sv ? 144.0f : 136.0f;
    float v = -0.5f * (float)S + (float)p * ((float)S / (float)(S - 1));
    val = expf(-0.5f * v * v / (sigma * sigma));
  }
  g_wtab[idx] = val;
}

__global__ void init_twm_kernel() {
  int idx = blockIdx.x * blockDim.x + threadIdx.x;
  if (idx >= TWN) return;
  double ang;
  if (idx < 256) {
    ang = -2.0 * M_PI * (double)idx / (double)NF;           // W^n, N=768
  } else {
    int j = idx - 256;
    int m, denom;
    if      (j < 64) { m = j;      denom = 256; }
    else if (j < 80) { m = j - 64; denom = 64;  }
    else if (j < 84) { m = j - 80; denom = 16;  }
    else             { m = 0;      denom = 4;   }
    ang = -2.0 * M_PI * (double)m / (double)denom;
  }
  double sn, cs; sincos(ang, &sn, &cs);
  g_twm[idx] = make_float2((float)cs, (float)sn);
}

// ---------------- mixed-radix 768-pt FFT (3 * 4^4) in padded smem columns ----------------
// Forward (DIF): natural input -> scrambled output: pos g*256+p holds X[3*drev4_4(p)+g].
// Inverse (DIT): scrambled input in same layout -> natural output (unscaled).
template<int NCOLS, bool INV>
__device__ __forceinline__ void fft768_run(float2* cols, const float2* tws, int tid) {
  const int TPC = 512 / NCOLS;
  float2* col = cols + (tid / TPC) * CSTRP;
  int tc = tid % TPC;
  const float2* tw3 = tws;         // 256 entries
  const float2* tw4 = tws + 256;   // 85 entries
  if (!INV) {
    // radix-3 DIF stage (stride 256)
    __syncthreads();
    for (int n = tc; n < 256; n += TPC) {
      float2 a = col[PD(n)], b = col[PD(n + 256)], c = col[PD(n + 512)];
      float2 u = make_float2(b.x + c.x, b.y + c.y);
      float2 v = make_float2(b.x - c.x, b.y - c.y);
      float2 t = make_float2(a.x - 0.5f * u.x, a.y - 0.5f * u.y);
      float2 y1 = make_float2(t.x + S3F * v.y, t.y - S3F * v.x);  // a + w*b + w2*c
      float2 y2 = make_float2(t.x - S3F * v.y, t.y + S3F * v.x);
      float2 w1 = tw3[n];
      float2 w2 = cmul(w1, w1);
      col[PD(n)]       = make_float2(a.x + u.x, a.y + u.y);
      col[PD(n + 256)] = cmul(y1, w1);
      col[PD(n + 512)] = cmul(y2, w2);
    }
    // 4 radix-4 DIF stages on each 256-chunk
#pragma unroll
    for (int s = 0; s < 4; ++s) {
      const int qsh = 6 - 2 * s;
      const int q   = 1 << qsh;
      const int off = (s == 0) ? 0 : (s == 1) ? 64 : (s == 2) ? 80 : 84;
      __syncthreads();
#pragma unroll 1
      for (int bf = tc; bf < 192; bf += TPC) {
        int chunk = bf >> 6, j = bf & 63;
        int m  = j & (q - 1);
        int i0 = chunk * 256 + ((j >> qsh) << (qsh + 2)) + m;
        float2 w1 = tw4[off + m];
        float2 w2 = cmul(w1, w1);
        float2 w3 = cmul(w2, w1);
        int p0 = PD(i0), p1 = PD(i0 + q), p2 = PD(i0 + 2 * q), p3 = PD(i0 + 3 * q);
        float2 a = col[p0], b = col[p1], c = col[p2], d = col[p3];
        float2 t0 = make_float2(a.x + c.x, a.y + c.y);
        float2 t1 = make_float2(a.x - c.x, a.y - c.y);
        float2 t2 = make_float2(b.x + d.x, b.y + d.y);
        float2 t3 = make_float2(b.x - d.x, b.y - d.y);
        float2 u1 = make_float2(t1.x + t3.y, t1.y - t3.x);
        float2 u3 = make_float2(t1.x - t3.y, t1.y + t3.x);
        col[p0] = make_float2(t0.x + t2.x, t0.y + t2.y);
        col[p1] = cmul(u1, w1);
        col[p2] = cmul(make_float2(t0.x - t2.x, t0.y - t2.y), w2);
        col[p3] = cmul(u3, w3);
      }
    }
  } else {
    // 4 radix-4 DIT stages on each 256-chunk (reverse order, conj twiddles)
#pragma unroll
    for (int ss = 0; ss < 4; ++ss) {
      const int s   = 3 - ss;
      const int qsh = 6 - 2 * s;
      const int q   = 1 << qsh;
      const int off = (s == 0) ? 0 : (s == 1) ? 64 : (s == 2) ? 80 : 84;
      __syncthreads();
#pragma unroll 1
      for (int bf = tc; bf < 192; bf += TPC) {
        int chunk = bf >> 6, j = bf & 63;
        int m  = j & (q - 1);
        int i0 = chunk * 256 + ((j >> qsh) << (qsh + 2)) + m;
        float2 w1 = tw4[off + m]; w1.y = -w1.y;
        float2 w2 = cmul(w1, w1);
        float2 w3 = cmul(w2, w1);
        int p0 = PD(i0), p1 = PD(i0 + q), p2 = PD(i0 + 2 * q), p3 = PD(i0 + 3 * q);
        float2 a = col[p0];
        float2 bb = cmul(col[p1], w1);
        float2 cc = cmul(col[p2], w2);
        float2 dd = cmul(col[p3], w3);
        float2 t0 = make_float2(a.x + cc.x, a.y + cc.y);
        float2 t1 = make_float2(a.x - cc.x, a.y - cc.y);
        float2 t2 = make_float2(bb.x + dd.x, bb.y + dd.y);
        float2 t3 = make_float2(bb.x - dd.x, bb.y - dd.y);
        col[p0] = make_float2(t0.x + t2.x, t0.y + t2.y);
        col[p1] = make_float2(t1.x - t3.y, t1.y + t3.x);
        col[p2] = make_float2(t0.x - t2.x, t0.y - t2.y);
        col[p3] = make_float2(t1.x + t3.y, t1.y - t3.x);
      }
    }
    // radix-3 DIT final stage (stride 256, conj twiddles)
    __syncthreads();
    for (int n = tc; n < 256; n += TPC) {
      float2 w1 = tw3[n]; w1.y = -w1.y;
      float2 w2 = cmul(w1, w1);
      float2 z0 = col[PD(n)];
      float2 z1 = cmul(col[PD(n + 256)], w1);
      float2 z2 = cmul(col[PD(n + 512)], w2);
      float2 u = make_float2(z1.x + z2.x, z1.y + z2.y);
      float2 v = make_float2(z1.x - z2.x, z1.y - z2.y);
      float2 t = make_float2(z0.x - 0.5f * u.x, z0.y - 0.5f * u.y);
      col[PD(n)]       = make_float2(z0.x + u.x, z0.y + u.y);
      col[PD(n + 256)] = make_float2(t.x - S3F * v.y, t.y + S3F * v.x);  // + i*s3*v
      col[PD(n + 512)] = make_float2(t.x + S3F * v.y, t.y - S3F * v.x);  // - i*s3*v
    }
  }
  __syncthreads();
}

#define SM8_BYTES ((TWN + 8 * CSTRP) * sizeof(float2))   // 53.4 KB
#define SM2_BYTES ((TWN + 2 * CSTRP) * sizeof(float2))   // 15.4 KB

__device__ __forceinline__ void load_tws(float2* tws, int tid) {
  for (int i = tid; i < TWN; i += 512) tws[i] = g_twm[i];
}

// ---------------- seg pass 1: two-for-one forward FFT along y ----------------
// 8 packed FFTs/block = 16 real columns. grid (36, 32).
// Output: g_mid[a][fy 0..384][C] natural fy, C contiguous (stride 576).
__global__ __launch_bounds__(512) void seg_fy(const float* __restrict__ Timg) {
  int g = blockIdx.x, a = blockIdx.y;
  int b = a >> 4, t = a & 15, ti = t >> 2, tj = t & 3;
  int h0, h1, w0, w1; tile_range(ti, &h0, &h1); tile_range(tj, &w0, &w1);
  int Hsz = h1 - h0, Wsz = w1 - w0;
  extern __shared__ float2 sm[];
  float2* tws = sm; float2* cols = sm + TWN;
  int tid = threadIdx.x;
  load_tws(tws, tid);
  const float* Tb = Timg + (size_t)b * IMG * IMG;
  for (int idx = tid; idx < 8 * NF; idx += 512) {
    int c = idx / NF, R = idx - c * NF;
    int C0 = g * 16 + 2 * c;
    float vr = 0.0f, vi = 0.0f;
    if (R < Hsz) {
      int base = IMG - 1 - (h0 + R);
      if (C0 < Wsz)     vr = Tb[(size_t)(w0 + C0) * IMG + base];
      if (C0 + 1 < Wsz) vi = Tb[(size_t)(w0 + C0 + 1) * IMG + base];
    }
    cols[c * CSTRP + PD(R)] = make_float2(vr, vi);
  }
  fft768_run<8, false>(cols, tws, tid);
  float2* outp = g_mid + (size_t)a * NH * SEGMAX;
  for (int idx = tid; idx < NH * 8; idx += 512) {
    int c = idx & 7, fy = idx >> 3;
    float2 z1 = cols[c * CSTRP + PD(posf(fy))];
    float2 z2 = cols[c * CSTRP + PD(posf((NF - fy) % NF))];
    z2.y = -z2.y;   // conj
    float2 c0 = make_float2(0.5f * (z1.x + z2.x), 0.5f * (z1.y + z2.y));
    float2 c1 = make_float2(0.5f * (z1.y - z2.y), -0.5f * (z1.x - z2.x));
    float4* o4 = (float4*)(outp + (size_t)fy * SEGMAX + g * 16 + 2 * c);
    *o4 = make_float4(c0.x, c0.y, c1.x, c1.y);
  }
}

// ---------------- seg pass 2: forward FFT along x, rows fy=0..384 ----------------
// grid (193, 32); 2 rows/block, tail-guarded
__global__ __launch_bounds__(512) void seg_fx() {
  int fy0 = blockIdx.x * 2, a = blockIdx.y;
  extern __shared__ float2 sm[];
  float2* tws = sm; float2* cols = sm + TWN;
  int tid = threadIdx.x;
  load_tws(tws, tid);
  const float2* mid = g_mid + (size_t)a * NH * SEGMAX;
  for (int idx = tid; idx < 2 * NF; idx += 512) {
    int row = (idx >= NF) ? 1 : 0;
    int C = idx - row * NF;
    int fy = fy0 + row; if (fy > NH - 1) fy = NH - 1;
    float2 v = make_float2(0.0f, 0.0f);
    if (C < SEGMAX) v = mid[(size_t)fy * SEGMAX + C];
    cols[row * CSTRP + PD(C)] = v;
  }
  fft768_run<2, false>(cols, tws, tid);
  for (int idx = tid; idx < 2 * NF; idx += 512) {
    int row = (idx >= NF) ? 1 : 0;
    int fx = idx - row * NF;
    if (fy0 + row <= NH - 1)
      g_segF[((size_t)a * NH + fy0 + row) * NF + fx] = cols[row * CSTRP + PD(fx)];
  }
}

// ---------------- psf pass 1: two-for-one forward FFT along p ----------------
// grid (8, 48). k[p][q] = psfs[l,hd,q,127-p]. Output g_mid[ap][fy][q] (stride 128).
__global__ __launch_bounds__(512) void psf_fy(const float* __restrict__ psfs) {
  int g = blockIdx.x, ap = blockIdx.y;
  int l = ap / 16, t = ap % 16, ti = t >> 2, tj = t & 3;
  int hd = tj * 4 + ti;
  extern __shared__ float2 sm[];
  float2* tws = sm; float2* cols = sm + TWN;
  int tid = threadIdx.x;
  load_tws(tws, tid);
  const float* Pb = psfs + ((size_t)l * 16 + hd) * PK * PK;
  for (int idx = tid; idx < 8 * NF; idx += 512) {
    int c = idx / NF, p = idx - c * NF;
    int q0 = g * 16 + 2 * c;
    float vr = 0.0f, vi = 0.0f;
    if (p < PK) {
      vr = Pb[(size_t)q0 * PK + (PK - 1 - p)];
      vi = Pb[(size_t)(q0 + 1) * PK + (PK - 1 - p)];
    }
    cols[c * CSTRP + PD(p)] = make_float2(vr, vi);
  }
  fft768_run<8, false>(cols, tws, tid);
  float2* outp = g_mid + (size_t)ap * NH * PK;
  for (int idx = tid; idx < NH * 8; idx += 512) {
    int c = idx & 7, fy = idx >> 3;
    float2 z1 = cols[c * CSTRP + PD(posf(fy))];
    float2 z2 = cols[c * CSTRP + PD(posf((NF - fy) % NF))];
    z2.y = -z2.y;
    float2 c0 = make_float2(0.5f * (z1.x + z2.x), 0.5f * (z1.y + z2.y));
    float2 c1 = make_float2(0.5f * (z1.y - z2.y), -0.5f * (z1.x - z2.x));
    float4* o4 = (float4*)(outp + (size_t)fy * PK + g * 16 + 2 * c);
    *o4 = make_float4(c0.x, c0.y, c1.x, c1.y);
  }
}

// ---------------- psf pass 2: forward FFT along q, rows fy=0..384 ----------------
// grid (193, 48)
__global__ __launch_bounds__(512) void psf_fx() {
  int fy0 = blockIdx.x * 2, ap = blockIdx.y;
  extern __shared__ float2 sm[];
  float2* tws = sm; float2* cols = sm + TWN;
  int tid = threadIdx.x;
  load_tws(tws, tid);
  const float2* mid = g_mid + (size_t)ap * NH * PK;
  for (int idx = tid; idx < 2 * NF; idx += 512) {
    int row = (idx >= NF) ? 1 : 0;
    int C = idx - row * NF;
    int fy = fy0 + row; if (fy > NH - 1) fy = NH - 1;
    float2 v = make_float2(0.0f, 0.0f);
    if (C < PK) v = mid[(size_t)fy * PK + C];
    cols[row * CSTRP + PD(C)] = v;
  }
  fft768_run<2, false>(cols, tws, tid);
  for (int idx = tid; idx < 2 * NF; idx += 512) {
    int row = (idx >= NF) ? 1 : 0;
    int fx = idx - row * NF;
    if (fy0 + row <= NH - 1)
      g_psfF[((size_t)ap * NH + fy0 + row) * NF + fx] = cols[row * CSTRP + PD(fx)];
  }
}

// ---------------- inverse pass A: pointwise product + IFFT along x (385 rows) --------
// grid (193, 32, 3); 2 rows/block. Stores Q[(l*32+a)][fy][x-64] for x in [64,640).
__global__ __launch_bounds__(512) void conv_x() {
  int fy0 = blockIdx.x * 2, a = blockIdx.y, l = blockIdx.z;
  int al = l * 16 + (a & 15);
  extern __shared__ float2 sm[];
  float2* tws = sm; float2* cols = sm + TWN;
  int tid = threadIdx.x;
  load_tws(tws, tid);
  const float2* Sb = g_segF + (size_t)a * NH * NF;
  const float2* Fb = g_psfF + (size_t)al * NH * NF;
  for (int idx = tid; idx < 2 * NF; idx += 512) {
    int row = (idx >= NF) ? 1 : 0;
    int fx = idx - row * NF;
    int fy = fy0 + row; if (fy > NH - 1) fy = NH - 1;
    float2 S = Sb[(size_t)fy * NF + fx];
    float2 F = Fb[(size_t)fy * NF + fx];
    cols[row * CSTRP + PD(fx)] = cmul(S, F);
  }
  fft768_run<2, true>(cols, tws, tid);
  const float sc = 1.0f / (float)NF;
  float2* Q = g_mid + (size_t)(l * 32 + a) * NH * SEGMAX;
  for (int idx = tid; idx < 2 * SEGMAX; idx += 512) {
    int row = (idx >= SEGMAX) ? 1 : 0;
    int x = idx - row * SEGMAX;
    if (fy0 + row <= NH - 1) {
      float2 v = cols[row * CSTRP + PD(64 + x)];
      Q[(size_t)(fy0 + row) * SEGMAX + x] = make_float2(v.x * sc, v.y * sc);
    }
  }
}

// ---------------- inverse pass B: C2R IFFT along y (two columns per FFT) -------------
// grid (36, 32, 3); 8 packed FFTs/block = 16 x-columns. Window + store to g_acc.
__global__ __launch_bounds__(512) void conv_y() {
  int g = blockIdx.x, a = blockIdx.y, l = blockIdx.z;
  int b = a >> 4, t = a & 15, ti = t >> 2, tj = t & 3;
  int h0, h1, w0, w1; tile_range(ti, &h0, &h1); tile_range(tj, &w0, &w1);
  int Hsz = h1 - h0, Wsz = w1 - w0;
  extern __shared__ float2 sm[];
  float2* tws = sm; float2* cols = sm + TWN;
  int tid = threadIdx.x;
  load_tws(tws, tid);
  const float2* Q = g_mid + (size_t)(l * 32 + a) * NH * SEGMAX;
  // Build full H spectrum (scrambled positions): H[fy] = Q0 + i*Q1,
  // H[768-fy] = conj(Q0) + i*conj(Q1).
  for (int idx = tid; idx < NH * 8; idx += 512) {
    int c = idx & 7, fy = idx >> 3;
    const float4 q4 = *(const float4*)(Q + (size_t)fy * SEGMAX + g * 16 + 2 * c);
    cols[c * CSTRP + PD(posf(fy))] = make_float2(q4.x - q4.w, q4.y + q4.z);
    if (fy >= 1 && fy <= NF / 2 - 1)
      cols[c * CSTRP + PD(posf(NF - fy))] = make_float2(q4.x + q4.w, q4.z - q4.y);
  }
  fft768_run<8, true>(cols, tws, tid);
  int sv = (Hsz == 576 && Wsz == 576) ? 1 : 0;
  const float sc = 1.0f / (float)NF;
  float* outbase = g_acc + (size_t)((b * 3 + l) * 16 + t) * (SEGMAX * SEGMAX);
  for (int idx = tid; idx < 8 * SEGMAX; idx += 512) {
    int c = idx & 7, r = idx >> 3;
    int x0 = g * 16 + 2 * c;
    if (r < Hsz && x0 < Wsz) {
      float2 v = cols[c * CSTRP + PD(r + 64)];
      float wy  = g_wtab[(ti * 2 + sv) * SEGMAX + r];
      float wx0 = g_wtab[(tj * 2 + sv) * SEGMAX + x0];
      float wx1 = g_wtab[(tj * 2 + sv) * SEGMAX + x0 + 1];
      float2 o = make_float2(v.x * sc * wy * wx0, v.y * sc * wy * wx1);
      *(float2*)(outbase + (size_t)r * Wsz + x0) = o;
    }
  }
}

// ---------------- overlap-add gather + normalize + inverse rotation ----------------
__global__ __launch_bounds__(256) void finalize_kernel(float* __restrict__ outp) {
  size_t idx = (size_t)blockIdx.x * 256 + threadIdx.x;
  if (idx >= (size_t)2 * 3 * IMG * IMG) return;
  int J = (int)(idx & (IMG - 1));
  size_t r2 = idx >> 11;
  int I = (int)(r2 & (IMG - 1));
  size_t r3 = r2 >> 11;
  int l = (int)(r3 % 3);
  int b = (int)(r3 / 3);
  int y = IMG - 1 - J;
  int x = I;
  float s = 0.0f, wsum = 0.0f;
#pragma unroll
  for (int i = 0; i < 4; ++i) {
    int h0, h1; tile_range(i, &h0, &h1);
    if (y < h0 || y >= h1) continue;
#pragma unroll
    for (int j = 0; j < 4; ++j) {
      int w0, w1; tile_range(j, &w0, &w1);
      if (x < w0 || x >= w1) continue;
      int Hsz = h1 - h0, Wsz = w1 - w0;
      int sv = (Hsz == 576 && Wsz == 576) ? 1 : 0;
      int r = y - h0, c = x - w0;
      float wy = g_wtab[(i * 2 + sv) * SEGMAX + r];
      float wx = g_wtab[(j * 2 + sv) * SEGMAX + c];
      int t = i * 4 + j;
      s += g_acc[(size_t)((b * 3 + l) * 16 + t) * (SEGMAX * SEGMAX) + (size_t)r * Wsz + c];
      wsum += wy * wx;
    }
  }
  float res = s / fmaxf(wsum, 1e-12f);
  if (!(res == res)) res = 0.0f;
  outp[idx] = res;
}

extern "C" void kernel_launch(void* const* d_in, const int* in_sizes, int n_in,
                              void* d_out, int out_size) {
  const float* Timg = (const float*)d_in[0];
  const float* psfs = (const float*)d_in[1];
  (void)in_sizes; (void)n_in;
  float* outp = (float*)d_out;

  cudaFuncSetAttribute(seg_fy, cudaFuncAttributeMaxDynamicSharedMemorySize, (int)SM8_BYTES);
  cudaFuncSetAttribute(psf_fy, cudaFuncAttributeMaxDynamicSharedMemorySize, (int)SM8_BYTES);
  cudaFuncSetAttribute(conv_y, cudaFuncAttributeMaxDynamicSharedMemorySize, (int)SM8_BYTES);

  init_wtab_kernel<<<18, 256>>>();
  init_twm_kernel<<<2, 256>>>();

  seg_fy<<<dim3(36, 32), 512, SM8_BYTES>>>(Timg);
  seg_fx<<<dim3(193, 32), 512, SM2_BYTES>>>();
  psf_fy<<<dim3(8, 48), 512, SM8_BYTES>>>(psfs);
  psf_fx<<<dim3(193, 48), 512, SM2_BYTES>>>();

  conv_x<<<dim3(193, 32, 3), 512, SM2_BYTES>>>();
  conv_y<<<dim3(36, 32, 3), 512, SM8_BYTES>>>();

  size_t total = (size_t)2 * 3 * IMG * IMG;
  finalize_kernel<<<(unsigned)((total + 255) / 256), 256>>>(outp);
}

// round 7
// speedup vs baseline: 68.5686x; 1.1319x over previous
#include <cuda_runtime.h>
#include <math.h>

#ifndef M_PI
#define M_PI 3.14159265358979323846
#endif

// Problem constants (fixed shapes: (2,1,2048,2048) images, (3,16,128,128) psfs, overlap=64)
#define IMG     2048
#define HS_     512
#define OV2     32
#define PK      128
#define SEGMAX  576
#define NF      768                     // FFT length = 3 * 4^4  (>= 703 support)
#define NH      385                     // Hermitian rows: fy in [0,384]

#define PD(i)   ((i) + ((i) >> 4))      // smem pad: +1 float2 per 16 (all stages conflict-free)
#define CSTRP   815                     // >= PD(767)+1 = 815
#define TWN     341                     // 256 (W_768^n) + 64 (W_256) + 16 (W_64) + 4 (W_16) + 1
#define S3F     0.86602540378443864676f // sqrt(3)/2

// ---------------- static scratch ----------------
__device__ __align__(16) float  g_acc[(size_t)2 * 3 * 16 * SEGMAX * SEGMAX];   // 127 MB
__device__ float  g_wtab[4 * 2 * SEGMAX];
__device__ float2 g_twm[TWN];
__device__ __align__(16) float2 g_segF[(size_t)32 * NH * NF];                  // 76 MB  [a][fy][fx']
__device__ __align__(16) float2 g_psfF[(size_t)48 * NH * NF];                  // 113 MB [al][fy][fx']
// multi-use: seg mid [32][385][576]; psf mid [48][385][128]; Q [96][385][576]
__device__ __align__(16) float2 g_mid[(size_t)96 * NH * SEGMAX];               // 170 MB

__device__ __forceinline__ void tile_range(int i, int* a0, int* a1) {
  int lo = i * HS_ - OV2; if (lo < 0) lo = 0;
  int hi = (i + 1) * HS_ + OV2; if (hi > IMG) hi = IMG;
  *a0 = lo; *a1 = hi;
}
__device__ __forceinline__ float2 cmul(float2 a, float2 b) {
  return make_float2(a.x * b.x - a.y * b.y, a.x * b.y + a.y * b.x);
}
__device__ __forceinline__ int drev4_4(int k) {
  return ((k & 3) << 6) | (((k >> 2) & 3) << 4) | (((k >> 4) & 3) << 2) | ((k >> 6) & 3);
}
// smem position holding natural frequency f: chunk = f%3, within-chunk base-4 digit reversal
__device__ __forceinline__ int posf(int f) {
  return (f % 3) * 256 + drev4_4(f / 3);
}

// radix-4 butterflies operating on registers (outputs in place)
__device__ __forceinline__ void dif4(float2& a, float2& b, float2& c, float2& d, float2 w1) {
  float2 t0 = make_float2(a.x + c.x, a.y + c.y);
  float2 t1 = make_float2(a.x - c.x, a.y - c.y);
  float2 t2 = make_float2(b.x + d.x, b.y + d.y);
  float2 t3 = make_float2(b.x - d.x, b.y - d.y);
  float2 w2 = cmul(w1, w1);
  float2 w3 = cmul(w2, w1);
  float2 u1 = make_float2(t1.x + t3.y, t1.y - t3.x);
  float2 u3 = make_float2(t1.x - t3.y, t1.y + t3.x);
  a = make_float2(t0.x + t2.x, t0.y + t2.y);
  b = cmul(u1, w1);
  c = cmul(make_float2(t0.x - t2.x, t0.y - t2.y), w2);
  d = cmul(u3, w3);
}
__device__ __forceinline__ void dif4_nw(float2& a, float2& b, float2& c, float2& d) {
  float2 t0 = make_float2(a.x + c.x, a.y + c.y);
  float2 t1 = make_float2(a.x - c.x, a.y - c.y);
  float2 t2 = make_float2(b.x + d.x, b.y + d.y);
  float2 t3 = make_float2(b.x - d.x, b.y - d.y);
  a = make_float2(t0.x + t2.x, t0.y + t2.y);
  b = make_float2(t1.x + t3.y, t1.y - t3.x);
  c = make_float2(t0.x - t2.x, t0.y - t2.y);
  d = make_float2(t1.x - t3.y, t1.y + t3.x);
}
// DIT butterfly; w1 is ALREADY conjugated
__device__ __forceinline__ void dit4(float2& a, float2& b, float2& c, float2& d, float2 w1) {
  float2 w2 = cmul(w1, w1);
  float2 w3 = cmul(w2, w1);
  float2 bb = cmul(b, w1), cc = cmul(c, w2), dd = cmul(d, w3);
  float2 t0 = make_float2(a.x + cc.x, a.y + cc.y);
  float2 t1 = make_float2(a.x - cc.x, a.y - cc.y);
  float2 t2 = make_float2(bb.x + dd.x, bb.y + dd.y);
  float2 t3 = make_float2(bb.x - dd.x, bb.y - dd.y);
  a = make_float2(t0.x + t2.x, t0.y + t2.y);
  b = make_float2(t1.x - t3.y, t1.y + t3.x);
  c = make_float2(t0.x - t2.x, t0.y - t2.y);
  d = make_float2(t1.x + t3.y, t1.y - t3.x);
}
__device__ __forceinline__ void dit4_nw(float2& a, float2& b, float2& c, float2& d) {
  float2 t0 = make_float2(a.x + c.x, a.y + c.y);
  float2 t1 = make_float2(a.x - c.x, a.y - c.y);
  float2 t2 = make_float2(b.x + d.x, b.y + d.y);
  float2 t3 = make_float2(b.x - d.x, b.y - d.y);
  a = make_float2(t0.x + t2.x, t0.y + t2.y);
  b = make_float2(t1.x - t3.y, t1.y + t3.x);
  c = make_float2(t0.x - t2.x, t0.y - t2.y);
  d = make_float2(t1.x + t3.y, t1.y - t3.x);
}

// ---------------- init ----------------
__global__ void init_wtab_kernel() {
  int idx = blockIdx.x * blockDim.x + threadIdx.x;
  if (idx >= 4 * 2 * SEGMAX) return;
  int p  = idx % SEGMAX;
  int sv = (idx / SEGMAX) & 1;
  int i  = idx / (2 * SEGMAX);
  int a0, a1; tile_range(i, &a0, &a1);
  int S = a1 - a0;
  float val = 0.0f;
  if (p < S) {
    float sigma = sv ? 144.0f : 136.0f;
    float v = -0.5f * (float)S + (float)p * ((float)S / (float)(S - 1));
    val = expf(-0.5f * v * v / (sigma * sigma));
  }
  g_wtab[idx] = val;
}

__global__ void init_twm_kernel() {
  int idx = blockIdx.x * blockDim.x + threadIdx.x;
  if (idx >= TWN) return;
  double ang;
  if (idx < 256) {
    ang = -2.0 * M_PI * (double)idx / (double)NF;           // W_768^n
  } else {
    int j = idx - 256;
    int m, denom;
    if      (j < 64) { m = j;      denom = 256; }
    else if (j < 80) { m = j - 64; denom = 64;  }
    else if (j < 84) { m = j - 80; denom = 16;  }
    else             { m = 0;      denom = 4;   }
    ang = -2.0 * M_PI * (double)m / (double)denom;
  }
  double sn, cs; sincos(ang, &sn, &cs);
  g_twm[idx] = make_float2((float)cs, (float)sn);
}

// ---------------- mixed-radix 768-pt FFT (3 * 4^4), register radix-16 stages ------------
// Forward (DIF): natural input -> scrambled output: pos g*256+p holds X[3*drev4_4(p)+g].
// Inverse (DIT): scrambled input in same layout -> natural output (unscaled).
// NCOLS = 8, 512 threads, TPC = 64 (warps never straddle columns).
template<bool INV>
__device__ __forceinline__ void fft768_run(float2* cols, const float2* tws, int tid) {
  const int TPC = 64;
  float2* col = cols + (tid / TPC) * CSTRP;
  int tc = tid % TPC;
  const float2* tw3 = tws;         // 256: W_768^n
  const float2* tw4 = tws + 256;   // 64 (W_256) + 16 (W_64) + 4 (W_16) + 1
  bool active = (tc < 48);
  int chunk = tc >> 4;             // 0..2 (valid when active)
  int mm = tc & 15;
  float2 x[16];
  if (!INV) {
    // ---- radix-3 DIF stage (stride 256) ----
    __syncthreads();
    for (int n = tc; n < 256; n += TPC) {
      float2 a = col[PD(n)], b = col[PD(n + 256)], c = col[PD(n + 512)];
      float2 u = make_float2(b.x + c.x, b.y + c.y);
      float2 v = make_float2(b.x - c.x, b.y - c.y);
      float2 t = make_float2(a.x - 0.5f * u.x, a.y - 0.5f * u.y);
      float2 y1 = make_float2(t.x + S3F * v.y, t.y - S3F * v.x);
      float2 y2 = make_float2(t.x - S3F * v.y, t.y + S3F * v.x);
      float2 w1 = tw3[n];
      float2 w2 = cmul(w1, w1);
      col[PD(n)]       = make_float2(a.x + u.x, a.y + u.y);
      col[PD(n + 256)] = cmul(y1, w1);
      col[PD(n + 512)] = cmul(y2, w2);
    }
    // ---- stage B: merged radix-4 q=64 + q=16 (footprint stride 16) ----
    __syncthreads();
    if (active) {
      int base = chunk * 256 + mm;
#pragma unroll
      for (int j = 0; j < 16; ++j) x[j] = col[PD(base + 16 * j)];
#pragma unroll
      for (int j0 = 0; j0 < 4; ++j0)
        dif4(x[j0], x[j0 + 4], x[j0 + 8], x[j0 + 12], tw4[mm + 16 * j0]);   // W_256^(mm+16*j0)
      float2 wB = tw4[64 + mm];                                             // W_64^mm
#pragma unroll
      for (int a = 0; a < 4; ++a)
        dif4(x[4 * a], x[4 * a + 1], x[4 * a + 2], x[4 * a + 3], wB);
#pragma unroll
      for (int j = 0; j < 16; ++j) col[PD(base + 16 * j)] = x[j];
    }
    // ---- stage C: merged radix-4 q=4 + q=1 (footprint stride 1) ----
    __syncthreads();
    if (active) {
      int base = chunk * 256 + 16 * mm;
#pragma unroll
      for (int k = 0; k < 16; ++k) x[k] = col[PD(base + k)];
#pragma unroll
      for (int k0 = 0; k0 < 4; ++k0)
        dif4(x[k0], x[k0 + 4], x[k0 + 8], x[k0 + 12], tw4[80 + k0]);        // W_16^k0
#pragma unroll
      for (int a = 0; a < 4; ++a)
        dif4_nw(x[4 * a], x[4 * a + 1], x[4 * a + 2], x[4 * a + 3]);
#pragma unroll
      for (int k = 0; k < 16; ++k) col[PD(base + k)] = x[k];
    }
  } else {
    // ---- stage C_inv: inverse of (q=1 then q=4) ----
    __syncthreads();
    if (active) {
      int base = chunk * 256 + 16 * mm;
#pragma unroll
      for (int k = 0; k < 16; ++k) x[k] = col[PD(base + k)];
#pragma unroll
      for (int a = 0; a < 4; ++a)
        dit4_nw(x[4 * a], x[4 * a + 1], x[4 * a + 2], x[4 * a + 3]);
#pragma unroll
      for (int k0 = 0; k0 < 4; ++k0) {
        float2 w = tw4[80 + k0]; w.y = -w.y;
        dit4(x[k0], x[k0 + 4], x[k0 + 8], x[k0 + 12], w);
      }
#pragma unroll
      for (int k = 0; k < 16; ++k) col[PD(base + k)] = x[k];
    }
    // ---- stage B_inv: inverse of (q=16 then q=64) ----
    __syncthreads();
    if (active) {
      int base = chunk * 256 + mm;
#pragma unroll
      for (int j = 0; j < 16; ++j) x[j] = col[PD(base + 16 * j)];
      float2 wB = tw4[64 + mm]; wB.y = -wB.y;
#pragma unroll
      for (int a = 0; a < 4; ++a)
        dit4(x[4 * a], x[4 * a + 1], x[4 * a + 2], x[4 * a + 3], wB);
#pragma unroll
      for (int j0 = 0; j0 < 4; ++j0) {
        float2 w = tw4[mm + 16 * j0]; w.y = -w.y;
        dit4(x[j0], x[j0 + 4], x[j0 + 8], x[j0 + 12], w);
      }
#pragma unroll
      for (int j = 0; j < 16; ++j) col[PD(base + 16 * j)] = x[j];
    }
    // ---- radix-3 DIT stage ----
    __syncthreads();
    for (int n = tc; n < 256; n += TPC) {
      float2 w1 = tw3[n]; w1.y = -w1.y;
      float2 w2 = cmul(w1, w1);
      float2 z0 = col[PD(n)];
      float2 z1 = cmul(col[PD(n + 256)], w1);
      float2 z2 = cmul(col[PD(n + 512)], w2);
      float2 u = make_float2(z1.x + z2.x, z1.y + z2.y);
      float2 v = make_float2(z1.x - z2.x, z1.y - z2.y);
      float2 t = make_float2(z0.x - 0.5f * u.x, z0.y - 0.5f * u.y);
      col[PD(n)]       = make_float2(z0.x + u.x, z0.y + u.y);
      col[PD(n + 256)] = make_float2(t.x - S3F * v.y, t.y + S3F * v.x);
      col[PD(n + 512)] = make_float2(t.x + S3F * v.y, t.y - S3F * v.x);
    }
  }
  __syncthreads();
}

#define SM8_BYTES ((TWN + 8 * CSTRP) * sizeof(float2))   // ~53.6 KB

__device__ __forceinline__ void load_tws(float2* tws, int tid) {
  for (int i = tid; i < TWN; i += 512) tws[i] = g_twm[i];
}

// ---------------- seg pass 1: two-for-one forward FFT along y ----------------
// 8 packed FFTs/block = 16 real columns. grid (36, 32).
__global__ __launch_bounds__(512) void seg_fy(const float* __restrict__ Timg) {
  int g = blockIdx.x, a = blockIdx.y;
  int b = a >> 4, t = a & 15, ti = t >> 2, tj = t & 3;
  int h0, h1, w0, w1; tile_range(ti, &h0, &h1); tile_range(tj, &w0, &w1);
  int Hsz = h1 - h0, Wsz = w1 - w0;
  extern __shared__ float2 sm[];
  float2* tws = sm; float2* cols = sm + TWN;
  int tid = threadIdx.x;
  load_tws(tws, tid);
  const float* Tb = Timg + (size_t)b * IMG * IMG;
  for (int idx = tid; idx < 8 * NF; idx += 512) {
    int c = idx / NF, R = idx - c * NF;
    int C0 = g * 16 + 2 * c;
    float vr = 0.0f, vi = 0.0f;
    if (R < Hsz) {
      int base = IMG - 1 - (h0 + R);
      if (C0 < Wsz)     vr = Tb[(size_t)(w0 + C0) * IMG + base];
      if (C0 + 1 < Wsz) vi = Tb[(size_t)(w0 + C0 + 1) * IMG + base];
    }
    cols[c * CSTRP + PD(R)] = make_float2(vr, vi);
  }
  fft768_run<false>(cols, tws, tid);
  float2* outp = g_mid + (size_t)a * NH * SEGMAX;
  for (int idx = tid; idx < NH * 8; idx += 512) {
    int c = idx & 7, fy = idx >> 3;
    float2 z1 = cols[c * CSTRP + PD(posf(fy))];
    float2 z2 = cols[c * CSTRP + PD(posf((NF - fy) % NF))];
    z2.y = -z2.y;
    float2 c0 = make_float2(0.5f * (z1.x + z2.x), 0.5f * (z1.y + z2.y));
    float2 c1 = make_float2(0.5f * (z1.y - z2.y), -0.5f * (z1.x - z2.x));
    float4* o4 = (float4*)(outp + (size_t)fy * SEGMAX + g * 16 + 2 * c);
    *o4 = make_float4(c0.x, c0.y, c1.x, c1.y);
  }
}

// ---------------- seg pass 2: forward FFT along x, 8 rows/block ----------------
// grid (49, 32)
__global__ __launch_bounds__(512) void seg_fx() {
  int fy0 = blockIdx.x * 8, a = blockIdx.y;
  extern __shared__ float2 sm[];
  float2* tws = sm; float2* cols = sm + TWN;
  int tid = threadIdx.x;
  load_tws(tws, tid);
  const float2* mid = g_mid + (size_t)a * NH * SEGMAX;
  for (int idx = tid; idx < 8 * NF; idx += 512) {
    int row = idx / NF, C = idx - row * NF;
    int fy = fy0 + row; if (fy > NH - 1) fy = NH - 1;
    float2 v = make_float2(0.0f, 0.0f);
    if (C < SEGMAX) v = mid[(size_t)fy * SEGMAX + C];
    cols[row * CSTRP + PD(C)] = v;
  }
  fft768_run<false>(cols, tws, tid);
  for (int idx = tid; idx < 8 * NF; idx += 512) {
    int row = idx / NF, fx = idx - row * NF;
    if (fy0 + row <= NH - 1)
      g_segF[((size_t)a * NH + fy0 + row) * NF + fx] = cols[row * CSTRP + PD(fx)];
  }
}

// ---------------- psf pass 1: two-for-one forward FFT along p ----------------
// grid (8, 48). k[p][q] = psfs[l,hd,q,127-p]. Output g_mid[ap][fy][q] (stride 128).
__global__ __launch_bounds__(512) void psf_fy(const float* __restrict__ psfs) {
  int g = blockIdx.x, ap = blockIdx.y;
  int l = ap / 16, t = ap % 16, ti = t >> 2, tj = t & 3;
  int hd = tj * 4 + ti;
  extern __shared__ float2 sm[];
  float2* tws = sm; float2* cols = sm + TWN;
  int tid = threadIdx.x;
  load_tws(tws, tid);
  const float* Pb = psfs + ((size_t)l * 16 + hd) * PK * PK;
  for (int idx = tid; idx < 8 * NF; idx += 512) {
    int c = idx / NF, p = idx - c * NF;
    int q0 = g * 16 + 2 * c;
    float vr = 0.0f, vi = 0.0f;
    if (p < PK) {
      vr = Pb[(size_t)q0 * PK + (PK - 1 - p)];
      vi = Pb[(size_t)(q0 + 1) * PK + (PK - 1 - p)];
    }
    cols[c * CSTRP + PD(p)] = make_float2(vr, vi);
  }
  fft768_run<false>(cols, tws, tid);
  float2* outp = g_mid + (size_t)ap * NH * PK;
  for (int idx = tid; idx < NH * 8; idx += 512) {
    int c = idx & 7, fy = idx >> 3;
    float2 z1 = cols[c * CSTRP + PD(posf(fy))];
    float2 z2 = cols[c * CSTRP + PD(posf((NF - fy) % NF))];
    z2.y = -z2.y;
    float2 c0 = make_float2(0.5f * (z1.x + z2.x), 0.5f * (z1.y + z2.y));
    float2 c1 = make_float2(0.5f * (z1.y - z2.y), -0.5f * (z1.x - z2.x));
    float4* o4 = (float4*)(outp + (size_t)fy * PK + g * 16 + 2 * c);
    *o4 = make_float4(c0.x, c0.y, c1.x, c1.y);
  }
}

// ---------------- psf pass 2: forward FFT along q, 8 rows/block ----------------
// grid (49, 48)
__global__ __launch_bounds__(512) void psf_fx() {
  int fy0 = blockIdx.x * 8, ap = blockIdx.y;
  extern __shared__ float2 sm[];
  float2* tws = sm; float2* cols = sm + TWN;
  int tid = threadIdx.x;
  load_tws(tws, tid);
  const float2* mid = g_mid + (size_t)ap * NH * PK;
  for (int idx = tid; idx < 8 * NF; idx += 512) {
    int row = idx / NF, C = idx - row * NF;
    int fy = fy0 + row; if (fy > NH - 1) fy = NH - 1;
    float2 v = make_float2(0.0f, 0.0f);
    if (C < PK) v = mid[(size_t)fy * PK + C];
    cols[row * CSTRP + PD(C)] = v;
  }
  fft768_run<false>(cols, tws, tid);
  for (int idx = tid; idx < 8 * NF; idx += 512) {
    int row = idx / NF, fx = idx - row * NF;
    if (fy0 + row <= NH - 1)
      g_psfF[((size_t)ap * NH + fy0 + row) * NF + fx] = cols[row * CSTRP + PD(fx)];
  }
}

// ---------------- inverse pass A: pointwise product + IFFT along x, 8 rows/block ------
// grid (49, 32, 3). Stores Q[(l*32+a)][fy][x-64] for x in [64,640).
__global__ __launch_bounds__(512) void conv_x() {
  int fy0 = blockIdx.x * 8, a = blockIdx.y, l = blockIdx.z;
  int al = l * 16 + (a & 15);
  extern __shared__ float2 sm[];
  float2* tws = sm; float2* cols = sm + TWN;
  int tid = threadIdx.x;
  load_tws(tws, tid);
  const float2* Sb = g_segF + (size_t)a * NH * NF;
  const float2* Fb = g_psfF + (size_t)al * NH * NF;
  for (int idx = tid; idx < 8 * NF; idx += 512) {
    int row = idx / NF, fx = idx - row * NF;
    int fy = fy0 + row; if (fy > NH - 1) fy = NH - 1;
    float2 S = Sb[(size_t)fy * NF + fx];
    float2 F = Fb[(size_t)fy * NF + fx];
    cols[row * CSTRP + PD(fx)] = cmul(S, F);
  }
  fft768_run<true>(cols, tws, tid);
  const float sc = 1.0f / (float)NF;
  float2* Q = g_mid + (size_t)(l * 32 + a) * NH * SEGMAX;
  for (int idx = tid; idx < 8 * SEGMAX; idx += 512) {
    int row = idx / SEGMAX, x = idx - row * SEGMAX;
    if (fy0 + row <= NH - 1) {
      float2 v = cols[row * CSTRP + PD(64 + x)];
      Q[(size_t)(fy0 + row) * SEGMAX + x] = make_float2(v.x * sc, v.y * sc);
    }
  }
}

// ---------------- inverse pass B: C2R IFFT along y (two columns per FFT) -------------
// grid (36, 32, 3); 8 packed FFTs/block = 16 x-columns. Window + store to g_acc.
__global__ __launch_bounds__(512) void conv_y() {
  int g = blockIdx.x, a = blockIdx.y, l = blockIdx.z;
  int b = a >> 4, t = a & 15, ti = t >> 2, tj = t & 3;
  int h0, h1, w0, w1; tile_range(ti, &h0, &h1); tile_range(tj, &w0, &w1);
  int Hsz = h1 - h0, Wsz = w1 - w0;
  extern __shared__ float2 sm[];
  float2* tws = sm; float2* cols = sm + TWN;
  int tid = threadIdx.x;
  load_tws(tws, tid);
  const float2* Q = g_mid + (size_t)(l * 32 + a) * NH * SEGMAX;
  for (int idx = tid; idx < NH * 8; idx += 512) {
    int c = idx & 7, fy = idx >> 3;
    const float4 q4 = *(const float4*)(Q + (size_t)fy * SEGMAX + g * 16 + 2 * c);
    cols[c * CSTRP + PD(posf(fy))] = make_float2(q4.x - q4.w, q4.y + q4.z);
    if (fy >= 1 && fy <= NF / 2 - 1)
      cols[c * CSTRP + PD(posf(NF - fy))] = make_float2(q4.x + q4.w, q4.z - q4.y);
  }
  fft768_run<true>(cols, tws, tid);
  int sv = (Hsz == 576 && Wsz == 576) ? 1 : 0;
  const float sc = 1.0f / (float)NF;
  float* outbase = g_acc + (size_t)((b * 3 + l) * 16 + t) * (SEGMAX * SEGMAX);
  for (int idx = tid; idx < 8 * SEGMAX; idx += 512) {
    int c = idx & 7, r = idx >> 3;
    int x0 = g * 16 + 2 * c;
    if (r < Hsz && x0 < Wsz) {
      float2 v = cols[c * CSTRP + PD(r + 64)];
      float wy  = g_wtab[(ti * 2 + sv) * SEGMAX + r];
      float wx0 = g_wtab[(tj * 2 + sv) * SEGMAX + x0];
      float wx1 = g_wtab[(tj * 2 + sv) * SEGMAX + x0 + 1];
      float2 o = make_float2(v.x * sc * wy * wx0, v.y * sc * wy * wx1);
      *(float2*)(outbase + (size_t)r * Wsz + x0) = o;
    }
  }
}

// ---------------- overlap-add gather + normalize + rotation via smem transpose -------
// grid (64, 64, 6), block (32, 8). Out tile: J in [J0,J0+32), I in [I0,I0+32).
__global__ __launch_bounds__(256) void finalize_t(float* __restrict__ outp) {
  int J0 = blockIdx.x * 32, I0 = blockIdx.y * 32;
  int z = blockIdx.z;            // z = b*3 + l
  __shared__ float ssum[32][33];
  __shared__ float swin[32][33];
  int lx = threadIdx.x, ly = threadIdx.y;
  for (int yy = ly; yy < 32; yy += 8) { ssum[yy][lx] = 0.0f; swin[yy][lx] = 0.0f; }
  __syncthreads();
  int ylo = IMG - 1 - (J0 + 31);   // y = ylo + yy, yy in [0,32)
#pragma unroll
  for (int i = 0; i < 4; ++i) {
    int h0, h1; tile_range(i, &h0, &h1);
    if (ylo + 31 < h0 || ylo >= h1) continue;
#pragma unroll
    for (int j = 0; j < 4; ++j) {
      int w0, w1; tile_range(j, &w0, &w1);
      if (I0 + 31 < w0 || I0 >= w1) continue;
      int Hsz = h1 - h0, Wsz = w1 - w0;
      int sv = (Hsz == 576 && Wsz == 576) ? 1 : 0;
      const float* base = g_acc + (size_t)(z * 16 + i * 4 + j) * (SEGMAX * SEGMAX);
      int x = I0 + lx;
      bool xok = (x >= w0 && x < w1);
      float wx = xok ? g_wtab[(j * 2 + sv) * SEGMAX + (x - w0)] : 0.0f;
      for (int yy = ly; yy < 32; yy += 8) {
        int y = ylo + yy;
        if (xok && y >= h0 && y < h1) {
          int r = y - h0;
          ssum[yy][lx] += base[(size_t)r * Wsz + (x - w0)];
          swin[yy][lx] += g_wtab[(i * 2 + sv) * SEGMAX + r] * wx;
        }
      }
    }
  }
  __syncthreads();
  for (int ii = ly; ii < 32; ii += 8) {
    int I = I0 + ii;
    int J = J0 + lx;
    int yy = 31 - lx;              // (IMG-1-J) - ylo
    float s = ssum[yy][ii];
    float w = swin[yy][ii];
    float res = s / fmaxf(w, 1e-12f);
    if (!(res == res)) res = 0.0f;
    outp[((size_t)z * IMG + I) * IMG + J] = res;
  }
}

extern "C" void kernel_launch(void* const* d_in, const int* in_sizes, int n_in,
                              void* d_out, int out_size) {
  const float* Timg = (const float*)d_in[0];
  const float* psfs = (const float*)d_in[1];
  (void)in_sizes; (void)n_in;
  float* outp = (float*)d_out;

  cudaFuncSetAttribute(seg_fy, cudaFuncAttributeMaxDynamicSharedMemorySize, (int)SM8_BYTES);
  cudaFuncSetAttribute(seg_fx, cudaFuncAttributeMaxDynamicSharedMemorySize, (int)SM8_BYTES);
  cudaFuncSetAttribute(psf_fy, cudaFuncAttributeMaxDynamicSharedMemorySize, (int)SM8_BYTES);
  cudaFuncSetAttribute(psf_fx, cudaFuncAttributeMaxDynamicSharedMemorySize, (int)SM8_BYTES);
  cudaFuncSetAttribute(conv_x, cudaFuncAttributeMaxDynamicSharedMemorySize, (int)SM8_BYTES);
  cudaFuncSetAttribute(conv_y, cudaFuncAttributeMaxDynamicSharedMemorySize, (int)SM8_BYTES);

  init_wtab_kernel<<<18, 256>>>();
  init_twm_kernel<<<2, 256>>>();

  seg_fy<<<dim3(36, 32), 512, SM8_BYTES>>>(Timg);
  seg_fx<<<dim3(49, 32), 512, SM8_BYTES>>>();
  psf_fy<<<dim3(8, 48), 512, SM8_BYTES>>>(psfs);
  psf_fx<<<dim3(49, 48), 512, SM8_BYTES>>>();

  conv_x<<<dim3(49, 32, 3), 512, SM8_BYTES>>>();
  conv_y<<<dim3(36, 32, 3), 512, SM8_BYTES>>>();

  finalize_t<<<dim3(64, 64, 6), dim3(32, 8)>>>(outp);
}

// round 8
// speedup vs baseline: 77.8874x; 1.1359x over previous
#include <cuda_runtime.h>
#include <math.h>

#ifndef M_PI
#define M_PI 3.14159265358979323846
#endif

// Problem constants (fixed shapes: (2,1,2048,2048) images, (3,16,128,128) psfs, overlap=64)
#define IMG     2048
#define HS_     512
#define OV2     32
#define PK      128
#define SEGMAX  576
#define NF      768                     // FFT length = 3 * 4^4  (>= 703 support)
#define NH      385                     // Hermitian rows: fy in [0,384]

#define PD(i)   ((i) + ((i) >> 4))      // smem pad: +1 float2 per 16 (all stages conflict-free)
#define CSTRP   815                     // >= PD(767)+1 = 815
#define TWN     341                     // 256 (W_768^n) + 64 (W_256) + 16 (W_64) + 4 (W_16) + 1
#define S3F     0.86602540378443864676f // sqrt(3)/2
#define NTH     256                     // threads per FFT block (4 columns x TPC=64)

// ---------------- static scratch ----------------
__device__ __align__(16) float  g_acc[(size_t)2 * 3 * 16 * SEGMAX * SEGMAX];   // 127 MB
__device__ float  g_wtab[4 * 2 * SEGMAX];
__device__ float2 g_twm[TWN];
__device__ __align__(16) float2 g_segF[(size_t)32 * NH * NF];                  // 76 MB  [a][fy][fx']
__device__ __align__(16) float2 g_psfF[(size_t)48 * NH * NF];                  // 113 MB [al][fy][fx']
// multi-use: seg mid [32][385][576]; psf mid [48][385][128]; Q [96][385][576]
__device__ __align__(16) float2 g_mid[(size_t)96 * NH * SEGMAX];               // 170 MB

__device__ __forceinline__ void tile_range(int i, int* a0, int* a1) {
  int lo = i * HS_ - OV2; if (lo < 0) lo = 0;
  int hi = (i + 1) * HS_ + OV2; if (hi > IMG) hi = IMG;
  *a0 = lo; *a1 = hi;
}
__device__ __forceinline__ float2 cmul(float2 a, float2 b) {
  return make_float2(a.x * b.x - a.y * b.y, a.x * b.y + a.y * b.x);
}
__device__ __forceinline__ int drev4_4(int k) {
  return ((k & 3) << 6) | (((k >> 2) & 3) << 4) | (((k >> 4) & 3) << 2) | ((k >> 6) & 3);
}
// smem position holding natural frequency f: chunk = f%3, within-chunk base-4 digit reversal
__device__ __forceinline__ int posf(int f) {
  return (f % 3) * 256 + drev4_4(f / 3);
}

// radix-4 butterflies operating on registers (outputs in place)
__device__ __forceinline__ void dif4(float2& a, float2& b, float2& c, float2& d, float2 w1) {
  float2 t0 = make_float2(a.x + c.x, a.y + c.y);
  float2 t1 = make_float2(a.x - c.x, a.y - c.y);
  float2 t2 = make_float2(b.x + d.x, b.y + d.y);
  float2 t3 = make_float2(b.x - d.x, b.y - d.y);
  float2 w2 = cmul(w1, w1);
  float2 w3 = cmul(w2, w1);
  float2 u1 = make_float2(t1.x + t3.y, t1.y - t3.x);
  float2 u3 = make_float2(t1.x - t3.y, t1.y + t3.x);
  a = make_float2(t0.x + t2.x, t0.y + t2.y);
  b = cmul(u1, w1);
  c = cmul(make_float2(t0.x - t2.x, t0.y - t2.y), w2);
  d = cmul(u3, w3);
}
__device__ __forceinline__ void dif4_nw(float2& a, float2& b, float2& c, float2& d) {
  float2 t0 = make_float2(a.x + c.x, a.y + c.y);
  float2 t1 = make_float2(a.x - c.x, a.y - c.y);
  float2 t2 = make_float2(b.x + d.x, b.y + d.y);
  float2 t3 = make_float2(b.x - d.x, b.y - d.y);
  a = make_float2(t0.x + t2.x, t0.y + t2.y);
  b = make_float2(t1.x + t3.y, t1.y - t3.x);
  c = make_float2(t0.x - t2.x, t0.y - t2.y);
  d = make_float2(t1.x - t3.y, t1.y + t3.x);
}
// DIT butterfly; w1 is ALREADY conjugated
__device__ __forceinline__ void dit4(float2& a, float2& b, float2& c, float2& d, float2 w1) {
  float2 w2 = cmul(w1, w1);
  float2 w3 = cmul(w2, w1);
  float2 bb = cmul(b, w1), cc = cmul(c, w2), dd = cmul(d, w3);
  float2 t0 = make_float2(a.x + cc.x, a.y + cc.y);
  float2 t1 = make_float2(a.x - cc.x, a.y - cc.y);
  float2 t2 = make_float2(bb.x + dd.x, bb.y + dd.y);
  float2 t3 = make_float2(bb.x - dd.x, bb.y - dd.y);
  a = make_float2(t0.x + t2.x, t0.y + t2.y);
  b = make_float2(t1.x - t3.y, t1.y + t3.x);
  c = make_float2(t0.x - t2.x, t0.y - t2.y);
  d = make_float2(t1.x + t3.y, t1.y - t3.x);
}
__device__ __forceinline__ void dit4_nw(float2& a, float2& b, float2& c, float2& d) {
  float2 t0 = make_float2(a.x + c.x, a.y + c.y);
  float2 t1 = make_float2(a.x - c.x, a.y - c.y);
  float2 t2 = make_float2(b.x + d.x, b.y + d.y);
  float2 t3 = make_float2(b.x - d.x, b.y - d.y);
  a = make_float2(t0.x + t2.x, t0.y + t2.y);
  b = make_float2(t1.x - t3.y, t1.y + t3.x);
  c = make_float2(t0.x - t2.x, t0.y - t2.y);
  d = make_float2(t1.x + t3.y, t1.y - t3.x);
}

// ---------------- init ----------------
__global__ void init_wtab_kernel() {
  int idx = blockIdx.x * blockDim.x + threadIdx.x;
  if (idx >= 4 * 2 * SEGMAX) return;
  int p  = idx % SEGMAX;
  int sv = (idx / SEGMAX) & 1;
  int i  = idx / (2 * SEGMAX);
  int a0, a1; tile_range(i, &a0, &a1);
  int S = a1 - a0;
  float val = 0.0f;
  if (p < S) {
    float sigma = sv ? 144.0f : 136.0f;
    float v = -0.5f * (float)S + (float)p * ((float)S / (float)(S - 1));
    val = expf(-0.5f * v * v / (sigma * sigma));
  }
  g_wtab[idx] = val;
}

__global__ void init_twm_kernel() {
  int idx = blockIdx.x * blockDim.x + threadIdx.x;
  if (idx >= TWN) return;
  double ang;
  if (idx < 256) {
    ang = -2.0 * M_PI * (double)idx / (double)NF;           // W_768^n
  } else {
    int j = idx - 256;
    int m, denom;
    if      (j < 64) { m = j;      denom = 256; }
    else if (j < 80) { m = j - 64; denom = 64;  }
    else if (j < 84) { m = j - 80; denom = 16;  }
    else             { m = 0;      denom = 4;   }
    ang = -2.0 * M_PI * (double)m / (double)denom;
  }
  double sn, cs; sincos(ang, &sn, &cs);
  g_twm[idx] = make_float2((float)cs, (float)sn);
}

// ---------------- mixed-radix 768-pt FFT (3 * 4^4), register radix-16 stages ------------
// Forward (DIF): natural input -> scrambled output: pos g*256+p holds X[3*drev4_4(p)+g].
// Inverse (DIT): scrambled input in same layout -> natural output (unscaled).
// 4 columns per block, NTH=256 threads, TPC=64 (warps never straddle columns).
template<bool INV>
__device__ __forceinline__ void fft768_run(float2* cols, const float2* tws, int tid) {
  const int TPC = 64;
  float2* col = cols + (tid / TPC) * CSTRP;
  int tc = tid % TPC;
  const float2* tw3 = tws;         // 256: W_768^n
  const float2* tw4 = tws + 256;   // 64 (W_256) + 16 (W_64) + 4 (W_16) + 1
  bool active = (tc < 48);
  int chunk = tc >> 4;             // 0..2 (valid when active)
  int mm = tc & 15;
  float2 x[16];
  if (!INV) {
    // ---- radix-3 DIF stage (stride 256) ----
    __syncthreads();
    for (int n = tc; n < 256; n += TPC) {
      float2 a = col[PD(n)], b = col[PD(n + 256)], c = col[PD(n + 512)];
      float2 u = make_float2(b.x + c.x, b.y + c.y);
      float2 v = make_float2(b.x - c.x, b.y - c.y);
      float2 t = make_float2(a.x - 0.5f * u.x, a.y - 0.5f * u.y);
      float2 y1 = make_float2(t.x + S3F * v.y, t.y - S3F * v.x);
      float2 y2 = make_float2(t.x - S3F * v.y, t.y + S3F * v.x);
      float2 w1 = tw3[n];
      float2 w2 = cmul(w1, w1);
      col[PD(n)]       = make_float2(a.x + u.x, a.y + u.y);
      col[PD(n + 256)] = cmul(y1, w1);
      col[PD(n + 512)] = cmul(y2, w2);
    }
    // ---- stage B: merged radix-4 q=64 + q=16 (footprint stride 16) ----
    __syncthreads();
    if (active) {
      int base = chunk * 256 + mm;
#pragma unroll
      for (int j = 0; j < 16; ++j) x[j] = col[PD(base + 16 * j)];
#pragma unroll
      for (int j0 = 0; j0 < 4; ++j0)
        dif4(x[j0], x[j0 + 4], x[j0 + 8], x[j0 + 12], tw4[mm + 16 * j0]);   // W_256^(mm+16*j0)
      float2 wB = tw4[64 + mm];                                             // W_64^mm
#pragma unroll
      for (int a = 0; a < 4; ++a)
        dif4(x[4 * a], x[4 * a + 1], x[4 * a + 2], x[4 * a + 3], wB);
#pragma unroll
      for (int j = 0; j < 16; ++j) col[PD(base + 16 * j)] = x[j];
    }
    // ---- stage C: merged radix-4 q=4 + q=1 (footprint stride 1) ----
    __syncthreads();
    if (active) {
      int base = chunk * 256 + 16 * mm;
#pragma unroll
      for (int k = 0; k < 16; ++k) x[k] = col[PD(base + k)];
#pragma unroll
      for (int k0 = 0; k0 < 4; ++k0)
        dif4(x[k0], x[k0 + 4], x[k0 + 8], x[k0 + 12], tw4[80 + k0]);        // W_16^k0
#pragma unroll
      for (int a = 0; a < 4; ++a)
        dif4_nw(x[4 * a], x[4 * a + 1], x[4 * a + 2], x[4 * a + 3]);
#pragma unroll
      for (int k = 0; k < 16; ++k) col[PD(base + k)] = x[k];
    }
  } else {
    // ---- stage C_inv: inverse of (q=1 then q=4) ----
    __syncthreads();
    if (active) {
      int base = chunk * 256 + 16 * mm;
#pragma unroll
      for (int k = 0; k < 16; ++k) x[k] = col[PD(base + k)];
#pragma unroll
      for (int a = 0; a < 4; ++a)
        dit4_nw(x[4 * a], x[4 * a + 1], x[4 * a + 2], x[4 * a + 3]);
#pragma unroll
      for (int k0 = 0; k0 < 4; ++k0) {
        float2 w = tw4[80 + k0]; w.y = -w.y;
        dit4(x[k0], x[k0 + 4], x[k0 + 8], x[k0 + 12], w);
      }
#pragma unroll
      for (int k = 0; k < 16; ++k) col[PD(base + k)] = x[k];
    }
    // ---- stage B_inv: inverse of (q=16 then q=64) ----
    __syncthreads();
    if (active) {
      int base = chunk * 256 + mm;
#pragma unroll
      for (int j = 0; j < 16; ++j) x[j] = col[PD(base + 16 * j)];
      float2 wB = tw4[64 + mm]; wB.y = -wB.y;
#pragma unroll
      for (int a = 0; a < 4; ++a)
        dit4(x[4 * a], x[4 * a + 1], x[4 * a + 2], x[4 * a + 3], wB);
#pragma unroll
      for (int j0 = 0; j0 < 4; ++j0) {
        float2 w = tw4[mm + 16 * j0]; w.y = -w.y;
        dit4(x[j0], x[j0 + 4], x[j0 + 8], x[j0 + 12], w);
      }
#pragma unroll
      for (int j = 0; j < 16; ++j) col[PD(base + 16 * j)] = x[j];
    }
    // ---- radix-3 DIT stage ----
    __syncthreads();
    for (int n = tc; n < 256; n += TPC) {
      float2 w1 = tw3[n]; w1.y = -w1.y;
      float2 w2 = cmul(w1, w1);
      float2 z0 = col[PD(n)];
      float2 z1 = cmul(col[PD(n + 256)], w1);
      float2 z2 = cmul(col[PD(n + 512)], w2);
      float2 u = make_float2(z1.x + z2.x, z1.y + z2.y);
      float2 v = make_float2(z1.x - z2.x, z1.y - z2.y);
      float2 t = make_float2(z0.x - 0.5f * u.x, z0.y - 0.5f * u.y);
      col[PD(n)]       = make_float2(z0.x + u.x, z0.y + u.y);
      col[PD(n + 256)] = make_float2(t.x - S3F * v.y, t.y + S3F * v.x);
      col[PD(n + 512)] = make_float2(t.x + S3F * v.y, t.y - S3F * v.x);
    }
  }
  __syncthreads();
}

#define SM4_BYTES ((TWN + 4 * CSTRP) * sizeof(float2))   // ~28.9 KB

__device__ __forceinline__ void load_tws(float2* tws, int tid) {
  for (int i = tid; i < TWN; i += NTH) tws[i] = g_twm[i];
}

// ---------------- seg pass 1: two-for-one forward FFT along y ----------------
// 4 packed FFTs/block = 8 real columns. grid (72, 32).
__global__ __launch_bounds__(NTH, 5) void seg_fy(const float* __restrict__ Timg) {
  int g = blockIdx.x, a = blockIdx.y;
  int b = a >> 4, t = a & 15, ti = t >> 2, tj = t & 3;
  int h0, h1, w0, w1; tile_range(ti, &h0, &h1); tile_range(tj, &w0, &w1);
  int Hsz = h1 - h0, Wsz = w1 - w0;
  extern __shared__ float2 sm[];
  float2* tws = sm; float2* cols = sm + TWN;
  int tid = threadIdx.x;
  load_tws(tws, tid);
  const float* Tb = Timg + (size_t)b * IMG * IMG;
  for (int idx = tid; idx < 4 * NF; idx += NTH) {
    int c = idx / NF, R = idx - c * NF;
    int C0 = g * 8 + 2 * c;
    float vr = 0.0f, vi = 0.0f;
    if (R < Hsz) {
      int base = IMG - 1 - (h0 + R);
      if (C0 < Wsz)     vr = Tb[(size_t)(w0 + C0) * IMG + base];
      if (C0 + 1 < Wsz) vi = Tb[(size_t)(w0 + C0 + 1) * IMG + base];
    }
    cols[c * CSTRP + PD(R)] = make_float2(vr, vi);
  }
  fft768_run<false>(cols, tws, tid);
  float2* outp = g_mid + (size_t)a * NH * SEGMAX;
  for (int idx = tid; idx < NH * 4; idx += NTH) {
    int c = idx & 3, fy = idx >> 2;
    float2 z1 = cols[c * CSTRP + PD(posf(fy))];
    float2 z2 = cols[c * CSTRP + PD(posf((NF - fy) % NF))];
    z2.y = -z2.y;
    float2 c0 = make_float2(0.5f * (z1.x + z2.x), 0.5f * (z1.y + z2.y));
    float2 c1 = make_float2(0.5f * (z1.y - z2.y), -0.5f * (z1.x - z2.x));
    float4* o4 = (float4*)(outp + (size_t)fy * SEGMAX + g * 8 + 2 * c);
    *o4 = make_float4(c0.x, c0.y, c1.x, c1.y);
  }
}

// ---------------- seg pass 2: forward FFT along x, 4 rows/block ----------------
// grid (97, 32)
__global__ __launch_bounds__(NTH, 5) void seg_fx() {
  int fy0 = blockIdx.x * 4, a = blockIdx.y;
  extern __shared__ float2 sm[];
  float2* tws = sm; float2* cols = sm + TWN;
  int tid = threadIdx.x;
  load_tws(tws, tid);
  const float2* mid = g_mid + (size_t)a * NH * SEGMAX;
  for (int idx = tid; idx < 4 * NF; idx += NTH) {
    int row = idx / NF, C = idx - row * NF;
    int fy = fy0 + row; if (fy > NH - 1) fy = NH - 1;
    float2 v = make_float2(0.0f, 0.0f);
    if (C < SEGMAX) v = mid[(size_t)fy * SEGMAX + C];
    cols[row * CSTRP + PD(C)] = v;
  }
  fft768_run<false>(cols, tws, tid);
  for (int idx = tid; idx < 4 * NF; idx += NTH) {
    int row = idx / NF, fx = idx - row * NF;
    if (fy0 + row <= NH - 1)
      g_segF[((size_t)a * NH + fy0 + row) * NF + fx] = cols[row * CSTRP + PD(fx)];
  }
}

// ---------------- psf pass 1: two-for-one forward FFT along p ----------------
// grid (16, 48). k[p][q] = psfs[l,hd,q,127-p]. Output g_mid[ap][fy][q] (stride 128).
__global__ __launch_bounds__(NTH, 5) void psf_fy(const float* __restrict__ psfs) {
  int g = blockIdx.x, ap = blockIdx.y;
  int l = ap / 16, t = ap % 16, ti = t >> 2, tj = t & 3;
  int hd = tj * 4 + ti;
  extern __shared__ float2 sm[];
  float2* tws = sm; float2* cols = sm + TWN;
  int tid = threadIdx.x;
  load_tws(tws, tid);
  const float* Pb = psfs + ((size_t)l * 16 + hd) * PK * PK;
  for (int idx = tid; idx < 4 * NF; idx += NTH) {
    int c = idx / NF, p = idx - c * NF;
    int q0 = g * 8 + 2 * c;
    float vr = 0.0f, vi = 0.0f;
    if (p < PK) {
      vr = Pb[(size_t)q0 * PK + (PK - 1 - p)];
      vi = Pb[(size_t)(q0 + 1) * PK + (PK - 1 - p)];
    }
    cols[c * CSTRP + PD(p)] = make_float2(vr, vi);
  }
  fft768_run<false>(cols, tws, tid);
  float2* outp = g_mid + (size_t)ap * NH * PK;
  for (int idx = tid; idx < NH * 4; idx += NTH) {
    int c = idx & 3, fy = idx >> 2;
    float2 z1 = cols[c * CSTRP + PD(posf(fy))];
    float2 z2 = cols[c * CSTRP + PD(posf((NF - fy) % NF))];
    z2.y = -z2.y;
    float2 c0 = make_float2(0.5f * (z1.x + z2.x), 0.5f * (z1.y + z2.y));
    float2 c1 = make_float2(0.5f * (z1.y - z2.y), -0.5f * (z1.x - z2.x));
    float4* o4 = (float4*)(outp + (size_t)fy * PK + g * 8 + 2 * c);
    *o4 = make_float4(c0.x, c0.y, c1.x, c1.y);
  }
}

// ---------------- psf pass 2: forward FFT along q, 4 rows/block ----------------
// grid (97, 48)
__global__ __launch_bounds__(NTH, 5) void psf_fx() {
  int fy0 = blockIdx.x * 4, ap = blockIdx.y;
  extern __shared__ float2 sm[];
  float2* tws = sm; float2* cols = sm + TWN;
  int tid = threadIdx.x;
  load_tws(tws, tid);
  const float2* mid = g_mid + (size_t)ap * NH * PK;
  for (int idx = tid; idx < 4 * NF; idx += NTH) {
    int row = idx / NF, C = idx - row * NF;
    int fy = fy0 + row; if (fy > NH - 1) fy = NH - 1;
    float2 v = make_float2(0.0f, 0.0f);
    if (C < PK) v = mid[(size_t)fy * PK + C];
    cols[row * CSTRP + PD(C)] = v;
  }
  fft768_run<false>(cols, tws, tid);
  for (int idx = tid; idx < 4 * NF; idx += NTH) {
    int row = idx / NF, fx = idx - row * NF;
    if (fy0 + row <= NH - 1)
      g_psfF[((size_t)ap * NH + fy0 + row) * NF + fx] = cols[row * CSTRP + PD(fx)];
  }
}

// ---------------- inverse pass A: pointwise product + IFFT along x, 4 rows/block ------
// grid (97, 32, 3). Stores Q[(l*32+a)][fy][x-64] for x in [64,640).
__global__ __launch_bounds__(NTH, 5) void conv_x() {
  int fy0 = blockIdx.x * 4, a = blockIdx.y, l = blockIdx.z;
  int al = l * 16 + (a & 15);
  extern __shared__ float2 sm[];
  float2* tws = sm; float2* cols = sm + TWN;
  int tid = threadIdx.x;
  load_tws(tws, tid);
  const float2* Sb = g_segF + (size_t)a * NH * NF;
  const float2* Fb = g_psfF + (size_t)al * NH * NF;
  for (int idx = tid; idx < 4 * NF; idx += NTH) {
    int row = idx / NF, fx = idx - row * NF;
    int fy = fy0 + row; if (fy > NH - 1) fy = NH - 1;
    float2 S = Sb[(size_t)fy * NF + fx];
    float2 F = Fb[(size_t)fy * NF + fx];
    cols[row * CSTRP + PD(fx)] = cmul(S, F);
  }
  fft768_run<true>(cols, tws, tid);
  const float sc = 1.0f / (float)NF;
  float2* Q = g_mid + (size_t)(l * 32 + a) * NH * SEGMAX;
  for (int idx = tid; idx < 4 * SEGMAX; idx += NTH) {
    int row = idx / SEGMAX, x = idx - row * SEGMAX;
    if (fy0 + row <= NH - 1) {
      float2 v = cols[row * CSTRP + PD(64 + x)];
      Q[(size_t)(fy0 + row) * SEGMAX + x] = make_float2(v.x * sc, v.y * sc);
    }
  }
}

// ---------------- inverse pass B: C2R IFFT along y (two columns per FFT) -------------
// grid (72, 32, 3); 4 packed FFTs/block = 8 x-columns. Window + store to g_acc.
__global__ __launch_bounds__(NTH, 5) void conv_y() {
  int g = blockIdx.x, a = blockIdx.y, l = blockIdx.z;
  int b = a >> 4, t = a & 15, ti = t >> 2, tj = t & 3;
  int h0, h1, w0, w1; tile_range(ti, &h0, &h1); tile_range(tj, &w0, &w1);
  int Hsz = h1 - h0, Wsz = w1 - w0;
  extern __shared__ float2 sm[];
  float2* tws = sm; float2* cols = sm + TWN;
  int tid = threadIdx.x;
  load_tws(tws, tid);
  const float2* Q = g_mid + (size_t)(l * 32 + a) * NH * SEGMAX;
  for (int idx = tid; idx < NH * 4; idx += NTH) {
    int c = idx & 3, fy = idx >> 2;
    const float4 q4 = *(const float4*)(Q + (size_t)fy * SEGMAX + g * 8 + 2 * c);
    cols[c * CSTRP + PD(posf(fy))] = make_float2(q4.x - q4.w, q4.y + q4.z);
    if (fy >= 1 && fy <= NF / 2 - 1)
      cols[c * CSTRP + PD(posf(NF - fy))] = make_float2(q4.x + q4.w, q4.z - q4.y);
  }
  fft768_run<true>(cols, tws, tid);
  int sv = (Hsz == 576 && Wsz == 576) ? 1 : 0;
  const float sc = 1.0f / (float)NF;
  float* outbase = g_acc + (size_t)((b * 3 + l) * 16 + t) * (SEGMAX * SEGMAX);
  for (int idx = tid; idx < 4 * SEGMAX; idx += NTH) {
    int c = idx & 3, r = idx >> 2;
    int x0 = g * 8 + 2 * c;
    if (r < Hsz && x0 < Wsz) {
      float2 v = cols[c * CSTRP + PD(r + 64)];
      float wy  = g_wtab[(ti * 2 + sv) * SEGMAX + r];
      float wx0 = g_wtab[(tj * 2 + sv) * SEGMAX + x0];
      float wx1 = g_wtab[(tj * 2 + sv) * SEGMAX + x0 + 1];
      float2 o = make_float2(v.x * sc * wy * wx0, v.y * sc * wy * wx1);
      *(float2*)(outbase + (size_t)r * Wsz + x0) = o;
    }
  }
}

// ---------------- overlap-add gather + normalize + rotation via smem transpose -------
// grid (64, 64, 6), block (32, 8). Out tile: J in [J0,J0+32), I in [I0,I0+32).
__global__ __launch_bounds__(256) void finalize_t(float* __restrict__ outp) {
  int J0 = blockIdx.x * 32, I0 = blockIdx.y * 32;
  int z = blockIdx.z;            // z = b*3 + l
  __shared__ float ssum[32][33];
  __shared__ float swin[32][33];
  int lx = threadIdx.x, ly = threadIdx.y;
  for (int yy = ly; yy < 32; yy += 8) { ssum[yy][lx] = 0.0f; swin[yy][lx] = 0.0f; }
  __syncthreads();
  int ylo = IMG - 1 - (J0 + 31);   // y = ylo + yy, yy in [0,32)
#pragma unroll
  for (int i = 0; i < 4; ++i) {
    int h0, h1; tile_range(i, &h0, &h1);
    if (ylo + 31 < h0 || ylo >= h1) continue;
#pragma unroll
    for (int j = 0; j < 4; ++j) {
      int w0, w1; tile_range(j, &w0, &w1);
      if (I0 + 31 < w0 || I0 >= w1) continue;
      int Hsz = h1 - h0, Wsz = w1 - w0;
      int sv = (Hsz == 576 && Wsz == 576) ? 1 : 0;
      const float* base = g_acc + (size_t)(z * 16 + i * 4 + j) * (SEGMAX * SEGMAX);
      int x = I0 + lx;
      bool xok = (x >= w0 && x < w1);
      float wx = xok ? g_wtab[(j * 2 + sv) * SEGMAX + (x - w0)] : 0.0f;
      for (int yy = ly; yy < 32; yy += 8) {
        int y = ylo + yy;
        if (xok && y >= h0 && y < h1) {
          int r = y - h0;
          ssum[yy][lx] += base[(size_t)r * Wsz + (x - w0)];
          swin[yy][lx] += g_wtab[(i * 2 + sv) * SEGMAX + r] * wx;
        }
      }
    }
  }
  __syncthreads();
  for (int ii = ly; ii < 32; ii += 8) {
    int I = I0 + ii;
    int J = J0 + lx;
    int yy = 31 - lx;              // (IMG-1-J) - ylo
    float s = ssum[yy][ii];
    float w = swin[yy][ii];
    float res = s / fmaxf(w, 1e-12f);
    if (!(res == res)) res = 0.0f;
    outp[((size_t)z * IMG + I) * IMG + J] = res;
  }
}

extern "C" void kernel_launch(void* const* d_in, const int* in_sizes, int n_in,
                              void* d_out, int out_size) {
  const float* Timg = (const float*)d_in[0];
  const float* psfs = (const float*)d_in[1];
  (void)in_sizes; (void)n_in;
  float* outp = (float*)d_out;

  cudaFuncSetAttribute(seg_fy, cudaFuncAttributeMaxDynamicSharedMemorySize, (int)SM4_BYTES);
  cudaFuncSetAttribute(seg_fx, cudaFuncAttributeMaxDynamicSharedMemorySize, (int)SM4_BYTES);
  cudaFuncSetAttribute(psf_fy, cudaFuncAttributeMaxDynamicSharedMemorySize, (int)SM4_BYTES);
  cudaFuncSetAttribute(psf_fx, cudaFuncAttributeMaxDynamicSharedMemorySize, (int)SM4_BYTES);
  cudaFuncSetAttribute(conv_x, cudaFuncAttributeMaxDynamicSharedMemorySize, (int)SM4_BYTES);
  cudaFuncSetAttribute(conv_y, cudaFuncAttributeMaxDynamicSharedMemorySize, (int)SM4_BYTES);

  init_wtab_kernel<<<18, 256>>>();
  init_twm_kernel<<<2, 256>>>();

  seg_fy<<<dim3(72, 32), NTH, SM4_BYTES>>>(Timg);
  seg_fx<<<dim3(97, 32), NTH, SM4_BYTES>>>();
  psf_fy<<<dim3(16, 48), NTH, SM4_BYTES>>>(psfs);
  psf_fx<<<dim3(97, 48), NTH, SM4_BYTES>>>();

  conv_x<<<dim3(97, 32, 3), NTH, SM4_BYTES>>>();
  conv_y<<<dim3(72, 32, 3), NTH, SM4_BYTES>>>();

  finalize_t<<<dim3(64, 64, 6), dim3(32, 8)>>>(outp);
}

// round 11
// speedup vs baseline: 87.5449x; 1.1240x over previous
#include <cuda_runtime.h>
#include <math.h>

#ifndef M_PI
#define M_PI 3.14159265358979323846
#endif

// Problem constants (fixed shapes: (2,1,2048,2048) images, (3,16,128,128) psfs, overlap=64)
#define IMG     2048
#define HS_     512
#define OV2     32
#define PK      128
#define SEGMAX  576
#define NF      768                     // FFT length = 3 * 4^4  (>= 703 support)
#define NH      385                     // Hermitian rows: fy in [0,384]

#define PD(i)   ((i) + ((i) >> 4))      // smem pad: +1 float2 per 16 (all stages conflict-free)
#define CSTRP   815                     // >= PD(767)+1 = 815
#define TWN     341                     // 256 (W_768^n) + 64 (W_256) + 16 (W_64) + 4 (W_16) + 1
#define S3F     0.86602540378443864676f // sqrt(3)/2
#define NTH     256                     // threads per FFT block (4 columns x TPC=64)

// psf-mid offset inside g_mid: AFTER the 32 seg-mid tile-batches so psf_fy cannot
// clobber seg-mid before segconv_x consumes it (R8 bug). psf-mid then lies inside the
// Q[l=1] region, which segconv_x writes only after psf_fx has consumed psf-mid.
#define PSFMID  ((size_t)32 * NH * SEGMAX)

// ---------------- static scratch ----------------
__device__ __align__(16) float  g_acc[(size_t)2 * 3 * 16 * SEGMAX * SEGMAX];   // 127 MB
__device__ float  g_wtab[4 * 2 * SEGMAX];
__device__ float2 g_twm[TWN];
__device__ __align__(16) float2 g_psfF[(size_t)48 * NH * NF];                  // 113 MB [al][fy][fx']
// multi-use: seg mid [32][385][576] @0; psf mid [48][385][128] @PSFMID; Q [96][385][576]
__device__ __align__(16) float2 g_mid[(size_t)96 * NH * SEGMAX];               // 170 MB

__device__ __forceinline__ void tile_range(int i, int* a0, int* a1) {
  int lo = i * HS_ - OV2; if (lo < 0) lo = 0;
  int hi = (i + 1) * HS_ + OV2; if (hi > IMG) hi = IMG;
  *a0 = lo; *a1 = hi;
}
__device__ __forceinline__ float2 cmul(float2 a, float2 b) {
  return make_float2(a.x * b.x - a.y * b.y, a.x * b.y + a.y * b.x);
}
__device__ __forceinline__ int drev4_4(int k) {
  return ((k & 3) << 6) | (((k >> 2) & 3) << 4) | (((k >> 4) & 3) << 2) | ((k >> 6) & 3);
}
// smem position holding natural frequency f: chunk = f%3, within-chunk base-4 digit reversal
__device__ __forceinline__ int posf(int f) {
  return (f % 3) * 256 + drev4_4(f / 3);
}

// radix-4 butterflies operating on registers (outputs in place)
__device__ __forceinline__ void dif4(float2& a, float2& b, float2& c, float2& d, float2 w1) {
  float2 t0 = make_float2(a.x + c.x, a.y + c.y);
  float2 t1 = make_float2(a.x - c.x, a.y - c.y);
  float2 t2 = make_float2(b.x + d.x, b.y + d.y);
  float2 t3 = make_float2(b.x - d.x, b.y - d.y);
  float2 w2 = cmul(w1, w1);
  float2 w3 = cmul(w2, w1);
  float2 u1 = make_float2(t1.x + t3.y, t1.y - t3.x);
  float2 u3 = make_float2(t1.x - t3.y, t1.y + t3.x);
  a = make_float2(t0.x + t2.x, t0.y + t2.y);
  b = cmul(u1, w1);
  c = cmul(make_float2(t0.x - t2.x, t0.y - t2.y), w2);
  d = cmul(u3, w3);
}
__device__ __forceinline__ void dif4_nw(float2& a, float2& b, float2& c, float2& d) {
  float2 t0 = make_float2(a.x + c.x, a.y + c.y);
  float2 t1 = make_float2(a.x - c.x, a.y - c.y);
  float2 t2 = make_float2(b.x + d.x, b.y + d.y);
  float2 t3 = make_float2(b.x - d.x, b.y - d.y);
  a = make_float2(t0.x + t2.x, t0.y + t2.y);
  b = make_float2(t1.x + t3.y, t1.y - t3.x);
  c = make_float2(t0.x - t2.x, t0.y - t2.y);
  d = make_float2(t1.x - t3.y, t1.y + t3.x);
}
// DIT butterfly; w1 is ALREADY conjugated
__device__ __forceinline__ void dit4(float2& a, float2& b, float2& c, float2& d, float2 w1) {
  float2 w2 = cmul(w1, w1);
  float2 w3 = cmul(w2, w1);
  float2 bb = cmul(b, w1), cc = cmul(c, w2), dd = cmul(d, w3);
  float2 t0 = make_float2(a.x + cc.x, a.y + cc.y);
  float2 t1 = make_float2(a.x - cc.x, a.y - cc.y);
  float2 t2 = make_float2(bb.x + dd.x, bb.y + dd.y);
  float2 t3 = make_float2(bb.x - dd.x, bb.y - dd.y);
  a = make_float2(t0.x + t2.x, t0.y + t2.y);
  b = make_float2(t1.x - t3.y, t1.y + t3.x);
  c = make_float2(t0.x - t2.x, t0.y - t2.y);
  d = make_float2(t1.x + t3.y, t1.y - t3.x);
}
__device__ __forceinline__ void dit4_nw(float2& a, float2& b, float2& c, float2& d) {
  float2 t0 = make_float2(a.x + c.x, a.y + c.y);
  float2 t1 = make_float2(a.x - c.x, a.y - c.y);
  float2 t2 = make_float2(b.x + d.x, b.y + d.y);
  float2 t3 = make_float2(b.x - d.x, b.y - d.y);
  a = make_float2(t0.x + t2.x, t0.y + t2.y);
  b = make_float2(t1.x - t3.y, t1.y + t3.x);
  c = make_float2(t0.x - t2.x, t0.y - t2.y);
  d = make_float2(t1.x + t3.y, t1.y - t3.x);
}

// ---------------- init (merged) ----------------
__global__ void init_tabs_kernel() {
  int idx = blockIdx.x * blockDim.x + threadIdx.x;
  if (idx < 4 * 2 * SEGMAX) {
    int p  = idx % SEGMAX;
    int sv = (idx / SEGMAX) & 1;
    int i  = idx / (2 * SEGMAX);
    int a0, a1; tile_range(i, &a0, &a1);
    int S = a1 - a0;
    float val = 0.0f;
    if (p < S) {
      float sigma = sv ? 144.0f : 136.0f;
      float v = -0.5f * (float)S + (float)p * ((float)S / (float)(S - 1));
      val = expf(-0.5f * v * v / (sigma * sigma));
    }
    g_wtab[idx] = val;
  }
  int jt = idx - 4 * 2 * SEGMAX;
  if (jt >= 0 && jt < TWN) {
    double ang;
    if (jt < 256) {
      ang = -2.0 * M_PI * (double)jt / (double)NF;           // W_768^n
    } else {
      int j = jt - 256;
      int m, denom;
      if      (j < 64) { m = j;      denom = 256; }
      else if (j < 80) { m = j - 64; denom = 64;  }
      else if (j < 84) { m = j - 80; denom = 16;  }
      else             { m = 0;      denom = 4;   }
      ang = -2.0 * M_PI * (double)m / (double)denom;
    }
    double sn, cs; sincos(ang, &sn, &cs);
    g_twm[jt] = make_float2((float)cs, (float)sn);
  }
}

// ---------------- mixed-radix 768-pt FFT (3 * 4^4), register radix-16 stages ------------
// Forward (DIF): natural input -> scrambled output: pos g*256+p holds X[3*drev4_4(p)+g].
// Inverse (DIT): scrambled input in same layout -> natural output (unscaled).
// 4 columns per block, NTH=256 threads, TPC=64 (warps never straddle columns).
template<bool INV>
__device__ __forceinline__ void fft768_run(float2* cols, const float2* tws, int tid) {
  const int TPC = 64;
  float2* col = cols + (tid / TPC) * CSTRP;
  int tc = tid % TPC;
  const float2* tw3 = tws;         // 256: W_768^n
  const float2* tw4 = tws + 256;   // 64 (W_256) + 16 (W_64) + 4 (W_16) + 1
  bool active = (tc < 48);
  int chunk = tc >> 4;             // 0..2 (valid when active)
  int mm = tc & 15;
  float2 x[16];
  if (!INV) {
    // ---- radix-3 DIF stage (stride 256) ----
    __syncthreads();
    for (int n = tc; n < 256; n += TPC) {
      float2 a = col[PD(n)], b = col[PD(n + 256)], c = col[PD(n + 512)];
      float2 u = make_float2(b.x + c.x, b.y + c.y);
      float2 v = make_float2(b.x - c.x, b.y - c.y);
      float2 t = make_float2(a.x - 0.5f * u.x, a.y - 0.5f * u.y);
      float2 y1 = make_float2(t.x + S3F * v.y, t.y - S3F * v.x);
      float2 y2 = make_float2(t.x - S3F * v.y, t.y + S3F * v.x);
      float2 w1 = tw3[n];
      float2 w2 = cmul(w1, w1);
      col[PD(n)]       = make_float2(a.x + u.x, a.y + u.y);
      col[PD(n + 256)] = cmul(y1, w1);
      col[PD(n + 512)] = cmul(y2, w2);
    }
    // ---- stage B: merged radix-4 q=64 + q=16 (footprint stride 16) ----
    __syncthreads();
    if (active) {
      int base = chunk * 256 + mm;
#pragma unroll
      for (int j = 0; j < 16; ++j) x[j] = col[PD(base + 16 * j)];
#pragma unroll
      for (int j0 = 0; j0 < 4; ++j0)
        dif4(x[j0], x[j0 + 4], x[j0 + 8], x[j0 + 12], tw4[mm + 16 * j0]);   // W_256^(mm+16*j0)
      float2 wB = tw4[64 + mm];                                             // W_64^mm
#pragma unroll
      for (int a = 0; a < 4; ++a)
        dif4(x[4 * a], x[4 * a + 1], x[4 * a + 2], x[4 * a + 3], wB);
#pragma unroll
      for (int j = 0; j < 16; ++j) col[PD(base + 16 * j)] = x[j];
    }
    // ---- stage C: merged radix-4 q=4 + q=1 (footprint stride 1) ----
    __syncthreads();
    if (active) {
      int base = chunk * 256 + 16 * mm;
#pragma unroll
      for (int k = 0; k < 16; ++k) x[k] = col[PD(base + k)];
#pragma unroll
      for (int k0 = 0; k0 < 4; ++k0)
        dif4(x[k0], x[k0 + 4], x[k0 + 8], x[k0 + 12], tw4[80 + k0]);        // W_16^k0
#pragma unroll
      for (int a = 0; a < 4; ++a)
        dif4_nw(x[4 * a], x[4 * a + 1], x[4 * a + 2], x[4 * a + 3]);
#pragma unroll
      for (int k = 0; k < 16; ++k) col[PD(base + k)] = x[k];
    }
  } else {
    // ---- stage C_inv: inverse of (q=1 then q=4) ----
    __syncthreads();
    if (active) {
      int base = chunk * 256 + 16 * mm;
#pragma unroll
      for (int k = 0; k < 16; ++k) x[k] = col[PD(base + k)];
#pragma unroll
      for (int a = 0; a < 4; ++a)
        dit4_nw(x[4 * a], x[4 * a + 1], x[4 * a + 2], x[4 * a + 3]);
#pragma unroll
      for (int k0 = 0; k0 < 4; ++k0) {
        float2 w = tw4[80 + k0]; w.y = -w.y;
        dit4(x[k0], x[k0 + 4], x[k0 + 8], x[k0 + 12], w);
      }
#pragma unroll
      for (int k = 0; k < 16; ++k) col[PD(base + k)] = x[k];
    }
    // ---- stage B_inv: inverse of (q=16 then q=64) ----
    __syncthreads();
    if (active) {
      int base = chunk * 256 + mm;
#pragma unroll
      for (int j = 0; j < 16; ++j) x[j] = col[PD(base + 16 * j)];
      float2 wB = tw4[64 + mm]; wB.y = -wB.y;
#pragma unroll
      for (int a = 0; a < 4; ++a)
        dit4(x[4 * a], x[4 * a + 1], x[4 * a + 2], x[4 * a + 3], wB);
#pragma unroll
      for (int j0 = 0; j0 < 4; ++j0) {
        float2 w = tw4[mm + 16 * j0]; w.y = -w.y;
        dit4(x[j0], x[j0 + 4], x[j0 + 8], x[j0 + 12], w);
      }
#pragma unroll
      for (int j = 0; j < 16; ++j) col[PD(base + 16 * j)] = x[j];
    }
    // ---- radix-3 DIT stage ----
    __syncthreads();
    for (int n = tc; n < 256; n += TPC) {
      float2 w1 = tw3[n]; w1.y = -w1.y;
      float2 w2 = cmul(w1, w1);
      float2 z0 = col[PD(n)];
      float2 z1 = cmul(col[PD(n + 256)], w1);
      float2 z2 = cmul(col[PD(n + 512)], w2);
      float2 u = make_float2(z1.x + z2.x, z1.y + z2.y);
      float2 v = make_float2(z1.x - z2.x, z1.y - z2.y);
      float2 t = make_float2(z0.x - 0.5f * u.x, z0.y - 0.5f * u.y);
      col[PD(n)]       = make_float2(z0.x + u.x, z0.y + u.y);
      col[PD(n + 256)] = make_float2(t.x - S3F * v.y, t.y + S3F * v.x);
      col[PD(n + 512)] = make_float2(t.x + S3F * v.y, t.y - S3F * v.x);
    }
  }
  __syncthreads();
}

#define SM4_BYTES  ((TWN + 4 * CSTRP) * sizeof(float2))             // ~28.9 KB
#define SMFU_BYTES ((TWN + 4 * CSTRP + 4 * NF) * sizeof(float2))    // ~53.4 KB (fused)

__device__ __forceinline__ void load_tws(float2* tws, int tid) {
  for (int i = tid; i < TWN; i += NTH) tws[i] = g_twm[i];
}

// ---------------- seg pass 1: two-for-one forward FFT along y ----------------
// 4 packed FFTs/block = 8 real columns. grid (72, 32).
__global__ __launch_bounds__(NTH, 5) void seg_fy(const float* __restrict__ Timg) {
  int g = blockIdx.x, a = blockIdx.y;
  int b = a >> 4, t = a & 15, ti = t >> 2, tj = t & 3;
  int h0, h1, w0, w1; tile_range(ti, &h0, &h1); tile_range(tj, &w0, &w1);
  int Hsz = h1 - h0, Wsz = w1 - w0;
  extern __shared__ float2 sm[];
  float2* tws = sm; float2* cols = sm + TWN;
  int tid = threadIdx.x;
  load_tws(tws, tid);
  const float* Tb = Timg + (size_t)b * IMG * IMG;
  for (int idx = tid; idx < 4 * NF; idx += NTH) {
    int c = idx / NF, R = idx - c * NF;
    int C0 = g * 8 + 2 * c;
    float vr = 0.0f, vi = 0.0f;
    if (R < Hsz) {
      int base = IMG - 1 - (h0 + R);
      if (C0 < Wsz)     vr = Tb[(size_t)(w0 + C0) * IMG + base];
      if (C0 + 1 < Wsz) vi = Tb[(size_t)(w0 + C0 + 1) * IMG + base];
    }
    cols[c * CSTRP + PD(R)] = make_float2(vr, vi);
  }
  fft768_run<false>(cols, tws, tid);
  float2* outp = g_mid + (size_t)a * NH * SEGMAX;
  for (int idx = tid; idx < NH * 4; idx += NTH) {
    int c = idx & 3, fy = idx >> 2;
    float2 z1 = cols[c * CSTRP + PD(posf(fy))];
    float2 z2 = cols[c * CSTRP + PD(posf((NF - fy) % NF))];
    z2.y = -z2.y;
    float2 c0 = make_float2(0.5f * (z1.x + z2.x), 0.5f * (z1.y + z2.y));
    float2 c1 = make_float2(0.5f * (z1.y - z2.y), -0.5f * (z1.x - z2.x));
    float4* o4 = (float4*)(outp + (size_t)fy * SEGMAX + g * 8 + 2 * c);
    *o4 = make_float4(c0.x, c0.y, c1.x, c1.y);
  }
}

// ---------------- psf pass 1: two-for-one forward FFT along p ----------------
// grid (16, 48). k[p][q] = psfs[l,hd,q,127-p]. Output psf-mid @PSFMID (stride 128).
__global__ __launch_bounds__(NTH, 5) void psf_fy(const float* __restrict__ psfs) {
  int g = blockIdx.x, ap = blockIdx.y;
  int l = ap / 16, t = ap % 16, ti = t >> 2, tj = t & 3;
  int hd = tj * 4 + ti;
  extern __shared__ float2 sm[];
  float2* tws = sm; float2* cols = sm + TWN;
  int tid = threadIdx.x;
  load_tws(tws, tid);
  const float* Pb = psfs + ((size_t)l * 16 + hd) * PK * PK;
  for (int idx = tid; idx < 4 * NF; idx += NTH) {
    int c = idx / NF, p = idx - c * NF;
    int q0 = g * 8 + 2 * c;
    float vr = 0.0f, vi = 0.0f;
    if (p < PK) {
      vr = Pb[(size_t)q0 * PK + (PK - 1 - p)];
      vi = Pb[(size_t)(q0 + 1) * PK + (PK - 1 - p)];
    }
    cols[c * CSTRP + PD(p)] = make_float2(vr, vi);
  }
  fft768_run<false>(cols, tws, tid);
  float2* outp = g_mid + PSFMID + (size_t)ap * NH * PK;
  for (int idx = tid; idx < NH * 4; idx += NTH) {
    int c = idx & 3, fy = idx >> 2;
    float2 z1 = cols[c * CSTRP + PD(posf(fy))];
    float2 z2 = cols[c * CSTRP + PD(posf((NF - fy) % NF))];
    z2.y = -z2.y;
    float2 c0 = make_float2(0.5f * (z1.x + z2.x), 0.5f * (z1.y + z2.y));
    float2 c1 = make_float2(0.5f * (z1.y - z2.y), -0.5f * (z1.x - z2.x));
    float4* o4 = (float4*)(outp + (size_t)fy * PK + g * 8 + 2 * c);
    *o4 = make_float4(c0.x, c0.y, c1.x, c1.y);
  }
}

// ---------------- psf pass 2: forward FFT along q, 4 rows/block ----------------
// grid (97, 48)
__global__ __launch_bounds__(NTH, 5) void psf_fx() {
  int fy0 = blockIdx.x * 4, ap = blockIdx.y;
  extern __shared__ float2 sm[];
  float2* tws = sm; float2* cols = sm + TWN;
  int tid = threadIdx.x;
  load_tws(tws, tid);
  const float2* mid = g_mid + PSFMID + (size_t)ap * NH * PK;
  for (int idx = tid; idx < 4 * NF; idx += NTH) {
    int row = idx / NF, C = idx - row * NF;
    int fy = fy0 + row; if (fy > NH - 1) fy = NH - 1;
    float2 v = make_float2(0.0f, 0.0f);
    if (C < PK) v = mid[(size_t)fy * PK + C];
    cols[row * CSTRP + PD(C)] = v;
  }
  fft768_run<false>(cols, tws, tid);
  for (int idx = tid; idx < 4 * NF; idx += NTH) {
    int row = idx / NF, fx = idx - row * NF;
    if (fy0 + row <= NH - 1)
      g_psfF[((size_t)ap * NH + fy0 + row) * NF + fx] = cols[row * CSTRP + PD(fx)];
  }
}

// ---------------- FUSED: seg forward x-FFT + product + 3x inverse x-IFFT --------------
// grid (97, 32). Spectrum parked in linear smem; Q[(l*32+a)][fy][x-64] stored per l.
// Q l=0 overlaps seg-mid rows read by THIS block only (same fy rows) -> safe ordering.
__global__ __launch_bounds__(NTH, 4) void segconv_x() {
  int fy0 = blockIdx.x * 4, a = blockIdx.y;
  extern __shared__ float2 sm[];
  float2* tws = sm; float2* cols = sm + TWN; float2* spec = sm + TWN + 4 * CSTRP;
  int tid = threadIdx.x;
  load_tws(tws, tid);
  const float2* mid = g_mid + (size_t)a * NH * SEGMAX;
  for (int idx = tid; idx < 4 * NF; idx += NTH) {
    int row = idx / NF, C = idx - row * NF;
    int fy = fy0 + row; if (fy > NH - 1) fy = NH - 1;
    float2 v = make_float2(0.0f, 0.0f);
    if (C < SEGMAX) v = mid[(size_t)fy * SEGMAX + C];
    cols[row * CSTRP + PD(C)] = v;
  }
  fft768_run<false>(cols, tws, tid);
  // park spectrum (position-linear, conflict-free)
  for (int idx = tid; idx < 4 * NF; idx += NTH) {
    int row = idx / NF, p = idx - row * NF;
    spec[idx] = cols[row * CSTRP + PD(p)];
  }
  __syncthreads();
  const float sc = 1.0f / (float)NF;
#pragma unroll 1
  for (int l = 0; l < 3; ++l) {
    int al = l * 16 + (a & 15);
    const float2* Fb = g_psfF + (size_t)al * NH * NF;
    for (int idx = tid; idx < 4 * NF; idx += NTH) {
      int row = idx / NF, p = idx - row * NF;
      int fy = fy0 + row; if (fy > NH - 1) fy = NH - 1;
      cols[row * CSTRP + PD(p)] = cmul(spec[idx], Fb[(size_t)fy * NF + p]);
    }
    fft768_run<true>(cols, tws, tid);
    float2* Q = g_mid + (size_t)(l * 32 + a) * NH * SEGMAX;
    for (int idx = tid; idx < 4 * SEGMAX; idx += NTH) {
      int row = idx / SEGMAX, x = idx - row * SEGMAX;
      if (fy0 + row <= NH - 1) {
        float2 v = cols[row * CSTRP + PD(64 + x)];
        Q[(size_t)(fy0 + row) * SEGMAX + x] = make_float2(v.x * sc, v.y * sc);
      }
    }
    __syncthreads();   // protect cols before next l overwrites
  }
}

// ---------------- inverse pass B: C2R IFFT along y (two columns per FFT) -------------
// grid (72, 32, 3); 4 packed FFTs/block = 8 x-columns. Window + store to g_acc.
__global__ __launch_bounds__(NTH, 5) void conv_y() {
  int g = blockIdx.x, a = blockIdx.y, l = blockIdx.z;
  int b = a >> 4, t = a & 15, ti = t >> 2, tj = t & 3;
  int h0, h1, w0, w1; tile_range(ti, &h0, &h1); tile_range(tj, &w0, &w1);
  int Hsz = h1 - h0, Wsz = w1 - w0;
  extern __shared__ float2 sm[];
  float2* tws = sm; float2* cols = sm + TWN;
  int tid = threadIdx.x;
  load_tws(tws, tid);
  const float2* Q = g_mid + (size_t)(l * 32 + a) * NH * SEGMAX;
  for (int idx = tid; idx < NH * 4; idx += NTH) {
    int c = idx & 3, fy = idx >> 2;
    const float4 q4 = *(const float4*)(Q + (size_t)fy * SEGMAX + g * 8 + 2 * c);
    cols[c * CSTRP + PD(posf(fy))] = make_float2(q4.x - q4.w, q4.y + q4.z);
    if (fy >= 1 && fy <= NF / 2 - 1)
      cols[c * CSTRP + PD(posf(NF - fy))] = make_float2(q4.x + q4.w, q4.z - q4.y);
  }
  fft768_run<true>(cols, tws, tid);
  int sv = (Hsz == 576 && Wsz == 576) ? 1 : 0;
  const float sc = 1.0f / (float)NF;
  float* outbase = g_acc + (size_t)((b * 3 + l) * 16 + t) * (SEGMAX * SEGMAX);
  for (int idx = tid; idx < 4 * SEGMAX; idx += NTH) {
    int c = idx & 3, r = idx >> 2;
    int x0 = g * 8 + 2 * c;
    if (r < Hsz && x0 < Wsz) {
      float2 v = cols[c * CSTRP + PD(r + 64)];
      float wy  = g_wtab[(ti * 2 + sv) * SEGMAX + r];
      float wx0 = g_wtab[(tj * 2 + sv) * SEGMAX + x0];
      float wx1 = g_wtab[(tj * 2 + sv) * SEGMAX + x0 + 1];
      float2 o = make_float2(v.x * sc * wy * wx0, v.y * sc * wy * wx1);
      *(float2*)(outbase + (size_t)r * Wsz + x0) = o;
    }
  }
}

// ---------------- overlap-add gather + normalize + rotation via smem transpose -------
// grid (64, 64, 6), block (32, 8). Out tile: J in [J0,J0+32), I in [I0,I0+32).
__global__ __launch_bounds__(256) void finalize_t(float* __restrict__ outp) {
  int J0 = blockIdx.x * 32, I0 = blockIdx.y * 32;
  int z = blockIdx.z;            // z = b*3 + l
  __shared__ float ssum[32][33];
  __shared__ float swin[32][33];
  int lx = threadIdx.x, ly = threadIdx.y;
  for (int yy = ly; yy < 32; yy += 8) { ssum[yy][lx] = 0.0f; swin[yy][lx] = 0.0f; }
  __syncthreads();
  int ylo = IMG - 1 - (J0 + 31);   // y = ylo + yy, yy in [0,32)
#pragma unroll
  for (int i = 0; i < 4; ++i) {
    int h0, h1; tile_range(i, &h0, &h1);
    if (ylo + 31 < h0 || ylo >= h1) continue;
#pragma unroll
    for (int j = 0; j < 4; ++j) {
      int w0, w1; tile_range(j, &w0, &w1);
      if (I0 + 31 < w0 || I0 >= w1) continue;
      int Hsz = h1 - h0, Wsz = w1 - w0;
      int sv = (Hsz == 576 && Wsz == 576) ? 1 : 0;
      const float* base = g_acc + (size_t)(z * 16 + i * 4 + j) * (SEGMAX * SEGMAX);
      int x = I0 + lx;
      bool xok = (x >= w0 && x < w1);
      float wx = xok ? g_wtab[(j * 2 + sv) * SEGMAX + (x - w0)] : 0.0f;
      for (int yy = ly; yy < 32; yy += 8) {
        int y = ylo + yy;
        if (xok && y >= h0 && y < h1) {
          int r = y - h0;
          ssum[yy][lx] += base[(size_t)r * Wsz + (x - w0)];
          swin[yy][lx] += g_wtab[(i * 2 + sv) * SEGMAX + r] * wx;
        }
      }
    }
  }
  __syncthreads();
  for (int ii = ly; ii < 32; ii += 8) {
    int I = I0 + ii;
    int J = J0 + lx;
    int yy = 31 - lx;              // (IMG-1-J) - ylo
    float s = ssum[yy][ii];
    float w = swin[yy][ii];
    float res = s / fmaxf(w, 1e-12f);
    if (!(res == res)) res = 0.0f;
    outp[((size_t)z * IMG + I) * IMG + J] = res;
  }
}

extern "C" void kernel_launch(void* const* d_in, const int* in_sizes, int n_in,
                              void* d_out, int out_size) {
  const float* Timg = (const float*)d_in[0];
  const float* psfs = (const float*)d_in[1];
  (void)in_sizes; (void)n_in;
  float* outp = (float*)d_out;

  cudaFuncSetAttribute(seg_fy,    cudaFuncAttributeMaxDynamicSharedMemorySize, (int)SM4_BYTES);
  cudaFuncSetAttribute(psf_fy,    cudaFuncAttributeMaxDynamicSharedMemorySize, (int)SM4_BYTES);
  cudaFuncSetAttribute(psf_fx,    cudaFuncAttributeMaxDynamicSharedMemorySize, (int)SM4_BYTES);
  cudaFuncSetAttribute(segconv_x, cudaFuncAttributeMaxDynamicSharedMemorySize, (int)SMFU_BYTES);
  cudaFuncSetAttribute(conv_y,    cudaFuncAttributeMaxDynamicSharedMemorySize, (int)SM4_BYTES);

  init_tabs_kernel<<<20, 256>>>();

  seg_fy<<<dim3(72, 32), NTH, SM4_BYTES>>>(Timg);
  psf_fy<<<dim3(16, 48), NTH, SM4_BYTES>>>(psfs);
  psf_fx<<<dim3(97, 48), NTH, SM4_BYTES>>>();

  segconv_x<<<dim3(97, 32), NTH, SMFU_BYTES>>>();
  conv_y<<<dim3(72, 32, 3), NTH, SM4_BYTES>>>();

  finalize_t<<<dim3(64, 64, 6), dim3(32, 8)>>>(outp);
}

// round 12
// speedup vs baseline: 101.1206x; 1.1551x over previous
#include <cuda_runtime.h>
#include <math.h>

#ifndef M_PI
#define M_PI 3.14159265358979323846
#endif

// Problem constants (fixed shapes: (2,1,2048,2048) images, (3,16,128,128) psfs, overlap=64)
#define IMG     2048
#define HS_     512
#define OV2     32
#define PK      128
#define SEGMAX  576
#define NF      768                     // FFT length = 3 * 4^4  (>= 703 support)
#define NH      385                     // Hermitian rows: fy in [0,384]

#define PD(i)   ((i) + ((i) >> 4))      // smem pad: +1 float2 per 16 (all stages conflict-free)
#define CSTRP   815                     // >= PD(767)+1 = 815
#define TWN     341                     // 256 (W_768^n) + 64 (W_256) + 16 (W_64) + 4 (W_16) + 1
#define S3F     0.86602540378443864676f // sqrt(3)/2
#define NTH     256                     // threads per FFT block (4 columns x TPC=64)

// psf-mid offset inside g_mid: AFTER the 32 seg-mid tile-batches (R8 aliasing fix).
#define PSFMID  ((size_t)32 * NH * SEGMAX)

// ---------------- static scratch ----------------
__device__ __align__(16) float  g_acc[(size_t)2 * 3 * 16 * SEGMAX * SEGMAX];   // 127 MB
__device__ float  g_wtab[4 * 2 * SEGMAX];
__device__ float2 g_twm[TWN];
__device__ ushort2 g_posftab[NH];       // .x = PD(posf(fy)), .y = PD(posf((NF-fy)%NF))
__device__ __align__(16) float2 g_psfF[(size_t)48 * NH * NF];                  // 113 MB [al][fy][fx']
// multi-use: seg mid [32][385][576] @0; psf mid [48][385][128] @PSFMID; Q [96][385][576]
__device__ __align__(16) float2 g_mid[(size_t)96 * NH * SEGMAX];               // 170 MB

__device__ __forceinline__ void tile_range(int i, int* a0, int* a1) {
  int lo = i * HS_ - OV2; if (lo < 0) lo = 0;
  int hi = (i + 1) * HS_ + OV2; if (hi > IMG) hi = IMG;
  *a0 = lo; *a1 = hi;
}
__device__ __forceinline__ float2 cmul(float2 a, float2 b) {
  return make_float2(a.x * b.x - a.y * b.y, a.x * b.y + a.y * b.x);
}
__device__ __forceinline__ int drev4_4(int k) {
  return ((k & 3) << 6) | (((k >> 2) & 3) << 4) | (((k >> 4) & 3) << 2) | ((k >> 6) & 3);
}
__device__ __forceinline__ int posf(int f) {
  return (f % 3) * 256 + drev4_4(f / 3);
}

// radix-4 butterflies operating on registers (outputs in place)
__device__ __forceinline__ void dif4(float2& a, float2& b, float2& c, float2& d, float2 w1) {
  float2 t0 = make_float2(a.x + c.x, a.y + c.y);
  float2 t1 = make_float2(a.x - c.x, a.y - c.y);
  float2 t2 = make_float2(b.x + d.x, b.y + d.y);
  float2 t3 = make_float2(b.x - d.x, b.y - d.y);
  float2 w2 = cmul(w1, w1);
  float2 w3 = cmul(w2, w1);
  float2 u1 = make_float2(t1.x + t3.y, t1.y - t3.x);
  float2 u3 = make_float2(t1.x - t3.y, t1.y + t3.x);
  a = make_float2(t0.x + t2.x, t0.y + t2.y);
  b = cmul(u1, w1);
  c = cmul(make_float2(t0.x - t2.x, t0.y - t2.y), w2);
  d = cmul(u3, w3);
}
__device__ __forceinline__ void dif4_nw(float2& a, float2& b, float2& c, float2& d) {
  float2 t0 = make_float2(a.x + c.x, a.y + c.y);
  float2 t1 = make_float2(a.x - c.x, a.y - c.y);
  float2 t2 = make_float2(b.x + d.x, b.y + d.y);
  float2 t3 = make_float2(b.x - d.x, b.y - d.y);
  a = make_float2(t0.x + t2.x, t0.y + t2.y);
  b = make_float2(t1.x + t3.y, t1.y - t3.x);
  c = make_float2(t0.x - t2.x, t0.y - t2.y);
  d = make_float2(t1.x - t3.y, t1.y + t3.x);
}
// DIT butterfly; w1 is ALREADY conjugated
__device__ __forceinline__ void dit4(float2& a, float2& b, float2& c, float2& d, float2 w1) {
  float2 w2 = cmul(w1, w1);
  float2 w3 = cmul(w2, w1);
  float2 bb = cmul(b, w1), cc = cmul(c, w2), dd = cmul(d, w3);
  float2 t0 = make_float2(a.x + cc.x, a.y + cc.y);
  float2 t1 = make_float2(a.x - cc.x, a.y - cc.y);
  float2 t2 = make_float2(bb.x + dd.x, bb.y + dd.y);
  float2 t3 = make_float2(bb.x - dd.x, bb.y - dd.y);
  a = make_float2(t0.x + t2.x, t0.y + t2.y);
  b = make_float2(t1.x - t3.y, t1.y + t3.x);
  c = make_float2(t0.x - t2.x, t0.y - t2.y);
  d = make_float2(t1.x + t3.y, t1.y - t3.x);
}
__device__ __forceinline__ void dit4_nw(float2& a, float2& b, float2& c, float2& d) {
  float2 t0 = make_float2(a.x + c.x, a.y + c.y);
  float2 t1 = make_float2(a.x - c.x, a.y - c.y);
  float2 t2 = make_float2(b.x + d.x, b.y + d.y);
  float2 t3 = make_float2(b.x - d.x, b.y - d.y);
  a = make_float2(t0.x + t2.x, t0.y + t2.y);
  b = make_float2(t1.x - t3.y, t1.y + t3.x);
  c = make_float2(t0.x - t2.x, t0.y - t2.y);
  d = make_float2(t1.x + t3.y, t1.y - t3.x);
}

// ---------------- init (merged: window + twiddles + scramble table) ----------------
__global__ void init_tabs_kernel() {
  int idx = blockIdx.x * blockDim.x + threadIdx.x;
  if (idx < 4 * 2 * SEGMAX) {
    int p  = idx % SEGMAX;
    int sv = (idx / SEGMAX) & 1;
    int i  = idx / (2 * SEGMAX);
    int a0, a1; tile_range(i, &a0, &a1);
    int S = a1 - a0;
    float val = 0.0f;
    if (p < S) {
      float sigma = sv ? 144.0f : 136.0f;
      float v = -0.5f * (float)S + (float)p * ((float)S / (float)(S - 1));
      val = expf(-0.5f * v * v / (sigma * sigma));
    }
    g_wtab[idx] = val;
  }
  int jt = idx - 4 * 2 * SEGMAX;
  if (jt >= 0 && jt < TWN) {
    double ang;
    if (jt < 256) {
      ang = -2.0 * M_PI * (double)jt / (double)NF;           // W_768^n
    } else {
      int j = jt - 256;
      int m, denom;
      if      (j < 64) { m = j;      denom = 256; }
      else if (j < 80) { m = j - 64; denom = 64;  }
      else if (j < 84) { m = j - 80; denom = 16;  }
      else             { m = 0;      denom = 4;   }
      ang = -2.0 * M_PI * (double)m / (double)denom;
    }
    double sn, cs; sincos(ang, &sn, &cs);
    g_twm[jt] = make_float2((float)cs, (float)sn);
  }
  int pt = idx - (4 * 2 * SEGMAX + TWN);
  if (pt >= 0 && pt < NH) {
    int px = PD(posf(pt));
    int py = PD(posf((NF - pt) % NF));
    g_posftab[pt] = make_ushort2((unsigned short)px, (unsigned short)py);
  }
}

// ---------------- mixed-radix 768-pt FFT (3 * 4^4), register radix-16 stages ------------
// Forward (DIF): natural input -> scrambled output: pos g*256+p holds X[3*drev4_4(p)+g].
// Inverse (DIT): scrambled input in same layout -> natural output (unscaled).
// 4 columns per block, NTH=256 threads, TPC=64 (warps never straddle columns).
template<bool INV>
__device__ __forceinline__ void fft768_run(float2* cols, const float2* tws, int tid) {
  const int TPC = 64;
  float2* col = cols + (tid / TPC) * CSTRP;
  int tc = tid % TPC;
  const float2* tw3 = tws;         // 256: W_768^n
  const float2* tw4 = tws + 256;   // 64 (W_256) + 16 (W_64) + 4 (W_16) + 1
  bool active = (tc < 48);
  int chunk = tc >> 4;             // 0..2 (valid when active)
  int mm = tc & 15;
  float2 x[16];
  if (!INV) {
    // ---- radix-3 DIF stage (stride 256) ----
    __syncthreads();
#pragma unroll
    for (int k = 0; k < 4; ++k) {
      int n = tc + 64 * k;
      float2 a = col[PD(n)], b = col[PD(n + 256)], c = col[PD(n + 512)];
      float2 u = make_float2(b.x + c.x, b.y + c.y);
      float2 v = make_float2(b.x - c.x, b.y - c.y);
      float2 t = make_float2(a.x - 0.5f * u.x, a.y - 0.5f * u.y);
      float2 y1 = make_float2(t.x + S3F * v.y, t.y - S3F * v.x);
      float2 y2 = make_float2(t.x - S3F * v.y, t.y + S3F * v.x);
      float2 w1 = tw3[n];
      float2 w2 = cmul(w1, w1);
      col[PD(n)]       = make_float2(a.x + u.x, a.y + u.y);
      col[PD(n + 256)] = cmul(y1, w1);
      col[PD(n + 512)] = cmul(y2, w2);
    }
    // ---- stage B: merged radix-4 q=64 + q=16 (footprint stride 16) ----
    __syncthreads();
    if (active) {
      int base = chunk * 256 + mm;
#pragma unroll
      for (int j = 0; j < 16; ++j) x[j] = col[PD(base + 16 * j)];
#pragma unroll
      for (int j0 = 0; j0 < 4; ++j0)
        dif4(x[j0], x[j0 + 4], x[j0 + 8], x[j0 + 12], tw4[mm + 16 * j0]);   // W_256^(mm+16*j0)
      float2 wB = tw4[64 + mm];                                             // W_64^mm
#pragma unroll
      for (int a = 0; a < 4; ++a)
        dif4(x[4 * a], x[4 * a + 1], x[4 * a + 2], x[4 * a + 3], wB);
#pragma unroll
      for (int j = 0; j < 16; ++j) col[PD(base + 16 * j)] = x[j];
    }
    // ---- stage C: merged radix-4 q=4 + q=1 (footprint stride 1) ----
    __syncthreads();
    if (active) {
      int base = chunk * 256 + 16 * mm;
#pragma unroll
      for (int k = 0; k < 16; ++k) x[k] = col[PD(base + k)];
#pragma unroll
      for (int k0 = 0; k0 < 4; ++k0)
        dif4(x[k0], x[k0 + 4], x[k0 + 8], x[k0 + 12], tw4[80 + k0]);        // W_16^k0
#pragma unroll
      for (int a = 0; a < 4; ++a)
        dif4_nw(x[4 * a], x[4 * a + 1], x[4 * a + 2], x[4 * a + 3]);
#pragma unroll
      for (int k = 0; k < 16; ++k) col[PD(base + k)] = x[k];
    }
  } else {
    // ---- stage C_inv ----
    __syncthreads();
    if (active) {
      int base = chunk * 256 + 16 * mm;
#pragma unroll
      for (int k = 0; k < 16; ++k) x[k] = col[PD(base + k)];
#pragma unroll
      for (int a = 0; a < 4; ++a)
        dit4_nw(x[4 * a], x[4 * a + 1], x[4 * a + 2], x[4 * a + 3]);
#pragma unroll
      for (int k0 = 0; k0 < 4; ++k0) {
        float2 w = tw4[80 + k0]; w.y = -w.y;
        dit4(x[k0], x[k0 + 4], x[k0 + 8], x[k0 + 12], w);
      }
#pragma unroll
      for (int k = 0; k < 16; ++k) col[PD(base + k)] = x[k];
    }
    // ---- stage B_inv ----
    __syncthreads();
    if (active) {
      int base = chunk * 256 + mm;
#pragma unroll
      for (int j = 0; j < 16; ++j) x[j] = col[PD(base + 16 * j)];
      float2 wB = tw4[64 + mm]; wB.y = -wB.y;
#pragma unroll
      for (int a = 0; a < 4; ++a)
        dit4(x[4 * a], x[4 * a + 1], x[4 * a + 2], x[4 * a + 3], wB);
#pragma unroll
      for (int j0 = 0; j0 < 4; ++j0) {
        float2 w = tw4[mm + 16 * j0]; w.y = -w.y;
        dit4(x[j0], x[j0 + 4], x[j0 + 8], x[j0 + 12], w);
      }
#pragma unroll
      for (int j = 0; j < 16; ++j) col[PD(base + 16 * j)] = x[j];
    }
    // ---- radix-3 DIT stage ----
    __syncthreads();
#pragma unroll
    for (int k = 0; k < 4; ++k) {
      int n = tc + 64 * k;
      float2 w1 = tw3[n]; w1.y = -w1.y;
      float2 w2 = cmul(w1, w1);
      float2 z0 = col[PD(n)];
      float2 z1 = cmul(col[PD(n + 256)], w1);
      float2 z2 = cmul(col[PD(n + 512)], w2);
      float2 u = make_float2(z1.x + z2.x, z1.y + z2.y);
      float2 v = make_float2(z1.x - z2.x, z1.y - z2.y);
      float2 t = make_float2(z0.x - 0.5f * u.x, z0.y - 0.5f * u.y);
      col[PD(n)]       = make_float2(z0.x + u.x, z0.y + u.y);
      col[PD(n + 256)] = make_float2(t.x - S3F * v.y, t.y + S3F * v.x);
      col[PD(n + 512)] = make_float2(t.x + S3F * v.y, t.y - S3F * v.x);
    }
  }
  __syncthreads();
}

#define SM4_BYTES  ((TWN + 4 * CSTRP) * sizeof(float2))             // ~28.9 KB
#define SMFU_BYTES ((TWN + 4 * CSTRP + 4 * NF) * sizeof(float2))    // ~53.4 KB (fused)

__device__ __forceinline__ void load_tws(float2* tws, int tid) {
  for (int i = tid; i < TWN; i += NTH) tws[i] = g_twm[i];
}

// ---------------- merged forward y pass: seg (blocks 0..2303) + psf (2304..3071) -------
// seg: a = bid/72, g = bid%72 -> 8 real columns starting g*8. Out: seg-mid @0.
// psf: ap = (bid-2304)/16, g = %16 -> 8 q-columns starting g*8. Out: psf-mid @PSFMID.
__global__ __launch_bounds__(NTH, 5) void fwd_y(const float* __restrict__ Timg,
                                                const float* __restrict__ psfs) {
  int bid = blockIdx.x;
  extern __shared__ float2 sm[];
  float2* tws = sm; float2* cols = sm + TWN;
  int tid = threadIdx.x;
  load_tws(tws, tid);
  bool isSeg = (bid < 2304);
  int a = 0, g = 0, ap = 0;
  if (isSeg) { a = bid / 72; g = bid - a * 72; }
  else       { int pb = bid - 2304; ap = pb >> 4; g = pb & 15; }

  if (isSeg) {
    int b = a >> 4, t = a & 15, ti = t >> 2, tj = t & 3;
    int h0, h1, w0, w1; tile_range(ti, &h0, &h1); tile_range(tj, &w0, &w1);
    int Hsz = h1 - h0, Wsz = w1 - w0;
    const float* Tb = Timg + (size_t)b * IMG * IMG;
#pragma unroll
    for (int c = 0; c < 4; ++c) {
      int C0 = g * 8 + 2 * c;
      const float* p0 = Tb + (size_t)(w0 + C0) * IMG;
      const float* p1 = p0 + IMG;
      bool ok0 = (C0 < Wsz), ok1 = (C0 + 1 < Wsz);
      float2* dst = cols + c * CSTRP;
#pragma unroll
      for (int R = tid; R < NF; R += NTH) {
        float vr = 0.0f, vi = 0.0f;
        if (R < Hsz) {
          int base = IMG - 1 - (h0 + R);
          if (ok0) vr = p0[base];
          if (ok1) vi = p1[base];
        }
        dst[PD(R)] = make_float2(vr, vi);
      }
    }
  } else {
    int l = ap / 16, t = ap - l * 16, ti = t >> 2, tj = t & 3;
    int hd = tj * 4 + ti;
    const float* Pb = psfs + ((size_t)l * 16 + hd) * PK * PK;
#pragma unroll
    for (int c = 0; c < 4; ++c) {
      int q0 = g * 8 + 2 * c;
      const float* s0 = Pb + (size_t)q0 * PK;
      const float* s1 = s0 + PK;
      float2* dst = cols + c * CSTRP;
#pragma unroll
      for (int p = tid; p < NF; p += NTH) {
        float vr = 0.0f, vi = 0.0f;
        if (p < PK) {
          vr = s0[PK - 1 - p];
          vi = s1[PK - 1 - p];
        }
        dst[PD(p)] = make_float2(vr, vi);
      }
    }
  }

  fft768_run<false>(cols, tws, tid);

  if (isSeg) {
    float2* outp = g_mid + (size_t)a * NH * SEGMAX;
    for (int idx = tid; idx < NH * 4; idx += NTH) {
      int c = idx & 3, fy = idx >> 2;
      ushort2 pp = g_posftab[fy];
      const float2* colc = cols + c * CSTRP;
      float2 z1 = colc[pp.x];
      float2 z2 = colc[pp.y];
      z2.y = -z2.y;
      float2 c0 = make_float2(0.5f * (z1.x + z2.x), 0.5f * (z1.y + z2.y));
      float2 c1 = make_float2(0.5f * (z1.y - z2.y), -0.5f * (z1.x - z2.x));
      float4* o4 = (float4*)(outp + (size_t)fy * SEGMAX + g * 8 + 2 * c);
      *o4 = make_float4(c0.x, c0.y, c1.x, c1.y);
    }
  } else {
    float2* outp = g_mid + PSFMID + (size_t)ap * NH * PK;
    for (int idx = tid; idx < NH * 4; idx += NTH) {
      int c = idx & 3, fy = idx >> 2;
      ushort2 pp = g_posftab[fy];
      const float2* colc = cols + c * CSTRP;
      float2 z1 = colc[pp.x];
      float2 z2 = colc[pp.y];
      z2.y = -z2.y;
      float2 c0 = make_float2(0.5f * (z1.x + z2.x), 0.5f * (z1.y + z2.y));
      float2 c1 = make_float2(0.5f * (z1.y - z2.y), -0.5f * (z1.x - z2.x));
      float4* o4 = (float4*)(outp + (size_t)fy * PK + g * 8 + 2 * c);
      *o4 = make_float4(c0.x, c0.y, c1.x, c1.y);
    }
  }
}

// ---------------- psf pass 2: forward FFT along q, 4 rows/block ----------------
// grid (97, 48)
__global__ __launch_bounds__(NTH, 5) void psf_fx() {
  int fy0 = blockIdx.x * 4, ap = blockIdx.y;
  extern __shared__ float2 sm[];
  float2* tws = sm; float2* cols = sm + TWN;
  int tid = threadIdx.x;
  load_tws(tws, tid);
  const float2* mid = g_mid + PSFMID + (size_t)ap * NH * PK;
#pragma unroll
  for (int row = 0; row < 4; ++row) {
    int fy = fy0 + row; if (fy > NH - 1) fy = NH - 1;
    const float2* src = mid + (size_t)fy * PK;
    float2* dst = cols + row * CSTRP;
#pragma unroll
    for (int C = tid; C < NF; C += NTH)
      dst[PD(C)] = (C < PK) ? src[C] : make_float2(0.0f, 0.0f);
  }
  fft768_run<false>(cols, tws, tid);
#pragma unroll
  for (int row = 0; row < 4; ++row) {
    int fy = fy0 + row;
    if (fy < NH) {
      float2* dst = g_psfF + ((size_t)ap * NH + fy) * NF;
      const float2* src = cols + row * CSTRP;
#pragma unroll
      for (int fx = tid; fx < NF; fx += NTH) dst[fx] = src[PD(fx)];
    }
  }
}

// ---------------- FUSED: seg forward x-FFT + product + 3x inverse x-IFFT --------------
// grid (97, 32). Spectrum parked in linear smem; Q[(l*32+a)][fy][x-64] stored per l.
__global__ __launch_bounds__(NTH, 4) void segconv_x() {
  int fy0 = blockIdx.x * 4, a = blockIdx.y;
  extern __shared__ float2 sm[];
  float2* tws = sm; float2* cols = sm + TWN; float2* spec = sm + TWN + 4 * CSTRP;
  int tid = threadIdx.x;
  load_tws(tws, tid);
  const float2* mid = g_mid + (size_t)a * NH * SEGMAX;
#pragma unroll
  for (int row = 0; row < 4; ++row) {
    int fy = fy0 + row; if (fy > NH - 1) fy = NH - 1;
    const float2* src = mid + (size_t)fy * SEGMAX;
    float2* dst = cols + row * CSTRP;
#pragma unroll
    for (int C = tid; C < NF; C += NTH)
      dst[PD(C)] = (C < SEGMAX) ? src[C] : make_float2(0.0f, 0.0f);
  }
  fft768_run<false>(cols, tws, tid);
  // park spectrum (position-linear, conflict-free)
#pragma unroll
  for (int row = 0; row < 4; ++row) {
    float2* sp = spec + row * NF;
    const float2* src = cols + row * CSTRP;
#pragma unroll
    for (int p = tid; p < NF; p += NTH) sp[p] = src[PD(p)];
  }
  __syncthreads();
  const float sc = 1.0f / (float)NF;
#pragma unroll 1
  for (int l = 0; l < 3; ++l) {
    int al = l * 16 + (a & 15);
    const float2* Fb = g_psfF + (size_t)al * NH * NF;
#pragma unroll
    for (int row = 0; row < 4; ++row) {
      int fy = fy0 + row; if (fy > NH - 1) fy = NH - 1;
      const float2* Frow = Fb + (size_t)fy * NF;
      const float2* sp = spec + row * NF;
      float2* dst = cols + row * CSTRP;
#pragma unroll
      for (int p = tid; p < NF; p += NTH)
        dst[PD(p)] = cmul(sp[p], Frow[p]);
    }
    fft768_run<true>(cols, tws, tid);
    float2* Q = g_mid + (size_t)(l * 32 + a) * NH * SEGMAX;
#pragma unroll
    for (int row = 0; row < 4; ++row) {
      int fy = fy0 + row;
      if (fy < NH) {
        float2* q = Q + (size_t)fy * SEGMAX;
        const float2* src = cols + row * CSTRP;
#pragma unroll
        for (int x = tid; x < SEGMAX; x += NTH) {
          float2 v = src[PD(64 + x)];
          q[x] = make_float2(v.x * sc, v.y * sc);
        }
      }
    }
    __syncthreads();   // protect cols before next l overwrites
  }
}

// ---------------- inverse pass B: C2R IFFT along y (two columns per FFT) -------------
// grid (72, 32, 3); 4 packed FFTs/block = 8 x-columns. Window + store to g_acc.
__global__ __launch_bounds__(NTH, 5) void conv_y() {
  int g = blockIdx.x, a = blockIdx.y, l = blockIdx.z;
  int b = a >> 4, t = a & 15, ti = t >> 2, tj = t & 3;
  int h0, h1, w0, w1; tile_range(ti, &h0, &h1); tile_range(tj, &w0, &w1);
  int Hsz = h1 - h0, Wsz = w1 - w0;
  extern __shared__ float2 sm[];
  float2* tws = sm; float2* cols = sm + TWN;
  int tid = threadIdx.x;
  load_tws(tws, tid);
  const float2* Q = g_mid + (size_t)(l * 32 + a) * NH * SEGMAX;
  for (int idx = tid; idx < NH * 4; idx += NTH) {
    int c = idx & 3, fy = idx >> 2;
    ushort2 pp = g_posftab[fy];
    const float4 q4 = *(const float4*)(Q + (size_t)fy * SEGMAX + g * 8 + 2 * c);
    float2* colc = cols + c * CSTRP;
    colc[pp.x] = make_float2(q4.x - q4.w, q4.y + q4.z);
    if (fy >= 1 && fy <= NF / 2 - 1)
      colc[pp.y] = make_float2(q4.x + q4.w, q4.z - q4.y);
  }
  fft768_run<true>(cols, tws, tid);
  int sv = (Hsz == 576 && Wsz == 576) ? 1 : 0;
  const float sc = 1.0f / (float)NF;
  float* outbase = g_acc + (size_t)((b * 3 + l) * 16 + t) * (SEGMAX * SEGMAX);
  for (int idx = tid; idx < 4 * SEGMAX; idx += NTH) {
    int c = idx & 3, r = idx >> 2;
    int x0 = g * 8 + 2 * c;
    if (r < Hsz && x0 < Wsz) {
      float2 v = cols[c * CSTRP + PD(r + 64)];
      float wy  = g_wtab[(ti * 2 + sv) * SEGMAX + r];
      float wx0 = g_wtab[(tj * 2 + sv) * SEGMAX + x0];
      float wx1 = g_wtab[(tj * 2 + sv) * SEGMAX + x0 + 1];
      float2 o = make_float2(v.x * sc * wy * wx0, v.y * sc * wy * wx1);
      *(float2*)(outbase + (size_t)r * Wsz + x0) = o;
    }
  }
}

// ---------------- overlap-add gather + normalize + rotation via smem transpose -------
// grid (64, 64, 6), block (32, 8). Out tile: J in [J0,J0+32), I in [I0,I0+32).
__global__ __launch_bounds__(256) void finalize_t(float* __restrict__ outp) {
  int J0 = blockIdx.x * 32, I0 = blockIdx.y * 32;
  int z = blockIdx.z;            // z = b*3 + l
  __shared__ float ssum[32][33];
  __shared__ float swin[32][33];
  int lx = threadIdx.x, ly = threadIdx.y;
  for (int yy = ly; yy < 32; yy += 8) { ssum[yy][lx] = 0.0f; swin[yy][lx] = 0.0f; }
  __syncthreads();
  int ylo = IMG - 1 - (J0 + 31);   // y = ylo + yy, yy in [0,32)
#pragma unroll
  for (int i = 0; i < 4; ++i) {
    int h0, h1; tile_range(i, &h0, &h1);
    if (ylo + 31 < h0 || ylo >= h1) continue;
#pragma unroll
    for (int j = 0; j < 4; ++j) {
      int w0, w1; tile_range(j, &w0, &w1);
      if (I0 + 31 < w0 || I0 >= w1) continue;
      int Hsz = h1 - h0, Wsz = w1 - w0;
      int sv = (Hsz == 576 && Wsz == 576) ? 1 : 0;
      const float* base = g_acc + (size_t)(z * 16 + i * 4 + j) * (SEGMAX * SEGMAX);
      int x = I0 + lx;
      bool xok = (x >= w0 && x < w1);
      float wx = xok ? g_wtab[(j * 2 + sv) * SEGMAX + (x - w0)] : 0.0f;
      for (int yy = ly; yy < 32; yy += 8) {
        int y = ylo + yy;
        if (xok && y >= h0 && y < h1) {
          int r = y - h0;
          ssum[yy][lx] += base[(size_t)r * Wsz + (x - w0)];
          swin[yy][lx] += g_wtab[(i * 2 + sv) * SEGMAX + r] * wx;
        }
      }
    }
  }
  __syncthreads();
  for (int ii = ly; ii < 32; ii += 8) {
    int I = I0 + ii;
    int J = J0 + lx;
    int yy = 31 - lx;              // (IMG-1-J) - ylo
    float s = ssum[yy][ii];
    float w = swin[yy][ii];
    float res = s / fmaxf(w, 1e-12f);
    if (!(res == res)) res = 0.0f;
    outp[((size_t)z * IMG + I) * IMG + J] = res;
  }
}

extern "C" void kernel_launch(void* const* d_in, const int* in_sizes, int n_in,
                              void* d_out, int out_size) {
  const float* Timg = (const float*)d_in[0];
  const float* psfs = (const float*)d_in[1];
  (void)in_sizes; (void)n_in;
  float* outp = (float*)d_out;

  cudaFuncSetAttribute(fwd_y,     cudaFuncAttributeMaxDynamicSharedMemorySize, (int)SM4_BYTES);
  cudaFuncSetAttribute(psf_fx,    cudaFuncAttributeMaxDynamicSharedMemorySize, (int)SM4_BYTES);
  cudaFuncSetAttribute(segconv_x, cudaFuncAttributeMaxDynamicSharedMemorySize, (int)SMFU_BYTES);
  cudaFuncSetAttribute(conv_y,    cudaFuncAttributeMaxDynamicSharedMemorySize, (int)SM4_BYTES);

  init_tabs_kernel<<<21, 256>>>();

  fwd_y<<<3072, NTH, SM4_BYTES>>>(Timg, psfs);     // seg_fy (2304) + psf_fy (768)
  psf_fx<<<dim3(97, 48), NTH, SM4_BYTES>>>();
  segconv_x<<<dim3(97, 32), NTH, SMFU_BYTES>>>();
  conv_y<<<dim3(72, 32, 3), NTH, SM4_BYTES>>>();

  finalize_t<<<dim3(64, 64, 6), dim3(32, 8)>>>(outp);
}